// round 12
// baseline (speedup 1.0000x reference)
#include <cuda_runtime.h>
#include <cuda_fp16.h>
#include <math.h>
#include <stdint.h>

#define T_ 1024
#define C_ 1024
#define B_ 4
#define H_ 16
#define L_ 12
#define V_ 50304
#define M_ 4096   // B*T tokens

// ======================= scratch (device globals) =======================
__device__ float g_x[(size_t)M_ * C_];
__device__ float g_h[(size_t)M_ * C_];
__device__ float g_qkv[(size_t)M_ * 3 * C_];
__device__ float g_logits[(size_t)M_ * V_];
__device__ __half g_h16[(size_t)M_ * C_];
__device__ __half g_mlp16[(size_t)M_ * 4 * C_];
__device__ __half g_kh[(size_t)M_ * C_];
__device__ __half g_kl[(size_t)M_ * C_];
__device__ __half g_vth[(size_t)M_ * C_];
__device__ __half g_vtl[(size_t)M_ * C_];
__device__ __half g_wqkv16[(size_t)L_ * 3 * C_ * C_];
__device__ __half g_wo16[(size_t)L_ * C_ * C_];
__device__ __half g_w1f[(size_t)L_ * C_ * 4 * C_];
__device__ __half g_w2f[(size_t)L_ * 4 * C_ * C_];
__device__ __half g_wlm16[(size_t)V_ * C_];

// ======================= small asm helpers =======================
__device__ __forceinline__ uint32_t smem_u32(const void* p) {
    uint32_t a;
    asm("{ .reg .u64 t; cvta.to.shared.u64 t, %1; cvt.u32.u64 %0, t; }" : "=r"(a) : "l"(p));
    return a;
}
__device__ __forceinline__ void ldmatrix_x4(uint32_t* r, uint32_t addr) {
    asm volatile("ldmatrix.sync.aligned.m8n8.x4.shared.b16 {%0,%1,%2,%3}, [%4];"
        : "=r"(r[0]), "=r"(r[1]), "=r"(r[2]), "=r"(r[3]) : "r"(addr));
}
__device__ __forceinline__ void mma_f16(float* d, const uint32_t* a, uint32_t b0, uint32_t b1) {
    asm volatile(
        "mma.sync.aligned.m16n8k16.row.col.f32.f16.f16.f32 "
        "{%0,%1,%2,%3}, {%4,%5,%6,%7}, {%8,%9}, {%0,%1,%2,%3};"
        : "+f"(d[0]), "+f"(d[1]), "+f"(d[2]), "+f"(d[3])
        : "r"(a[0]), "r"(a[1]), "r"(a[2]), "r"(a[3]), "r"(b0), "r"(b1));
}
#define CP_ASYNC16(dst, src) \
    asm volatile("cp.async.cg.shared.global [%0], [%1], 16;" :: "r"(dst), "l"(src))
#define CP_COMMIT() asm volatile("cp.async.commit_group;")
#define CP_WAIT2()  asm volatile("cp.async.wait_group 2;")
#define CP_WAIT0()  asm volatile("cp.async.wait_group 0;")

__device__ __forceinline__ uint32_t pack_h16(float x, float y) {
    __half2 h = __floats2half2_rn(x, y);
    return *(uint32_t*)&h;
}
__device__ __forceinline__ void split_h16(float x, float y, uint32_t& hi, uint32_t& lo) {
    __half hx = __float2half_rn(x), hy = __float2half_rn(y);
    hi = ((uint32_t)__half_as_ushort(hy) << 16) | __half_as_ushort(hx);
    lo = pack_h16(x - __half2float(hx), y - __half2float(hy));
}

// fast exp on the FMA pipe
__device__ __forceinline__ float fexp(float x) {
    float t = fmaxf(x, -80.0f) * 1.442695041f;
    float n = floorf(t);
    float f = t - n;
    float p = 0.0013276471f;
    p = p * f + 0.0096755413f;
    p = p * f + 0.0555041086f;
    p = p * f + 0.2402264923f;
    p = p * f + 0.6931471825f;
    p = p * f + 1.0f;
    return __int_as_float(((int)n << 23) + __float_as_int(p));
}

// ======================= weight prep (fp32 [K,N] -> fp16 [N,K]) ========
__global__ __launch_bounds__(256) void wsplit_f16_kernel(
    const float* __restrict__ W, __half* __restrict__ out, int K, int N, size_t out_ls)
{
    __shared__ float t[32][33];
    const float* Wl = W + (size_t)blockIdx.z * K * N;
    __half* ol = out + (size_t)blockIdx.z * out_ls;
    int n0 = blockIdx.x * 32, k0 = blockIdx.y * 32;
    int tx = threadIdx.x & 31, ty = threadIdx.x >> 5;
    #pragma unroll
    for (int i = 0; i < 4; i++)
        t[ty + 8 * i][tx] = Wl[(size_t)(k0 + ty + 8 * i) * N + n0 + tx];
    __syncthreads();
    #pragma unroll
    for (int i = 0; i < 4; i++) {
        float v = t[tx][ty + 8 * i];
        ol[(size_t)(n0 + ty + 8 * i) * K + k0 + tx] = __float2half(v);
    }
}

// ======================= fp16 2-term GEMM (fp32 A, fp16 W) =============
#define FRS 80
#define FSTG (128 * FRS)
#define F16_SMEM (3 * FSTG)

template <int BIAS, int RESID>
__global__ __launch_bounds__(256, 2) void gemm_f16a2(
    const float* __restrict__ A, const __half* __restrict__ Bw,
    const float* __restrict__ bias, const float* __restrict__ resid,
    float* __restrict__ C, int N, int K)
{
    __shared__ char sm[F16_SMEM];
    uint32_t sb = smem_u32(sm);
    int tid = threadIdx.x;
    int lane = tid & 31, wid = tid >> 5;
    int warp_m = wid >> 1, warp_n = wid & 1;
    int m0 = blockIdx.x * 128, n0 = blockIdx.y * 128;
    const int NC = K >> 5;

    float acc[2][8][4];
    #pragma unroll
    for (int t = 0; t < 2; t++)
        #pragma unroll
        for (int n = 0; n < 8; n++)
            #pragma unroll
            for (int j = 0; j < 4; j++) acc[t][n][j] = 0.f;

    const float* Abase = A + (size_t)(m0 + warp_m * 32 + (lane >> 2)) * K + (lane & 3) * 2;

    auto issueB = [&](int c, int s) {
        int k0 = c << 5;
        #pragma unroll
        for (int j = 0; j < 2; j++) {
            int fi = tid + j * 256;
            int row = fi >> 2, c16 = (fi & 3) << 4;
            const char* g = (const char*)Bw + ((size_t)(n0 + row) * K + k0) * 2 + c16;
            CP_ASYNC16(sb + s * FSTG + row * FRS + c16, g);
        }
        CP_COMMIT();
    };

    auto compute = [&](int c, int s) {
        #pragma unroll
        for (int ks = 0; ks < 2; ks++) {
            int kbase = (c << 5) + (ks << 4);
            float2 f[2][4];
            #pragma unroll
            for (int t = 0; t < 2; t++) {
                const float* ap = Abase + (size_t)t * 16 * K + kbase;
                f[t][0] = *(const float2*)(ap);
                f[t][1] = *(const float2*)(ap + (size_t)8 * K);
                f[t][2] = *(const float2*)(ap + 8);
                f[t][3] = *(const float2*)(ap + (size_t)8 * K + 8);
            }
            uint32_t bh[8][2];
            #pragma unroll
            for (int p = 0; p < 4; p++) {
                int row = warp_n * 64 + p * 16 + (lane & 7) + (((lane >> 4) & 1) << 3);
                uint32_t off = row * FRS + ks * 32 + (((lane >> 3) & 1) << 4);
                uint32_t r[4];
                ldmatrix_x4(r, sb + s * FSTG + off);
                bh[2 * p][0] = r[0]; bh[2 * p][1] = r[1];
                bh[2 * p + 1][0] = r[2]; bh[2 * p + 1][1] = r[3];
            }
            uint32_t ah[2][4], al[2][4];
            #pragma unroll
            for (int t = 0; t < 2; t++)
                #pragma unroll
                for (int j = 0; j < 4; j++)
                    split_h16(f[t][j].x, f[t][j].y, ah[t][j], al[t][j]);
            #pragma unroll
            for (int t = 0; t < 2; t++)
                #pragma unroll
                for (int n = 0; n < 8; n++) {
                    mma_f16(acc[t][n], ah[t], bh[n][0], bh[n][1]);
                    mma_f16(acc[t][n], al[t], bh[n][0], bh[n][1]);
                }
        }
    };

    issueB(0, 0);
    issueB(1, 1);
    issueB(2, 2);

    for (int c = 0; c < NC; c++) {
        int s = c % 3;
        CP_WAIT2();
        __syncthreads();
        compute(c, s);
        __syncthreads();
        if (c + 3 < NC) issueB(c + 3, s);
    }

    #pragma unroll
    for (int t = 0; t < 2; t++) {
        int row0 = m0 + warp_m * 32 + t * 16 + (lane >> 2);
        #pragma unroll
        for (int n = 0; n < 8; n++) {
            int col = n0 + warp_n * 64 + n * 8 + (lane & 3) * 2;
            float b0 = 0.f, b1 = 0.f;
            if (BIAS) { b0 = bias[col]; b1 = bias[col + 1]; }
            float v0 = acc[t][n][0] + b0, v1 = acc[t][n][1] + b1;
            float v2 = acc[t][n][2] + b0, v3 = acc[t][n][3] + b1;
            size_t o0 = (size_t)row0 * N + col;
            size_t o1 = (size_t)(row0 + 8) * N + col;
            if (RESID) {
                float2 r0 = *(const float2*)(resid + o0);
                float2 r1 = *(const float2*)(resid + o1);
                v0 += r0.x; v1 += r0.y; v2 += r1.x; v3 += r1.y;
            }
            *(float2*)(C + o0) = make_float2(v0, v1);
            *(float2*)(C + o1) = make_float2(v2, v3);
        }
    }
}

// ======================= fp16 single-digit GEMM ========================
template <int BIAS, int RELU, int RESID, int OUTF16>
__global__ __launch_bounds__(256, 2) void gemm_f16(
    const __half* __restrict__ A, const __half* __restrict__ Bw,
    const float* __restrict__ bias, const float* __restrict__ resid,
    float* __restrict__ C, __half* __restrict__ C16, int N, int K)
{
    __shared__ char sm[F16_SMEM];
    uint32_t sb = smem_u32(sm);
    int tid = threadIdx.x;
    int lane = tid & 31, wid = tid >> 5;
    int warp_m = wid >> 1, warp_n = wid & 1;
    int m0 = blockIdx.x * 128, n0 = blockIdx.y * 128;
    const int NC = K >> 5;

    float acc[2][8][4];
    #pragma unroll
    for (int t = 0; t < 2; t++)
        #pragma unroll
        for (int n = 0; n < 8; n++)
            #pragma unroll
            for (int j = 0; j < 4; j++) acc[t][n][j] = 0.f;

    const __half* Abase = A + (size_t)(m0 + warp_m * 32 + (lane >> 2)) * K + ((lane & 3) << 1);

    auto issueB = [&](int c, int s) {
        int k0 = c << 5;
        #pragma unroll
        for (int j = 0; j < 2; j++) {
            int fi = tid + j * 256;
            int row = fi >> 2, c16 = (fi & 3) << 4;
            const char* g = (const char*)Bw + ((size_t)(n0 + row) * K + k0) * 2 + c16;
            CP_ASYNC16(sb + s * FSTG + row * FRS + c16, g);
        }
        CP_COMMIT();
    };

    auto compute = [&](int c, int s) {
        #pragma unroll
        for (int ks = 0; ks < 2; ks++) {
            int kbase = (c << 5) + (ks << 4);
            uint32_t ah[2][4];
            #pragma unroll
            for (int t = 0; t < 2; t++) {
                size_t o = (size_t)(t * 16) * K + kbase;
                ah[t][0] = *(const uint32_t*)(Abase + o);
                ah[t][1] = *(const uint32_t*)(Abase + o + (size_t)8 * K);
                ah[t][2] = *(const uint32_t*)(Abase + o + 8);
                ah[t][3] = *(const uint32_t*)(Abase + o + (size_t)8 * K + 8);
            }
            uint32_t bh[8][2];
            #pragma unroll
            for (int p = 0; p < 4; p++) {
                int row = warp_n * 64 + p * 16 + (lane & 7) + (((lane >> 4) & 1) << 3);
                uint32_t off = row * FRS + ks * 32 + (((lane >> 3) & 1) << 4);
                uint32_t r[4];
                ldmatrix_x4(r, sb + s * FSTG + off);
                bh[2 * p][0] = r[0]; bh[2 * p][1] = r[1];
                bh[2 * p + 1][0] = r[2]; bh[2 * p + 1][1] = r[3];
            }
            #pragma unroll
            for (int t = 0; t < 2; t++)
                #pragma unroll
                for (int n = 0; n < 8; n++)
                    mma_f16(acc[t][n], ah[t], bh[n][0], bh[n][1]);
        }
    };

    issueB(0, 0);
    issueB(1, 1);
    issueB(2, 2);

    for (int c = 0; c < NC; c++) {
        int s = c % 3;
        CP_WAIT2();
        __syncthreads();
        compute(c, s);
        __syncthreads();
        if (c + 3 < NC) issueB(c + 3, s);
    }

    #pragma unroll
    for (int t = 0; t < 2; t++) {
        int row0 = m0 + warp_m * 32 + t * 16 + (lane >> 2);
        #pragma unroll
        for (int n = 0; n < 8; n++) {
            int col = n0 + warp_n * 64 + n * 8 + (lane & 3) * 2;
            float b0 = 0.f, b1 = 0.f;
            if (BIAS) { b0 = bias[col]; b1 = bias[col + 1]; }
            float v0 = acc[t][n][0] + b0, v1 = acc[t][n][1] + b1;
            float v2 = acc[t][n][2] + b0, v3 = acc[t][n][3] + b1;
            size_t o0 = (size_t)row0 * N + col;
            size_t o1 = (size_t)(row0 + 8) * N + col;
            if (RESID) {
                float2 r0 = *(const float2*)(resid + o0);
                float2 r1 = *(const float2*)(resid + o1);
                v0 += r0.x; v1 += r0.y; v2 += r1.x; v3 += r1.y;
            }
            if (RELU) {
                v0 = fmaxf(v0, 0.f); v1 = fmaxf(v1, 0.f);
                v2 = fmaxf(v2, 0.f); v3 = fmaxf(v3, 0.f);
            }
            if (OUTF16) {
                *(uint32_t*)(C16 + o0) = pack_h16(v0, v1);
                *(uint32_t*)(C16 + o1) = pack_h16(v2, v3);
            } else {
                *(float2*)(C + o0) = make_float2(v0, v1);
                *(float2*)(C + o1) = make_float2(v2, v3);
            }
        }
    }
}

// ======================= embedding ====================================
__global__ __launch_bounds__(256) void embed_kernel(
    const int* __restrict__ idx, const float* __restrict__ tok,
    const float* __restrict__ pos, float* __restrict__ x)
{
    int bt = blockIdx.x;
    int t = bt & (T_ - 1);
    int token = idx[bt];
    int c = threadIdx.x * 4;
    float4 tv = *(const float4*)(tok + (size_t)token * C_ + c);
    float4 pv = *(const float4*)(pos + (size_t)t * C_ + c);
    *(float4*)(x + (size_t)bt * C_ + c) =
        make_float4(tv.x + pv.x, tv.y + pv.y, tv.z + pv.z, tv.w + pv.w);
}

// ======================= layernorm (OUT: 0=fp32, 1=fp16) ==============
template <int OUT>
__global__ __launch_bounds__(256) void ln_out_kernel(
    const float* __restrict__ x, const float* __restrict__ g,
    const float* __restrict__ b, float* __restrict__ yf, __half* __restrict__ yh)
{
    __shared__ float red[8];
    __shared__ float bc_mean, bc_inv;
    int row = blockIdx.x, tid = threadIdx.x;
    const float* xr = x + (size_t)row * C_;
    float4 xv = *(const float4*)(xr + tid * 4);
    float s = xv.x + xv.y + xv.z + xv.w;
    #pragma unroll
    for (int o = 16; o; o >>= 1) s += __shfl_xor_sync(0xffffffffu, s, o);
    if ((tid & 31) == 0) red[tid >> 5] = s;
    __syncthreads();
    if (tid == 0) {
        float t = 0.f;
        #pragma unroll
        for (int i = 0; i < 8; i++) t += red[i];
        bc_mean = t * (1.0f / C_);
    }
    __syncthreads();
    float mean = bc_mean;
    float d0 = xv.x - mean, d1 = xv.y - mean, d2 = xv.z - mean, d3 = xv.w - mean;
    float sq = d0 * d0 + d1 * d1 + d2 * d2 + d3 * d3;
    #pragma unroll
    for (int o = 16; o; o >>= 1) sq += __shfl_xor_sync(0xffffffffu, sq, o);
    if ((tid & 31) == 0) red[tid >> 5] = sq;
    __syncthreads();
    if (tid == 0) {
        float t = 0.f;
        #pragma unroll
        for (int i = 0; i < 8; i++) t += red[i];
        bc_inv = rsqrtf(t * (1.0f / C_) + 1e-5f);
    }
    __syncthreads();
    float inv = bc_inv;
    float4 gv = *(const float4*)(g + tid * 4);
    float4 bv = *(const float4*)(b + tid * 4);
    float y0 = d0 * inv * gv.x + bv.x;
    float y1 = d1 * inv * gv.y + bv.y;
    float y2 = d2 * inv * gv.z + bv.z;
    float y3 = d3 * inv * gv.w + bv.w;
    size_t off = (size_t)row * C_ + tid * 4;
    if (OUT == 0) {
        *(float4*)(yf + off) = make_float4(y0, y1, y2, y3);
    } else {
        *(uint2*)(yh + off) = make_uint2(pack_h16(y0, y1), pack_h16(y2, y3));
    }
}

// ======================= K/V pre-conversion ===========================
__global__ __launch_bounds__(256) void kvprep_kernel(
    const float* __restrict__ qkv, __half* __restrict__ khg,
    __half* __restrict__ klg, __half* __restrict__ vth, __half* __restrict__ vtl)
{
    __shared__ __half sh[64][65], sl[64][65];
    int kb = blockIdx.x, bhx = blockIdx.y;
    int b = bhx >> 4, hh = bhx & 15;
    int tid = threadIdx.x;
    int r = tid >> 2, d0 = (tid & 3) << 4;
    size_t grow = (size_t)(b * T_ + kb * 64 + r);
    const float* Krow = qkv + grow * (3 * C_) + C_ + hh * 64;
    const float* Vrow = Krow + C_;
    __half* khr = khg + grow * C_ + hh * 64;
    __half* klr = klg + grow * C_ + hh * 64;
    #pragma unroll
    for (int d = d0; d < d0 + 16; d += 2) {
        float2 kv = *(const float2*)(Krow + d);
        uint32_t hi, lo;
        split_h16(kv.x, kv.y, hi, lo);
        *(uint32_t*)(khr + d) = hi;
        *(uint32_t*)(klr + d) = lo;
        float2 vv = *(const float2*)(Vrow + d);
        __half hx = __float2half_rn(vv.x), hy = __float2half_rn(vv.y);
        sh[r][d] = hx; sh[r][d + 1] = hy;
        sl[r][d] = __float2half_rn(vv.x - __half2float(hx));
        sl[r][d + 1] = __float2half_rn(vv.y - __half2float(hy));
    }
    __syncthreads();
    int dd = tid >> 2, k0 = (tid & 3) << 4;
    __half* vht = vth + ((size_t)bhx * 16 + kb) * 4096 + dd * 64;
    __half* vlt = vtl + ((size_t)bhx * 16 + kb) * 4096 + dd * 64;
    #pragma unroll
    for (int k = k0; k < k0 + 16; k += 2) {
        uint32_t hv = ((uint32_t)__half_as_ushort(sh[k + 1][dd]) << 16) | __half_as_ushort(sh[k][dd]);
        uint32_t lv = ((uint32_t)__half_as_ushort(sl[k + 1][dd]) << 16) | __half_as_ushort(sl[k][dd]);
        *(uint32_t*)(vht + k) = hv;
        *(uint32_t*)(vtl ? vlt + k : vlt + k) = lv;
    }
}

// ======================= tensor-core causal flash attention ===========
// 128 q-rows per block; 8 warps, each owns 16 q-rows x ALL 64 keys.
// No cross-warp reductions; kv-tile count per column ~halved.
#define ARS 72
#define AKV_BYTES (4 * 64 * ARS * 2)

__global__ __launch_bounds__(256) void attn_kernel(
    const float* __restrict__ QKV, const __half* __restrict__ khg,
    const __half* __restrict__ klg, const __half* __restrict__ vth,
    const __half* __restrict__ vtl, float* __restrict__ O)
{
    __shared__ __align__(16) char smb[AKV_BYTES];

    const int LDQ = 3 * C_;
    int qb = blockIdx.x, bhx = blockIdx.y;
    int b = bhx >> 4, hh = bhx & 15;
    const float* Qp = QKV + (size_t)b * T_ * LDQ + (size_t)hh * 64;
    size_t base_out = (size_t)b * T_ * C_ + (size_t)hh * 64;

    int tid = threadIdx.x, lane = tid & 31, wid = tid >> 5;
    int r0 = lane >> 2, c0 = (lane & 3) << 1;
    int growA = qb * 128 + wid * 16 + r0;     // this warp's lower q row

    uint32_t kbase = smem_u32(smb);
    uint32_t klbase = kbase + 64 * ARS * 2;
    uint32_t vbase = klbase + 64 * ARS * 2;
    uint32_t vlbase = vbase + 64 * ARS * 2;

    // ---- Q fragments (hi/lo fp16), pre-scaled by 1/8 (exact) ----
    uint32_t qh[4][4], ql[4][4];
    #pragma unroll
    for (int s = 0; s < 4; s++)
        #pragma unroll
        for (int j = 0; j < 4; j++) {
            int grow = growA + ((j & 1) << 3);
            int gcol = s * 16 + c0 + ((j >> 1) << 3);
            float2 v = *(const float2*)(Qp + (size_t)grow * LDQ + gcol);
            split_h16(v.x * 0.125f, v.y * 0.125f, qh[s][j], ql[s][j]);
        }

    float m0 = -1e30f, m1 = -1e30f, l0 = 0.f, l1 = 0.f;
    float o[8][4];
    #pragma unroll
    for (int n = 0; n < 8; n++)
        #pragma unroll
        for (int j = 0; j < 4; j++) o[n][j] = 0.f;

    const int NKB = 2 * qb + 2;   // kv tiles covering rows < (qb+1)*128
    for (int kb = 0; kb < NKB; kb++) {
        // ---- pure cp.async tile load (pre-converted fp16) ----
        {
            const __half* kh_t = khg + ((size_t)(b * T_ + kb * 64)) * C_ + hh * 64;
            const __half* kl_t = klg + ((size_t)(b * T_ + kb * 64)) * C_ + hh * 64;
            const __half* vh_t = vth + ((size_t)bhx * 16 + kb) * 4096;
            const __half* vl_t = vtl + ((size_t)bhx * 16 + kb) * 4096;
            #pragma unroll
            for (int j = 0; j < 2; j++) {
                int idx = tid + j * 256;
                int row = idx >> 3, cb = (idx & 7) << 4;
                CP_ASYNC16(kbase + row * 144 + cb, (const char*)(kh_t + (size_t)row * C_) + cb);
                CP_ASYNC16(klbase + row * 144 + cb, (const char*)(kl_t + (size_t)row * C_) + cb);
                CP_ASYNC16(vbase + row * 144 + cb, (const char*)(vh_t + row * 64) + cb);
                CP_ASYNC16(vlbase + row * 144 + cb, (const char*)(vl_t + row * 64) + cb);
            }
            CP_COMMIT();
            CP_WAIT0();
        }
        __syncthreads();

        // ---- S = Q K^T (3-term), all 64 keys per warp ----
        float c[8][4];
        #pragma unroll
        for (int n = 0; n < 8; n++)
            #pragma unroll
            for (int j = 0; j < 4; j++) c[n][j] = 0.f;

        #pragma unroll
        for (int s = 0; s < 4; s++) {
            #pragma unroll
            for (int p = 0; p < 4; p++) {
                int krow = p * 16 + (lane & 7) + (((lane >> 4) & 1) << 3);
                uint32_t off = krow * (ARS * 2) + s * 32 + (((lane >> 3) & 1) << 4);
                uint32_t rh[4], rl[4];
                ldmatrix_x4(rh, kbase + off);
                ldmatrix_x4(rl, klbase + off);
                mma_f16(c[2 * p],     qh[s], rh[0], rh[1]);
                mma_f16(c[2 * p],     ql[s], rh[0], rh[1]);
                mma_f16(c[2 * p],     qh[s], rl[0], rl[1]);
                mma_f16(c[2 * p + 1], qh[s], rh[2], rh[3]);
                mma_f16(c[2 * p + 1], ql[s], rh[2], rh[3]);
                mma_f16(c[2 * p + 1], qh[s], rl[2], rl[3]);
            }
        }

        // ---- causal mask (only possible on the last two tiles) ----
        if (kb >= 2 * qb) {
            #pragma unroll
            for (int n = 0; n < 8; n++) {
                int gk = kb * 64 + n * 8 + c0;
                if (gk > growA)         c[n][0] = -1e30f;
                if (gk + 1 > growA)     c[n][1] = -1e30f;
                if (gk > growA + 8)     c[n][2] = -1e30f;
                if (gk + 1 > growA + 8) c[n][3] = -1e30f;
            }
        }

        // ---- online softmax (warp-local) ----
        float mx0 = -1e30f, mx1 = -1e30f;
        #pragma unroll
        for (int n = 0; n < 8; n++) {
            mx0 = fmaxf(mx0, fmaxf(c[n][0], c[n][1]));
            mx1 = fmaxf(mx1, fmaxf(c[n][2], c[n][3]));
        }
        mx0 = fmaxf(mx0, __shfl_xor_sync(0xffffffffu, mx0, 1));
        mx0 = fmaxf(mx0, __shfl_xor_sync(0xffffffffu, mx0, 2));
        mx1 = fmaxf(mx1, __shfl_xor_sync(0xffffffffu, mx1, 1));
        mx1 = fmaxf(mx1, __shfl_xor_sync(0xffffffffu, mx1, 2));
        float mn0 = fmaxf(m0, mx0), mn1 = fmaxf(m1, mx1);
        float corr0 = fexp(m0 - mn0), corr1 = fexp(m1 - mn1);
        m0 = mn0; m1 = mn1;

        float ls0 = 0.f, ls1 = 0.f;
        #pragma unroll
        for (int n = 0; n < 8; n++) {
            c[n][0] = fexp(c[n][0] - mn0); ls0 += c[n][0];
            c[n][1] = fexp(c[n][1] - mn0); ls0 += c[n][1];
            c[n][2] = fexp(c[n][2] - mn1); ls1 += c[n][2];
            c[n][3] = fexp(c[n][3] - mn1); ls1 += c[n][3];
        }
        ls0 += __shfl_xor_sync(0xffffffffu, ls0, 1);
        ls0 += __shfl_xor_sync(0xffffffffu, ls0, 2);
        ls1 += __shfl_xor_sync(0xffffffffu, ls1, 1);
        ls1 += __shfl_xor_sync(0xffffffffu, ls1, 2);
        l0 = l0 * corr0 + ls0;
        l1 = l1 * corr1 + ls1;
        #pragma unroll
        for (int n = 0; n < 8; n++) {
            o[n][0] *= corr0; o[n][1] *= corr0;
            o[n][2] *= corr1; o[n][3] *= corr1;
        }

        // ---- O += P V (3-term), k2 = 16-key slabs ----
        #pragma unroll
        for (int k2 = 0; k2 < 4; k2++) {
            uint32_t ph[4], pl[4];
            split_h16(c[2 * k2][0], c[2 * k2][1], ph[0], pl[0]);
            split_h16(c[2 * k2][2], c[2 * k2][3], ph[1], pl[1]);
            split_h16(c[2 * k2 + 1][0], c[2 * k2 + 1][1], ph[2], pl[2]);
            split_h16(c[2 * k2 + 1][2], c[2 * k2 + 1][3], ph[3], pl[3]);
            #pragma unroll
            for (int p = 0; p < 4; p++) {
                int vrow = p * 16 + (lane & 7) + (((lane >> 4) & 1) << 3);
                uint32_t off = vrow * (ARS * 2) + (k2 * 16) * 2 + (((lane >> 3) & 1) << 4);
                uint32_t rv[4], rl[4];
                ldmatrix_x4(rv, vbase + off);
                ldmatrix_x4(rl, vlbase + off);
                mma_f16(o[2 * p],     ph, rv[0], rv[1]);
                mma_f16(o[2 * p],     pl, rv[0], rv[1]);
                mma_f16(o[2 * p],     ph, rl[0], rl[1]);
                mma_f16(o[2 * p + 1], ph, rv[2], rv[3]);
                mma_f16(o[2 * p + 1], pl, rv[2], rv[3]);
                mma_f16(o[2 * p + 1], ph, rl[2], rl[3]);
            }
        }
        __syncthreads();
    }

    // ---- normalize, store (warp-local) ----
    float inv0 = 1.0f / l0, inv1 = 1.0f / l1;
    #pragma unroll
    for (int n = 0; n < 8; n++) {
        int d = n * 8 + c0;
        *(float2*)(O + base_out + (size_t)growA * C_ + d) =
            make_float2(o[n][0] * inv0, o[n][1] * inv0);
        *(float2*)(O + base_out + (size_t)(growA + 8) * C_ + d) =
            make_float2(o[n][2] * inv1, o[n][3] * inv1);
    }
}

// ======================= loss =========================================
__global__ void loss_init_kernel(float* loss) { *loss = 0.f; }

__global__ __launch_bounds__(256) void loss_kernel(
    const float* __restrict__ logits, const int* __restrict__ targets,
    float* __restrict__ loss)
{
    __shared__ float red[8];
    __shared__ float bmx_s, bsum_s;
    int row = blockIdx.x, tid = threadIdx.x;
    const float4* lr4 = (const float4*)(logits + (size_t)row * V_);

    float mx = -1e30f;
    for (int i = tid; i < V_ / 4; i += 256) {
        float4 u = lr4[i];
        mx = fmaxf(mx, fmaxf(fmaxf(u.x, u.y), fmaxf(u.z, u.w)));
    }
    #pragma unroll
    for (int o = 16; o; o >>= 1) mx = fmaxf(mx, __shfl_xor_sync(0xffffffffu, mx, o));
    if ((tid & 31) == 0) red[tid >> 5] = mx;
    __syncthreads();
    if (tid == 0) {
        float t = red[0];
        #pragma unroll
        for (int i = 1; i < 8; i++) t = fmaxf(t, red[i]);
        bmx_s = t;
    }
    __syncthreads();
    float bmx = bmx_s;

    float s = 0.f;
    for (int i = tid; i < V_ / 4; i += 256) {
        float4 u = lr4[i];
        s += fexp(u.x - bmx) + fexp(u.y - bmx) + fexp(u.z - bmx) + fexp(u.w - bmx);
    }
    #pragma unroll
    for (int o = 16; o; o >>= 1) s += __shfl_xor_sync(0xffffffffu, s, o);
    if ((tid & 31) == 0) red[tid >> 5] = s;
    __syncthreads();
    if (tid == 0) {
        float t = 0.f;
        #pragma unroll
        for (int i = 0; i < 8; i++) t += red[i];
        bsum_s = t;
    }
    __syncthreads();
    if (tid == 0) {
        int tgt = targets[row];
        float lp = logits[(size_t)row * V_ + tgt] - bmx - logf(bsum_s);
        atomicAdd(loss, -lp * (1.0f / M_));
    }
}

// ======================= host =========================================
extern "C" void kernel_launch(void* const* d_in, const int* in_sizes, int n_in,
                              void* d_out, int out_size)
{
    const int*   idx     = (const int*)d_in[0];
    const int*   targets = (const int*)d_in[1];
    const float* tok     = (const float*)d_in[2];
    const float* pos     = (const float*)d_in[3];
    const float* ln1g    = (const float*)d_in[4];
    const float* ln1b    = (const float*)d_in[5];
    const float* Wq      = (const float*)d_in[6];
    const float* Wk      = (const float*)d_in[7];
    const float* Wv      = (const float*)d_in[8];
    const float* Wo      = (const float*)d_in[9];
    const float* bo      = (const float*)d_in[10];
    const float* ln2g    = (const float*)d_in[11];
    const float* ln2b    = (const float*)d_in[12];
    const float* W1      = (const float*)d_in[13];
    const float* b1      = (const float*)d_in[14];
    const float* W2      = (const float*)d_in[15];
    const float* b2      = (const float*)d_in[16];
    const float* lnfg    = (const float*)d_in[17];
    const float* lnfb    = (const float*)d_in[18];
    const float* Wlm     = (const float*)d_in[19];
    const float* blm     = (const float*)d_in[20];

    static float *x, *h, *qkv, *lgbuf;
    static __half *h16, *mlp16, *wqkv16, *wo16, *w1f, *w2f, *wlm16;
    static __half *khg, *klg, *vth, *vtl;
    static bool init = false;
    if (!init) {
        cudaGetSymbolAddress((void**)&x, g_x);
        cudaGetSymbolAddress((void**)&h, g_h);
        cudaGetSymbolAddress((void**)&qkv, g_qkv);
        cudaGetSymbolAddress((void**)&lgbuf, g_logits);
        cudaGetSymbolAddress((void**)&h16, g_h16);
        cudaGetSymbolAddress((void**)&mlp16, g_mlp16);
        cudaGetSymbolAddress((void**)&wqkv16, g_wqkv16);
        cudaGetSymbolAddress((void**)&wo16, g_wo16);
        cudaGetSymbolAddress((void**)&w1f, g_w1f);
        cudaGetSymbolAddress((void**)&w2f, g_w2f);
        cudaGetSymbolAddress((void**)&wlm16, g_wlm16);
        cudaGetSymbolAddress((void**)&khg, g_kh);
        cudaGetSymbolAddress((void**)&klg, g_kl);
        cudaGetSymbolAddress((void**)&vth, g_vth);
        cudaGetSymbolAddress((void**)&vtl, g_vtl);
        init = true;
    }

    const size_t NTV = (size_t)M_ * V_;
    float* logits_ptr = ((size_t)out_size >= NTV) ? (float*)d_out : lgbuf;
    float* loss_ptr = nullptr;
    if ((size_t)out_size == NTV + 1)     loss_ptr = (float*)d_out + NTV;
    else if ((size_t)out_size < NTV)     loss_ptr = (float*)d_out;

    const size_t CC = (size_t)C_ * C_;
    const size_t C3 = 3 * CC;
    const size_t C4 = 4 * CC;

    // ---- weight prep (all fp16 [N,K]) ----
    wsplit_f16_kernel<<<dim3(C_ / 32, C_ / 32, L_), 256>>>(Wq, wqkv16 + 0 * CC, C_, C_, C3);
    wsplit_f16_kernel<<<dim3(C_ / 32, C_ / 32, L_), 256>>>(Wk, wqkv16 + 1 * CC, C_, C_, C3);
    wsplit_f16_kernel<<<dim3(C_ / 32, C_ / 32, L_), 256>>>(Wv, wqkv16 + 2 * CC, C_, C_, C3);
    wsplit_f16_kernel<<<dim3(C_ / 32, C_ / 32, L_), 256>>>(Wo, wo16, C_, C_, CC);
    wsplit_f16_kernel<<<dim3(4 * C_ / 32, C_ / 32, L_), 256>>>(W1, w1f, C_, 4 * C_, C4);
    wsplit_f16_kernel<<<dim3(C_ / 32, 4 * C_ / 32, L_), 256>>>(W2, w2f, 4 * C_, C_, C4);
    wsplit_f16_kernel<<<dim3(V_ / 32, C_ / 32, 1), 256>>>(Wlm, wlm16, C_, V_, 0);

    dim3 gqkv(M_ / 128, 3 * C_ / 128);
    dim3 g1(M_ / 128, C_ / 128);
    dim3 g4(M_ / 128, 4 * C_ / 128);
    dim3 gl(M_ / 128, V_ / 128);
    dim3 gkv(T_ / 64, B_ * H_);
    dim3 ga(T_ / 128, B_ * H_);

    embed_kernel<<<M_, 256>>>(idx, tok, pos, x);

    for (int l = 0; l < L_; l++) {
        ln_out_kernel<0><<<M_, 256>>>(x, ln1g + (size_t)l * C_, ln1b + (size_t)l * C_, h, nullptr);
        gemm_f16a2<0,0><<<gqkv, 256>>>(h, wqkv16 + (size_t)l * C3, nullptr, nullptr, qkv, 3 * C_, C_);
        kvprep_kernel<<<gkv, 256>>>(qkv, khg, klg, vth, vtl);
        attn_kernel<<<ga, 256>>>(qkv, khg, klg, vth, vtl, h);
        gemm_f16a2<1,1><<<g1, 256>>>(h, wo16 + (size_t)l * CC, bo + (size_t)l * C_, x, x, C_, C_);
        ln_out_kernel<1><<<M_, 256>>>(x, ln2g + (size_t)l * C_, ln2b + (size_t)l * C_, nullptr, h16);
        gemm_f16<1,1,0,1><<<g4, 256>>>(h16, w1f + (size_t)l * C4,
            b1 + (size_t)l * 4 * C_, nullptr, nullptr, mlp16, 4 * C_, C_);
        gemm_f16<1,0,1,0><<<g1, 256>>>(mlp16, w2f + (size_t)l * C4,
            b2 + (size_t)l * C_, x, x, nullptr, C_, 4 * C_);
    }

    ln_out_kernel<1><<<M_, 256>>>(x, lnfg, lnfb, nullptr, h16);
    gemm_f16<1,0,0,0><<<gl, 256>>>(h16, wlm16, blm, nullptr, logits_ptr, nullptr, V_, C_);

    if (loss_ptr) {
        loss_init_kernel<<<1, 1>>>(loss_ptr);
        loss_kernel<<<M_, 256>>>(logits_ptr, targets, loss_ptr);
    }
}

// round 13
// speedup vs baseline: 1.0411x; 1.0411x over previous
#include <cuda_runtime.h>
#include <cuda_fp16.h>
#include <math.h>
#include <stdint.h>

#define T_ 1024
#define C_ 1024
#define B_ 4
#define H_ 16
#define L_ 12
#define V_ 50304
#define M_ 4096   // B*T tokens

// ======================= scratch (device globals) =======================
__device__ float g_x[(size_t)M_ * C_];
__device__ float g_h[(size_t)M_ * C_];
__device__ float g_qkv[(size_t)M_ * 3 * C_];
__device__ float g_logits[(size_t)M_ * V_];
__device__ __half g_h16[(size_t)M_ * C_];
__device__ __half g_mlp16[(size_t)M_ * 4 * C_];
__device__ __half g_kh[(size_t)M_ * C_];
__device__ __half g_kl[(size_t)M_ * C_];
__device__ __half g_vth[(size_t)M_ * C_];
__device__ __half g_vtl[(size_t)M_ * C_];
__device__ __half g_wqkv16[(size_t)L_ * 3 * C_ * C_];
__device__ __half g_wo16[(size_t)L_ * C_ * C_];
__device__ __half g_w1f[(size_t)L_ * C_ * 4 * C_];
__device__ __half g_w2f[(size_t)L_ * 4 * C_ * C_];
__device__ __half g_wlm16[(size_t)V_ * C_];

// ======================= small asm helpers =======================
__device__ __forceinline__ uint32_t smem_u32(const void* p) {
    uint32_t a;
    asm("{ .reg .u64 t; cvta.to.shared.u64 t, %1; cvt.u32.u64 %0, t; }" : "=r"(a) : "l"(p));
    return a;
}
__device__ __forceinline__ void ldmatrix_x4(uint32_t* r, uint32_t addr) {
    asm volatile("ldmatrix.sync.aligned.m8n8.x4.shared.b16 {%0,%1,%2,%3}, [%4];"
        : "=r"(r[0]), "=r"(r[1]), "=r"(r[2]), "=r"(r[3]) : "r"(addr));
}
__device__ __forceinline__ void mma_f16(float* d, const uint32_t* a, uint32_t b0, uint32_t b1) {
    asm volatile(
        "mma.sync.aligned.m16n8k16.row.col.f32.f16.f16.f32 "
        "{%0,%1,%2,%3}, {%4,%5,%6,%7}, {%8,%9}, {%0,%1,%2,%3};"
        : "+f"(d[0]), "+f"(d[1]), "+f"(d[2]), "+f"(d[3])
        : "r"(a[0]), "r"(a[1]), "r"(a[2]), "r"(a[3]), "r"(b0), "r"(b1));
}
#define CP_ASYNC16(dst, src) \
    asm volatile("cp.async.cg.shared.global [%0], [%1], 16;" :: "r"(dst), "l"(src))
#define CP_COMMIT() asm volatile("cp.async.commit_group;")
#define CP_WAIT2()  asm volatile("cp.async.wait_group 2;")
#define CP_WAIT0()  asm volatile("cp.async.wait_group 0;")

__device__ __forceinline__ uint32_t pack_h16(float x, float y) {
    __half2 h = __floats2half2_rn(x, y);
    return *(uint32_t*)&h;
}
__device__ __forceinline__ void split_h16(float x, float y, uint32_t& hi, uint32_t& lo) {
    __half hx = __float2half_rn(x), hy = __float2half_rn(y);
    hi = ((uint32_t)__half_as_ushort(hy) << 16) | __half_as_ushort(hx);
    lo = pack_h16(x - __half2float(hx), y - __half2float(hy));
}

// fast exp on the FMA pipe
__device__ __forceinline__ float fexp(float x) {
    float t = fmaxf(x, -80.0f) * 1.442695041f;
    float n = floorf(t);
    float f = t - n;
    float p = 0.0013276471f;
    p = p * f + 0.0096755413f;
    p = p * f + 0.0555041086f;
    p = p * f + 0.2402264923f;
    p = p * f + 0.6931471825f;
    p = p * f + 1.0f;
    return __int_as_float(((int)n << 23) + __float_as_int(p));
}

// ======================= weight prep (fp32 [K,N] -> fp16 [N,K]) ========
__global__ __launch_bounds__(256) void wsplit_f16_kernel(
    const float* __restrict__ W, __half* __restrict__ out, int K, int N, size_t out_ls)
{
    __shared__ float t[32][33];
    const float* Wl = W + (size_t)blockIdx.z * K * N;
    __half* ol = out + (size_t)blockIdx.z * out_ls;
    int n0 = blockIdx.x * 32, k0 = blockIdx.y * 32;
    int tx = threadIdx.x & 31, ty = threadIdx.x >> 5;
    #pragma unroll
    for (int i = 0; i < 4; i++)
        t[ty + 8 * i][tx] = Wl[(size_t)(k0 + ty + 8 * i) * N + n0 + tx];
    __syncthreads();
    #pragma unroll
    for (int i = 0; i < 4; i++) {
        float v = t[tx][ty + 8 * i];
        ol[(size_t)(n0 + ty + 8 * i) * K + k0 + tx] = __float2half(v);
    }
}

// ======================= fp16 2-term GEMM (fp32 A, fp16 W) =============
// KSPLIT: for col block [1024,2048) write fp16 hi/lo K planes instead of fp32.
#define FRS 80
#define FSTG (128 * FRS)
#define F16_SMEM (3 * FSTG)

template <int BIAS, int RESID, int KSPLIT>
__global__ __launch_bounds__(256, 2) void gemm_f16a2(
    const float* __restrict__ A, const __half* __restrict__ Bw,
    const float* __restrict__ bias, const float* __restrict__ resid,
    float* __restrict__ C, __half* __restrict__ Kh, __half* __restrict__ Kl,
    int N, int K)
{
    __shared__ char sm[F16_SMEM];
    uint32_t sb = smem_u32(sm);
    int tid = threadIdx.x;
    int lane = tid & 31, wid = tid >> 5;
    int warp_m = wid >> 1, warp_n = wid & 1;
    int m0 = blockIdx.x * 128, n0 = blockIdx.y * 128;
    const int NC = K >> 5;

    float acc[2][8][4];
    #pragma unroll
    for (int t = 0; t < 2; t++)
        #pragma unroll
        for (int n = 0; n < 8; n++)
            #pragma unroll
            for (int j = 0; j < 4; j++) acc[t][n][j] = 0.f;

    const float* Abase = A + (size_t)(m0 + warp_m * 32 + (lane >> 2)) * K + (lane & 3) * 2;

    auto issueB = [&](int c, int s) {
        int k0 = c << 5;
        #pragma unroll
        for (int j = 0; j < 2; j++) {
            int fi = tid + j * 256;
            int row = fi >> 2, c16 = (fi & 3) << 4;
            const char* g = (const char*)Bw + ((size_t)(n0 + row) * K + k0) * 2 + c16;
            CP_ASYNC16(sb + s * FSTG + row * FRS + c16, g);
        }
        CP_COMMIT();
    };

    auto compute = [&](int c, int s) {
        #pragma unroll
        for (int ks = 0; ks < 2; ks++) {
            int kbase = (c << 5) + (ks << 4);
            float2 f[2][4];
            #pragma unroll
            for (int t = 0; t < 2; t++) {
                const float* ap = Abase + (size_t)t * 16 * K + kbase;
                f[t][0] = *(const float2*)(ap);
                f[t][1] = *(const float2*)(ap + (size_t)8 * K);
                f[t][2] = *(const float2*)(ap + 8);
                f[t][3] = *(const float2*)(ap + (size_t)8 * K + 8);
            }
            uint32_t bh[8][2];
            #pragma unroll
            for (int p = 0; p < 4; p++) {
                int row = warp_n * 64 + p * 16 + (lane & 7) + (((lane >> 4) & 1) << 3);
                uint32_t off = row * FRS + ks * 32 + (((lane >> 3) & 1) << 4);
                uint32_t r[4];
                ldmatrix_x4(r, sb + s * FSTG + off);
                bh[2 * p][0] = r[0]; bh[2 * p][1] = r[1];
                bh[2 * p + 1][0] = r[2]; bh[2 * p + 1][1] = r[3];
            }
            uint32_t ah[2][4], al[2][4];
            #pragma unroll
            for (int t = 0; t < 2; t++)
                #pragma unroll
                for (int j = 0; j < 4; j++)
                    split_h16(f[t][j].x, f[t][j].y, ah[t][j], al[t][j]);
            #pragma unroll
            for (int t = 0; t < 2; t++)
                #pragma unroll
                for (int n = 0; n < 8; n++) {
                    mma_f16(acc[t][n], ah[t], bh[n][0], bh[n][1]);
                    mma_f16(acc[t][n], al[t], bh[n][0], bh[n][1]);
                }
        }
    };

    issueB(0, 0);
    issueB(1, 1);
    issueB(2, 2);

    for (int c = 0; c < NC; c++) {
        int s = c % 3;
        CP_WAIT2();
        __syncthreads();
        compute(c, s);
        __syncthreads();
        if (c + 3 < NC) issueB(c + 3, s);
    }

    bool kreg = KSPLIT && (n0 >= 1024) && (n0 < 2048);
    #pragma unroll
    for (int t = 0; t < 2; t++) {
        int row0 = m0 + warp_m * 32 + t * 16 + (lane >> 2);
        #pragma unroll
        for (int n = 0; n < 8; n++) {
            int col = n0 + warp_n * 64 + n * 8 + (lane & 3) * 2;
            float b0 = 0.f, b1 = 0.f;
            if (BIAS) { b0 = bias[col]; b1 = bias[col + 1]; }
            float v0 = acc[t][n][0] + b0, v1 = acc[t][n][1] + b1;
            float v2 = acc[t][n][2] + b0, v3 = acc[t][n][3] + b1;
            if (kreg) {
                // K region: write fp16 hi/lo planes directly (token-major)
                size_t k0o = (size_t)row0 * C_ + (col - 1024);
                size_t k1o = (size_t)(row0 + 8) * C_ + (col - 1024);
                uint32_t hi, lo;
                split_h16(v0, v1, hi, lo);
                *(uint32_t*)(Kh + k0o) = hi;
                *(uint32_t*)(Kl + k0o) = lo;
                split_h16(v2, v3, hi, lo);
                *(uint32_t*)(Kh + k1o) = hi;
                *(uint32_t*)(Kl + k1o) = lo;
            } else {
                size_t o0 = (size_t)row0 * N + col;
                size_t o1 = (size_t)(row0 + 8) * N + col;
                if (RESID) {
                    float2 r0 = *(const float2*)(resid + o0);
                    float2 r1 = *(const float2*)(resid + o1);
                    v0 += r0.x; v1 += r0.y; v2 += r1.x; v3 += r1.y;
                }
                *(float2*)(C + o0) = make_float2(v0, v1);
                *(float2*)(C + o1) = make_float2(v2, v3);
            }
        }
    }
}

// ======================= fp16 single-digit GEMM ========================
template <int BIAS, int RELU, int RESID, int OUTF16>
__global__ __launch_bounds__(256, 2) void gemm_f16(
    const __half* __restrict__ A, const __half* __restrict__ Bw,
    const float* __restrict__ bias, const float* __restrict__ resid,
    float* __restrict__ C, __half* __restrict__ C16, int N, int K)
{
    __shared__ char sm[F16_SMEM];
    uint32_t sb = smem_u32(sm);
    int tid = threadIdx.x;
    int lane = tid & 31, wid = tid >> 5;
    int warp_m = wid >> 1, warp_n = wid & 1;
    int m0 = blockIdx.x * 128, n0 = blockIdx.y * 128;
    const int NC = K >> 5;

    float acc[2][8][4];
    #pragma unroll
    for (int t = 0; t < 2; t++)
        #pragma unroll
        for (int n = 0; n < 8; n++)
            #pragma unroll
            for (int j = 0; j < 4; j++) acc[t][n][j] = 0.f;

    const __half* Abase = A + (size_t)(m0 + warp_m * 32 + (lane >> 2)) * K + ((lane & 3) << 1);

    auto issueB = [&](int c, int s) {
        int k0 = c << 5;
        #pragma unroll
        for (int j = 0; j < 2; j++) {
            int fi = tid + j * 256;
            int row = fi >> 2, c16 = (fi & 3) << 4;
            const char* g = (const char*)Bw + ((size_t)(n0 + row) * K + k0) * 2 + c16;
            CP_ASYNC16(sb + s * FSTG + row * FRS + c16, g);
        }
        CP_COMMIT();
    };

    auto compute = [&](int c, int s) {
        #pragma unroll
        for (int ks = 0; ks < 2; ks++) {
            int kbase = (c << 5) + (ks << 4);
            uint32_t ah[2][4];
            #pragma unroll
            for (int t = 0; t < 2; t++) {
                size_t o = (size_t)(t * 16) * K + kbase;
                ah[t][0] = *(const uint32_t*)(Abase + o);
                ah[t][1] = *(const uint32_t*)(Abase + o + (size_t)8 * K);
                ah[t][2] = *(const uint32_t*)(Abase + o + 8);
                ah[t][3] = *(const uint32_t*)(Abase + o + (size_t)8 * K + 8);
            }
            uint32_t bh[8][2];
            #pragma unroll
            for (int p = 0; p < 4; p++) {
                int row = warp_n * 64 + p * 16 + (lane & 7) + (((lane >> 4) & 1) << 3);
                uint32_t off = row * FRS + ks * 32 + (((lane >> 3) & 1) << 4);
                uint32_t r[4];
                ldmatrix_x4(r, sb + s * FSTG + off);
                bh[2 * p][0] = r[0]; bh[2 * p][1] = r[1];
                bh[2 * p + 1][0] = r[2]; bh[2 * p + 1][1] = r[3];
            }
            #pragma unroll
            for (int t = 0; t < 2; t++)
                #pragma unroll
                for (int n = 0; n < 8; n++)
                    mma_f16(acc[t][n], ah[t], bh[n][0], bh[n][1]);
        }
    };

    issueB(0, 0);
    issueB(1, 1);
    issueB(2, 2);

    for (int c = 0; c < NC; c++) {
        int s = c % 3;
        CP_WAIT2();
        __syncthreads();
        compute(c, s);
        __syncthreads();
        if (c + 3 < NC) issueB(c + 3, s);
    }

    #pragma unroll
    for (int t = 0; t < 2; t++) {
        int row0 = m0 + warp_m * 32 + t * 16 + (lane >> 2);
        #pragma unroll
        for (int n = 0; n < 8; n++) {
            int col = n0 + warp_n * 64 + n * 8 + (lane & 3) * 2;
            float b0 = 0.f, b1 = 0.f;
            if (BIAS) { b0 = bias[col]; b1 = bias[col + 1]; }
            float v0 = acc[t][n][0] + b0, v1 = acc[t][n][1] + b1;
            float v2 = acc[t][n][2] + b0, v3 = acc[t][n][3] + b1;
            size_t o0 = (size_t)row0 * N + col;
            size_t o1 = (size_t)(row0 + 8) * N + col;
            if (RESID) {
                float2 r0 = *(const float2*)(resid + o0);
                float2 r1 = *(const float2*)(resid + o1);
                v0 += r0.x; v1 += r0.y; v2 += r1.x; v3 += r1.y;
            }
            if (RELU) {
                v0 = fmaxf(v0, 0.f); v1 = fmaxf(v1, 0.f);
                v2 = fmaxf(v2, 0.f); v3 = fmaxf(v3, 0.f);
            }
            if (OUTF16) {
                *(uint32_t*)(C16 + o0) = pack_h16(v0, v1);
                *(uint32_t*)(C16 + o1) = pack_h16(v2, v3);
            } else {
                *(float2*)(C + o0) = make_float2(v0, v1);
                *(float2*)(C + o1) = make_float2(v2, v3);
            }
        }
    }
}

// ======================= embedding ====================================
__global__ __launch_bounds__(256) void embed_kernel(
    const int* __restrict__ idx, const float* __restrict__ tok,
    const float* __restrict__ pos, float* __restrict__ x)
{
    int bt = blockIdx.x;
    int t = bt & (T_ - 1);
    int token = idx[bt];
    int c = threadIdx.x * 4;
    float4 tv = *(const float4*)(tok + (size_t)token * C_ + c);
    float4 pv = *(const float4*)(pos + (size_t)t * C_ + c);
    *(float4*)(x + (size_t)bt * C_ + c) =
        make_float4(tv.x + pv.x, tv.y + pv.y, tv.z + pv.z, tv.w + pv.w);
}

// ======================= layernorm (OUT: 0=fp32, 1=fp16) ==============
template <int OUT>
__global__ __launch_bounds__(256) void ln_out_kernel(
    const float* __restrict__ x, const float* __restrict__ g,
    const float* __restrict__ b, float* __restrict__ yf, __half* __restrict__ yh)
{
    __shared__ float red[8];
    __shared__ float bc_mean, bc_inv;
    int row = blockIdx.x, tid = threadIdx.x;
    const float* xr = x + (size_t)row * C_;
    float4 xv = *(const float4*)(xr + tid * 4);
    float s = xv.x + xv.y + xv.z + xv.w;
    #pragma unroll
    for (int o = 16; o; o >>= 1) s += __shfl_xor_sync(0xffffffffu, s, o);
    if ((tid & 31) == 0) red[tid >> 5] = s;
    __syncthreads();
    if (tid == 0) {
        float t = 0.f;
        #pragma unroll
        for (int i = 0; i < 8; i++) t += red[i];
        bc_mean = t * (1.0f / C_);
    }
    __syncthreads();
    float mean = bc_mean;
    float d0 = xv.x - mean, d1 = xv.y - mean, d2 = xv.z - mean, d3 = xv.w - mean;
    float sq = d0 * d0 + d1 * d1 + d2 * d2 + d3 * d3;
    #pragma unroll
    for (int o = 16; o; o >>= 1) sq += __shfl_xor_sync(0xffffffffu, sq, o);
    if ((tid & 31) == 0) red[tid >> 5] = sq;
    __syncthreads();
    if (tid == 0) {
        float t = 0.f;
        #pragma unroll
        for (int i = 0; i < 8; i++) t += red[i];
        bc_inv = rsqrtf(t * (1.0f / C_) + 1e-5f);
    }
    __syncthreads();
    float inv = bc_inv;
    float4 gv = *(const float4*)(g + tid * 4);
    float4 bv = *(const float4*)(b + tid * 4);
    float y0 = d0 * inv * gv.x + bv.x;
    float y1 = d1 * inv * gv.y + bv.y;
    float y2 = d2 * inv * gv.z + bv.z;
    float y3 = d3 * inv * gv.w + bv.w;
    size_t off = (size_t)row * C_ + tid * 4;
    if (OUT == 0) {
        *(float4*)(yf + off) = make_float4(y0, y1, y2, y3);
    } else {
        *(uint2*)(yh + off) = make_uint2(pack_h16(y0, y1), pack_h16(y2, y3));
    }
}

// ======================= V pre-conversion (transpose) =================
__global__ __launch_bounds__(256) void vprep_kernel(
    const float* __restrict__ qkv, __half* __restrict__ vth, __half* __restrict__ vtl)
{
    __shared__ __half sh[64][65], sl[64][65];
    int kb = blockIdx.x, bhx = blockIdx.y;
    int b = bhx >> 4, hh = bhx & 15;
    int tid = threadIdx.x;
    int r = tid >> 2, d0 = (tid & 3) << 4;
    size_t grow = (size_t)(b * T_ + kb * 64 + r);
    const float* Vrow = qkv + grow * (3 * C_) + 2 * C_ + hh * 64;
    #pragma unroll
    for (int d = d0; d < d0 + 16; d += 2) {
        float2 vv = *(const float2*)(Vrow + d);
        __half hx = __float2half_rn(vv.x), hy = __float2half_rn(vv.y);
        sh[r][d] = hx; sh[r][d + 1] = hy;
        sl[r][d] = __float2half_rn(vv.x - __half2float(hx));
        sl[r][d + 1] = __float2half_rn(vv.y - __half2float(hy));
    }
    __syncthreads();
    int dd = tid >> 2, k0 = (tid & 3) << 4;
    __half* vht = vth + ((size_t)bhx * 16 + kb) * 4096 + dd * 64;
    __half* vlt = vtl + ((size_t)bhx * 16 + kb) * 4096 + dd * 64;
    #pragma unroll
    for (int k = k0; k < k0 + 16; k += 2) {
        uint32_t hv = ((uint32_t)__half_as_ushort(sh[k + 1][dd]) << 16) | __half_as_ushort(sh[k][dd]);
        uint32_t lv = ((uint32_t)__half_as_ushort(sl[k + 1][dd]) << 16) | __half_as_ushort(sl[k][dd]);
        *(uint32_t*)(vht + k) = hv;
        *(uint32_t*)(vlt + k) = lv;
    }
}

// ======================= tensor-core causal flash attention ===========
// (R11 version: 64 q-rows per block, keyhalf split)
#define ARS 72
#define AKV_BYTES (4 * 64 * ARS * 2)

__global__ __launch_bounds__(256) void attn_kernel(
    const float* __restrict__ QKV, const __half* __restrict__ khg,
    const __half* __restrict__ klg, const __half* __restrict__ vth,
    const __half* __restrict__ vtl, float* __restrict__ O)
{
    __shared__ __align__(16) char smb[AKV_BYTES + 1024];
    float* red0 = (float*)(smb + AKV_BYTES);
    float* red1 = red0 + 128;
    float* oex = (float*)smb;

    const int LDQ = 3 * C_;
    int qb = blockIdx.x, bhx = blockIdx.y;
    int b = bhx >> 4, hh = bhx & 15;
    const float* Qp = QKV + (size_t)b * T_ * LDQ + (size_t)hh * 64;
    size_t base_out = (size_t)b * T_ * C_ + (size_t)hh * 64;

    int tid = threadIdx.x, lane = tid & 31, wid = tid >> 5;
    int chunk = wid >> 1, keyhalf = wid & 1;
    int r0 = lane >> 2, c0 = (lane & 3) << 1;
    int rowl = chunk * 16 + r0;
    int growA = qb * 64 + rowl;

    uint32_t kbase = smem_u32(smb);
    uint32_t klbase = kbase + 64 * ARS * 2;
    uint32_t vbase = klbase + 64 * ARS * 2;
    uint32_t vlbase = vbase + 64 * ARS * 2;

    uint32_t qh[4][4], ql[4][4];
    #pragma unroll
    for (int s = 0; s < 4; s++)
        #pragma unroll
        for (int j = 0; j < 4; j++) {
            int grow = growA + ((j & 1) << 3);
            int gcol = s * 16 + c0 + ((j >> 1) << 3);
            float2 v = *(const float2*)(Qp + (size_t)grow * LDQ + gcol);
            split_h16(v.x, v.y, qh[s][j], ql[s][j]);
        }

    float m0 = -1e30f, m1 = -1e30f, l0 = 0.f, l1 = 0.f;
    float o[8][4];
    #pragma unroll
    for (int n = 0; n < 8; n++)
        #pragma unroll
        for (int j = 0; j < 4; j++) o[n][j] = 0.f;

    for (int kb = 0; kb <= qb; kb++) {
        {
            const __half* kh_t = khg + ((size_t)(b * T_ + kb * 64)) * C_ + hh * 64;
            const __half* kl_t = klg + ((size_t)(b * T_ + kb * 64)) * C_ + hh * 64;
            const __half* vh_t = vth + ((size_t)bhx * 16 + kb) * 4096;
            const __half* vl_t = vtl + ((size_t)bhx * 16 + kb) * 4096;
            #pragma unroll
            for (int j = 0; j < 2; j++) {
                int idx = tid + j * 256;
                int row = idx >> 3, cb = (idx & 7) << 4;
                CP_ASYNC16(kbase + row * 144 + cb, (const char*)(kh_t + (size_t)row * C_) + cb);
                CP_ASYNC16(klbase + row * 144 + cb, (const char*)(kl_t + (size_t)row * C_) + cb);
                CP_ASYNC16(vbase + row * 144 + cb, (const char*)(vh_t + row * 64) + cb);
                CP_ASYNC16(vlbase + row * 144 + cb, (const char*)(vl_t + row * 64) + cb);
            }
            CP_COMMIT();
            CP_WAIT0();
        }
        __syncthreads();

        float c[4][4];
        #pragma unroll
        for (int n = 0; n < 4; n++)
            #pragma unroll
            for (int j = 0; j < 4; j++) c[n][j] = 0.f;

        #pragma unroll
        for (int s = 0; s < 4; s++) {
            uint32_t bhf[4][2], blf[4][2];
            #pragma unroll
            for (int p = 0; p < 2; p++) {
                int krow = keyhalf * 32 + p * 16 + (lane & 7) + (((lane >> 4) & 1) << 3);
                uint32_t off = krow * (ARS * 2) + s * 32 + (((lane >> 3) & 1) << 4);
                uint32_t r[4];
                ldmatrix_x4(r, kbase + off);
                bhf[2 * p][0] = r[0]; bhf[2 * p][1] = r[1];
                bhf[2 * p + 1][0] = r[2]; bhf[2 * p + 1][1] = r[3];
                ldmatrix_x4(r, klbase + off);
                blf[2 * p][0] = r[0]; blf[2 * p][1] = r[1];
                blf[2 * p + 1][0] = r[2]; blf[2 * p + 1][1] = r[3];
            }
            #pragma unroll
            for (int n = 0; n < 4; n++) {
                mma_f16(c[n], qh[s], bhf[n][0], bhf[n][1]);
                mma_f16(c[n], ql[s], bhf[n][0], bhf[n][1]);
                mma_f16(c[n], qh[s], blf[n][0], blf[n][1]);
            }
        }

        #pragma unroll
        for (int n = 0; n < 4; n++)
            #pragma unroll
            for (int j = 0; j < 4; j++) c[n][j] *= 0.125f;
        if (kb == qb) {
            #pragma unroll
            for (int n = 0; n < 4; n++) {
                int gk = kb * 64 + keyhalf * 32 + n * 8 + c0;
                if (gk > growA)         c[n][0] = -1e30f;
                if (gk + 1 > growA)     c[n][1] = -1e30f;
                if (gk > growA + 8)     c[n][2] = -1e30f;
                if (gk + 1 > growA + 8) c[n][3] = -1e30f;
            }
        }

        float mx0 = fmaxf(fmaxf(c[0][0], c[0][1]), fmaxf(c[1][0], c[1][1]));
        mx0 = fmaxf(mx0, fmaxf(fmaxf(c[2][0], c[2][1]), fmaxf(c[3][0], c[3][1])));
        float mx1 = fmaxf(fmaxf(c[0][2], c[0][3]), fmaxf(c[1][2], c[1][3]));
        mx1 = fmaxf(mx1, fmaxf(fmaxf(c[2][2], c[2][3]), fmaxf(c[3][2], c[3][3])));
        mx0 = fmaxf(mx0, __shfl_xor_sync(0xffffffffu, mx0, 1));
        mx0 = fmaxf(mx0, __shfl_xor_sync(0xffffffffu, mx0, 2));
        mx1 = fmaxf(mx1, __shfl_xor_sync(0xffffffffu, mx1, 1));
        mx1 = fmaxf(mx1, __shfl_xor_sync(0xffffffffu, mx1, 2));
        if ((lane & 3) == 0) {
            red0[rowl * 2 + keyhalf] = mx0;
            red0[(rowl + 8) * 2 + keyhalf] = mx1;
        }
        __syncthreads();
        float mn0 = fmaxf(m0, fmaxf(red0[rowl * 2], red0[rowl * 2 + 1]));
        float mn1 = fmaxf(m1, fmaxf(red0[(rowl + 8) * 2], red0[(rowl + 8) * 2 + 1]));
        float corr0 = fexp(m0 - mn0), corr1 = fexp(m1 - mn1);
        m0 = mn0; m1 = mn1;

        float ls0 = 0.f, ls1 = 0.f;
        #pragma unroll
        for (int n = 0; n < 4; n++) {
            c[n][0] = fexp(c[n][0] - mn0); ls0 += c[n][0];
            c[n][1] = fexp(c[n][1] - mn0); ls0 += c[n][1];
            c[n][2] = fexp(c[n][2] - mn1); ls1 += c[n][2];
            c[n][3] = fexp(c[n][3] - mn1); ls1 += c[n][3];
        }
        ls0 += __shfl_xor_sync(0xffffffffu, ls0, 1);
        ls0 += __shfl_xor_sync(0xffffffffu, ls0, 2);
        ls1 += __shfl_xor_sync(0xffffffffu, ls1, 1);
        ls1 += __shfl_xor_sync(0xffffffffu, ls1, 2);
        if ((lane & 3) == 0) {
            red1[rowl * 2 + keyhalf] = ls0;
            red1[(rowl + 8) * 2 + keyhalf] = ls1;
        }
        l0 *= corr0; l1 *= corr1;
        #pragma unroll
        for (int n = 0; n < 8; n++) {
            o[n][0] *= corr0; o[n][1] *= corr0;
            o[n][2] *= corr1; o[n][3] *= corr1;
        }

        uint32_t ph[2][4], pl[2][4];
        #pragma unroll
        for (int k2 = 0; k2 < 2; k2++) {
            split_h16(c[2 * k2][0], c[2 * k2][1], ph[k2][0], pl[k2][0]);
            split_h16(c[2 * k2][2], c[2 * k2][3], ph[k2][1], pl[k2][1]);
            split_h16(c[2 * k2 + 1][0], c[2 * k2 + 1][1], ph[k2][2], pl[k2][2]);
            split_h16(c[2 * k2 + 1][2], c[2 * k2 + 1][3], ph[k2][3], pl[k2][3]);
        }

        #pragma unroll
        for (int k2 = 0; k2 < 2; k2++) {
            #pragma unroll
            for (int p = 0; p < 4; p++) {
                int vrow = p * 16 + (lane & 7) + (((lane >> 4) & 1) << 3);
                uint32_t off = vrow * (ARS * 2) + (keyhalf * 32 + k2 * 16) * 2 +
                               (((lane >> 3) & 1) << 4);
                uint32_t rv[4], rl[4];
                ldmatrix_x4(rv, vbase + off);
                ldmatrix_x4(rl, vlbase + off);
                mma_f16(o[2 * p],     ph[k2], rv[0], rv[1]);
                mma_f16(o[2 * p],     pl[k2], rv[0], rv[1]);
                mma_f16(o[2 * p],     ph[k2], rl[0], rl[1]);
                mma_f16(o[2 * p + 1], ph[k2], rv[2], rv[3]);
                mma_f16(o[2 * p + 1], pl[k2], rv[2], rv[3]);
                mma_f16(o[2 * p + 1], ph[k2], rl[2], rl[3]);
            }
        }
        __syncthreads();
        l0 += red1[rowl * 2] + red1[rowl * 2 + 1];
        l1 += red1[(rowl + 8) * 2] + red1[(rowl + 8) * 2 + 1];
    }

    __syncthreads();
    if (keyhalf == 1) {
        float* ox = oex + chunk * 1024;
        #pragma unroll
        for (int n = 0; n < 8; n++) {
            int d = n * 8 + c0;
            ox[r0 * 64 + d] = o[n][0];
            ox[r0 * 64 + d + 1] = o[n][1];
            ox[(r0 + 8) * 64 + d] = o[n][2];
            ox[(r0 + 8) * 64 + d + 1] = o[n][3];
        }
    }
    __syncthreads();
    if (keyhalf == 0) {
        const float* ox = oex + chunk * 1024;
        float inv0 = 1.0f / l0, inv1 = 1.0f / l1;
        #pragma unroll
        for (int n = 0; n < 8; n++) {
            int d = n * 8 + c0;
            float a0 = (o[n][0] + ox[r0 * 64 + d]) * inv0;
            float a1 = (o[n][1] + ox[r0 * 64 + d + 1]) * inv0;
            float a2 = (o[n][2] + ox[(r0 + 8) * 64 + d]) * inv1;
            float a3 = (o[n][3] + ox[(r0 + 8) * 64 + d + 1]) * inv1;
            *(float2*)(O + base_out + (size_t)growA * C_ + d) = make_float2(a0, a1);
            *(float2*)(O + base_out + (size_t)(growA + 8) * C_ + d) = make_float2(a2, a3);
        }
    }
}

// ======================= loss (single-pass online softmax) =============
__global__ void loss_init_kernel(float* loss) { *loss = 0.f; }

__global__ __launch_bounds__(256) void loss_kernel(
    const float* __restrict__ logits, const int* __restrict__ targets,
    float* __restrict__ loss)
{
    __shared__ float redm[8], reds[8];
    int row = blockIdx.x, tid = threadIdx.x;
    const float4* lr4 = (const float4*)(logits + (size_t)row * V_);

    float m = -1e30f, s = 0.f;
    for (int i = tid; i < V_ / 4; i += 256) {
        float4 u = lr4[i];
        float lm = fmaxf(fmaxf(u.x, u.y), fmaxf(u.z, u.w));
        if (lm > m) { s *= fexp(m - lm); m = lm; }
        s += fexp(u.x - m) + fexp(u.y - m) + fexp(u.z - m) + fexp(u.w - m);
    }
    // warp combine
    #pragma unroll
    for (int o = 16; o; o >>= 1) {
        float mo = __shfl_xor_sync(0xffffffffu, m, o);
        float so = __shfl_xor_sync(0xffffffffu, s, o);
        float mn = fmaxf(m, mo);
        s = s * fexp(m - mn) + so * fexp(mo - mn);
        m = mn;
    }
    if ((tid & 31) == 0) { redm[tid >> 5] = m; reds[tid >> 5] = s; }
    __syncthreads();
    if (tid == 0) {
        float mm = redm[0], ss = reds[0];
        #pragma unroll
        for (int i = 1; i < 8; i++) {
            float mn = fmaxf(mm, redm[i]);
            ss = ss * fexp(mm - mn) + reds[i] * fexp(redm[i] - mn);
            mm = mn;
        }
        int tgt = targets[row];
        float lp = logits[(size_t)row * V_ + tgt] - mm - logf(ss);
        atomicAdd(loss, -lp * (1.0f / M_));
    }
}

// ======================= host =========================================
extern "C" void kernel_launch(void* const* d_in, const int* in_sizes, int n_in,
                              void* d_out, int out_size)
{
    const int*   idx     = (const int*)d_in[0];
    const int*   targets = (const int*)d_in[1];
    const float* tok     = (const float*)d_in[2];
    const float* pos     = (const float*)d_in[3];
    const float* ln1g    = (const float*)d_in[4];
    const float* ln1b    = (const float*)d_in[5];
    const float* Wq      = (const float*)d_in[6];
    const float* Wk      = (const float*)d_in[7];
    const float* Wv      = (const float*)d_in[8];
    const float* Wo      = (const float*)d_in[9];
    const float* bo      = (const float*)d_in[10];
    const float* ln2g    = (const float*)d_in[11];
    const float* ln2b    = (const float*)d_in[12];
    const float* W1      = (const float*)d_in[13];
    const float* b1      = (const float*)d_in[14];
    const float* W2      = (const float*)d_in[15];
    const float* b2      = (const float*)d_in[16];
    const float* lnfg    = (const float*)d_in[17];
    const float* lnfb    = (const float*)d_in[18];
    const float* Wlm     = (const float*)d_in[19];
    const float* blm     = (const float*)d_in[20];

    static float *x, *h, *qkv, *lgbuf;
    static __half *h16, *mlp16, *wqkv16, *wo16, *w1f, *w2f, *wlm16;
    static __half *khg, *klg, *vth, *vtl;
    static bool init = false;
    if (!init) {
        cudaGetSymbolAddress((void**)&x, g_x);
        cudaGetSymbolAddress((void**)&h, g_h);
        cudaGetSymbolAddress((void**)&qkv, g_qkv);
        cudaGetSymbolAddress((void**)&lgbuf, g_logits);
        cudaGetSymbolAddress((void**)&h16, g_h16);
        cudaGetSymbolAddress((void**)&mlp16, g_mlp16);
        cudaGetSymbolAddress((void**)&wqkv16, g_wqkv16);
        cudaGetSymbolAddress((void**)&wo16, g_wo16);
        cudaGetSymbolAddress((void**)&w1f, g_w1f);
        cudaGetSymbolAddress((void**)&w2f, g_w2f);
        cudaGetSymbolAddress((void**)&wlm16, g_wlm16);
        cudaGetSymbolAddress((void**)&khg, g_kh);
        cudaGetSymbolAddress((void**)&klg, g_kl);
        cudaGetSymbolAddress((void**)&vth, g_vth);
        cudaGetSymbolAddress((void**)&vtl, g_vtl);
        init = true;
    }

    const size_t NTV = (size_t)M_ * V_;
    float* logits_ptr = ((size_t)out_size >= NTV) ? (float*)d_out : lgbuf;
    float* loss_ptr = nullptr;
    if ((size_t)out_size == NTV + 1)     loss_ptr = (float*)d_out + NTV;
    else if ((size_t)out_size < NTV)     loss_ptr = (float*)d_out;

    const size_t CC = (size_t)C_ * C_;
    const size_t C3 = 3 * CC;
    const size_t C4 = 4 * CC;

    // ---- weight prep (all fp16 [N,K]) ----
    wsplit_f16_kernel<<<dim3(C_ / 32, C_ / 32, L_), 256>>>(Wq, wqkv16 + 0 * CC, C_, C_, C3);
    wsplit_f16_kernel<<<dim3(C_ / 32, C_ / 32, L_), 256>>>(Wk, wqkv16 + 1 * CC, C_, C_, C3);
    wsplit_f16_kernel<<<dim3(C_ / 32, C_ / 32, L_), 256>>>(Wv, wqkv16 + 2 * CC, C_, C_, C3);
    wsplit_f16_kernel<<<dim3(C_ / 32, C_ / 32, L_), 256>>>(Wo, wo16, C_, C_, CC);
    wsplit_f16_kernel<<<dim3(4 * C_ / 32, C_ / 32, L_), 256>>>(W1, w1f, C_, 4 * C_, C4);
    wsplit_f16_kernel<<<dim3(C_ / 32, 4 * C_ / 32, L_), 256>>>(W2, w2f, 4 * C_, C_, C4);
    wsplit_f16_kernel<<<dim3(V_ / 32, C_ / 32, 1), 256>>>(Wlm, wlm16, C_, V_, 0);

    dim3 gqkv(M_ / 128, 3 * C_ / 128);
    dim3 g1(M_ / 128, C_ / 128);
    dim3 g4(M_ / 128, 4 * C_ / 128);
    dim3 gl(M_ / 128, V_ / 128);
    dim3 gkv(T_ / 64, B_ * H_);

    embed_kernel<<<M_, 256>>>(idx, tok, pos, x);

    for (int l = 0; l < L_; l++) {
        ln_out_kernel<0><<<M_, 256>>>(x, ln1g + (size_t)l * C_, ln1b + (size_t)l * C_, h, nullptr);
        gemm_f16a2<0,0,1><<<gqkv, 256>>>(h, wqkv16 + (size_t)l * C3, nullptr, nullptr,
                                         qkv, khg, klg, 3 * C_, C_);
        vprep_kernel<<<gkv, 256>>>(qkv, vth, vtl);
        attn_kernel<<<gkv, 256>>>(qkv, khg, klg, vth, vtl, h);
        gemm_f16a2<1,1,0><<<g1, 256>>>(h, wo16 + (size_t)l * CC, bo + (size_t)l * C_, x,
                                       x, nullptr, nullptr, C_, C_);
        ln_out_kernel<1><<<M_, 256>>>(x, ln2g + (size_t)l * C_, ln2b + (size_t)l * C_, nullptr, h16);
        gemm_f16<1,1,0,1><<<g4, 256>>>(h16, w1f + (size_t)l * C4,
            b1 + (size_t)l * 4 * C_, nullptr, nullptr, mlp16, 4 * C_, C_);
        gemm_f16<1,0,1,0><<<g1, 256>>>(mlp16, w2f + (size_t)l * C4,
            b2 + (size_t)l * C_, x, x, nullptr, C_, 4 * C_);
    }

    ln_out_kernel<1><<<M_, 256>>>(x, lnfg, lnfb, nullptr, h16);
    gemm_f16<1,0,0,0><<<gl, 256>>>(h16, wlm16, blm, nullptr, logits_ptr, nullptr, V_, C_);

    if (loss_ptr) {
        loss_init_kernel<<<1, 1>>>(loss_ptr);
        loss_kernel<<<M_, 256>>>(logits_ptr, targets, loss_ptr);
    }
}

// round 14
// speedup vs baseline: 1.0538x; 1.0122x over previous
#include <cuda_runtime.h>
#include <cuda_fp16.h>
#include <math.h>
#include <stdint.h>

#define T_ 1024
#define C_ 1024
#define B_ 4
#define H_ 16
#define L_ 12
#define V_ 50304
#define M_ 4096   // B*T tokens

// ======================= scratch (device globals) =======================
__device__ float g_x[(size_t)M_ * C_];
__device__ float g_h[(size_t)M_ * C_];
__device__ float g_qkv[(size_t)M_ * 3 * C_];
__device__ float g_logits[(size_t)M_ * V_];
__device__ __half g_h16[(size_t)M_ * C_];
__device__ __half g_mlp16[(size_t)M_ * 4 * C_];
__device__ __half g_kh[(size_t)M_ * C_];
__device__ __half g_kl[(size_t)M_ * C_];
__device__ __half g_vth[(size_t)M_ * C_];
__device__ __half g_vtl[(size_t)M_ * C_];
__device__ __half g_wqkv16[(size_t)L_ * 3 * C_ * C_];
__device__ __half g_wo16[(size_t)L_ * C_ * C_];
__device__ __half g_w1f[(size_t)L_ * C_ * 4 * C_];
__device__ __half g_w2f[(size_t)L_ * 4 * C_ * C_];
__device__ __half g_wlm16[(size_t)V_ * C_];

// ======================= small asm helpers =======================
__device__ __forceinline__ uint32_t smem_u32(const void* p) {
    uint32_t a;
    asm("{ .reg .u64 t; cvta.to.shared.u64 t, %1; cvt.u32.u64 %0, t; }" : "=r"(a) : "l"(p));
    return a;
}
__device__ __forceinline__ void ldmatrix_x4(uint32_t* r, uint32_t addr) {
    asm volatile("ldmatrix.sync.aligned.m8n8.x4.shared.b16 {%0,%1,%2,%3}, [%4];"
        : "=r"(r[0]), "=r"(r[1]), "=r"(r[2]), "=r"(r[3]) : "r"(addr));
}
__device__ __forceinline__ void mma_f16(float* d, const uint32_t* a, uint32_t b0, uint32_t b1) {
    asm volatile(
        "mma.sync.aligned.m16n8k16.row.col.f32.f16.f16.f32 "
        "{%0,%1,%2,%3}, {%4,%5,%6,%7}, {%8,%9}, {%0,%1,%2,%3};"
        : "+f"(d[0]), "+f"(d[1]), "+f"(d[2]), "+f"(d[3])
        : "r"(a[0]), "r"(a[1]), "r"(a[2]), "r"(a[3]), "r"(b0), "r"(b1));
}
#define CP_ASYNC16(dst, src) \
    asm volatile("cp.async.cg.shared.global [%0], [%1], 16;" :: "r"(dst), "l"(src))
#define CP_COMMIT() asm volatile("cp.async.commit_group;")
#define CP_WAIT2()  asm volatile("cp.async.wait_group 2;")
#define CP_WAIT1()  asm volatile("cp.async.wait_group 1;")
#define CP_WAIT0()  asm volatile("cp.async.wait_group 0;")

__device__ __forceinline__ uint32_t pack_h16(float x, float y) {
    __half2 h = __floats2half2_rn(x, y);
    return *(uint32_t*)&h;
}
__device__ __forceinline__ void split_h16(float x, float y, uint32_t& hi, uint32_t& lo) {
    __half hx = __float2half_rn(x), hy = __float2half_rn(y);
    hi = ((uint32_t)__half_as_ushort(hy) << 16) | __half_as_ushort(hx);
    lo = pack_h16(x - __half2float(hx), y - __half2float(hy));
}

// fast exp on the FMA pipe
__device__ __forceinline__ float fexp(float x) {
    float t = fmaxf(x, -80.0f) * 1.442695041f;
    float n = floorf(t);
    float f = t - n;
    float p = 0.0013276471f;
    p = p * f + 0.0096755413f;
    p = p * f + 0.0555041086f;
    p = p * f + 0.2402264923f;
    p = p * f + 0.6931471825f;
    p = p * f + 1.0f;
    return __int_as_float(((int)n << 23) + __float_as_int(p));
}

// ======================= weight prep (fp32 [K,N] -> fp16 [N,K]) ========
__global__ __launch_bounds__(256) void wsplit_f16_kernel(
    const float* __restrict__ W, __half* __restrict__ out, int K, int N, size_t out_ls)
{
    __shared__ float t[32][33];
    const float* Wl = W + (size_t)blockIdx.z * K * N;
    __half* ol = out + (size_t)blockIdx.z * out_ls;
    int n0 = blockIdx.x * 32, k0 = blockIdx.y * 32;
    int tx = threadIdx.x & 31, ty = threadIdx.x >> 5;
    #pragma unroll
    for (int i = 0; i < 4; i++)
        t[ty + 8 * i][tx] = Wl[(size_t)(k0 + ty + 8 * i) * N + n0 + tx];
    __syncthreads();
    #pragma unroll
    for (int i = 0; i < 4; i++) {
        float v = t[tx][ty + 8 * i];
        ol[(size_t)(n0 + ty + 8 * i) * K + k0 + tx] = __float2half(v);
    }
}

// ======================= fp16 2-term GEMM (fp32 A, fp16 W) =============
#define FRS 80
#define FSTG (128 * FRS)
#define F16_SMEM (3 * FSTG)

template <int BIAS, int RESID, int KSPLIT>
__global__ __launch_bounds__(256, 2) void gemm_f16a2(
    const float* __restrict__ A, const __half* __restrict__ Bw,
    const float* __restrict__ bias, const float* __restrict__ resid,
    float* __restrict__ C, __half* __restrict__ Kh, __half* __restrict__ Kl,
    int N, int K)
{
    __shared__ char sm[F16_SMEM];
    uint32_t sb = smem_u32(sm);
    int tid = threadIdx.x;
    int lane = tid & 31, wid = tid >> 5;
    int warp_m = wid >> 1, warp_n = wid & 1;
    int m0 = blockIdx.x * 128, n0 = blockIdx.y * 128;
    const int NC = K >> 5;

    float acc[2][8][4];
    #pragma unroll
    for (int t = 0; t < 2; t++)
        #pragma unroll
        for (int n = 0; n < 8; n++)
            #pragma unroll
            for (int j = 0; j < 4; j++) acc[t][n][j] = 0.f;

    const float* Abase = A + (size_t)(m0 + warp_m * 32 + (lane >> 2)) * K + (lane & 3) * 2;

    auto issueB = [&](int c, int s) {
        int k0 = c << 5;
        #pragma unroll
        for (int j = 0; j < 2; j++) {
            int fi = tid + j * 256;
            int row = fi >> 2, c16 = (fi & 3) << 4;
            const char* g = (const char*)Bw + ((size_t)(n0 + row) * K + k0) * 2 + c16;
            CP_ASYNC16(sb + s * FSTG + row * FRS + c16, g);
        }
        CP_COMMIT();
    };

    auto compute = [&](int c, int s) {
        #pragma unroll
        for (int ks = 0; ks < 2; ks++) {
            int kbase = (c << 5) + (ks << 4);
            float2 f[2][4];
            #pragma unroll
            for (int t = 0; t < 2; t++) {
                const float* ap = Abase + (size_t)t * 16 * K + kbase;
                f[t][0] = *(const float2*)(ap);
                f[t][1] = *(const float2*)(ap + (size_t)8 * K);
                f[t][2] = *(const float2*)(ap + 8);
                f[t][3] = *(const float2*)(ap + (size_t)8 * K + 8);
            }
            uint32_t bh[8][2];
            #pragma unroll
            for (int p = 0; p < 4; p++) {
                int row = warp_n * 64 + p * 16 + (lane & 7) + (((lane >> 4) & 1) << 3);
                uint32_t off = row * FRS + ks * 32 + (((lane >> 3) & 1) << 4);
                uint32_t r[4];
                ldmatrix_x4(r, sb + s * FSTG + off);
                bh[2 * p][0] = r[0]; bh[2 * p][1] = r[1];
                bh[2 * p + 1][0] = r[2]; bh[2 * p + 1][1] = r[3];
            }
            uint32_t ah[2][4], al[2][4];
            #pragma unroll
            for (int t = 0; t < 2; t++)
                #pragma unroll
                for (int j = 0; j < 4; j++)
                    split_h16(f[t][j].x, f[t][j].y, ah[t][j], al[t][j]);
            #pragma unroll
            for (int t = 0; t < 2; t++)
                #pragma unroll
                for (int n = 0; n < 8; n++) {
                    mma_f16(acc[t][n], ah[t], bh[n][0], bh[n][1]);
                    mma_f16(acc[t][n], al[t], bh[n][0], bh[n][1]);
                }
        }
    };

    issueB(0, 0);
    issueB(1, 1);
    issueB(2, 2);

    for (int c = 0; c < NC; c++) {
        int s = c % 3;
        CP_WAIT2();
        __syncthreads();
        compute(c, s);
        __syncthreads();
        if (c + 3 < NC) issueB(c + 3, s);
    }

    bool kreg = KSPLIT && (n0 >= 1024) && (n0 < 2048);
    #pragma unroll
    for (int t = 0; t < 2; t++) {
        int row0 = m0 + warp_m * 32 + t * 16 + (lane >> 2);
        #pragma unroll
        for (int n = 0; n < 8; n++) {
            int col = n0 + warp_n * 64 + n * 8 + (lane & 3) * 2;
            float b0 = 0.f, b1 = 0.f;
            if (BIAS) { b0 = bias[col]; b1 = bias[col + 1]; }
            float v0 = acc[t][n][0] + b0, v1 = acc[t][n][1] + b1;
            float v2 = acc[t][n][2] + b0, v3 = acc[t][n][3] + b1;
            if (kreg) {
                size_t k0o = (size_t)row0 * C_ + (col - 1024);
                size_t k1o = (size_t)(row0 + 8) * C_ + (col - 1024);
                uint32_t hi, lo;
                split_h16(v0, v1, hi, lo);
                *(uint32_t*)(Kh + k0o) = hi;
                *(uint32_t*)(Kl + k0o) = lo;
                split_h16(v2, v3, hi, lo);
                *(uint32_t*)(Kh + k1o) = hi;
                *(uint32_t*)(Kl + k1o) = lo;
            } else {
                size_t o0 = (size_t)row0 * N + col;
                size_t o1 = (size_t)(row0 + 8) * N + col;
                if (RESID) {
                    float2 r0 = *(const float2*)(resid + o0);
                    float2 r1 = *(const float2*)(resid + o1);
                    v0 += r0.x; v1 += r0.y; v2 += r1.x; v3 += r1.y;
                }
                *(float2*)(C + o0) = make_float2(v0, v1);
                *(float2*)(C + o1) = make_float2(v2, v3);
            }
        }
    }
}

// ======================= fp16 single-digit GEMM ========================
template <int BIAS, int RELU, int RESID, int OUTF16>
__global__ __launch_bounds__(256, 2) void gemm_f16(
    const __half* __restrict__ A, const __half* __restrict__ Bw,
    const float* __restrict__ bias, const float* __restrict__ resid,
    float* __restrict__ C, __half* __restrict__ C16, int N, int K)
{
    __shared__ char sm[F16_SMEM];
    uint32_t sb = smem_u32(sm);
    int tid = threadIdx.x;
    int lane = tid & 31, wid = tid >> 5;
    int warp_m = wid >> 1, warp_n = wid & 1;
    int m0 = blockIdx.x * 128, n0 = blockIdx.y * 128;
    const int NC = K >> 5;

    float acc[2][8][4];
    #pragma unroll
    for (int t = 0; t < 2; t++)
        #pragma unroll
        for (int n = 0; n < 8; n++)
            #pragma unroll
            for (int j = 0; j < 4; j++) acc[t][n][j] = 0.f;

    const __half* Abase = A + (size_t)(m0 + warp_m * 32 + (lane >> 2)) * K + ((lane & 3) << 1);

    auto issueB = [&](int c, int s) {
        int k0 = c << 5;
        #pragma unroll
        for (int j = 0; j < 2; j++) {
            int fi = tid + j * 256;
            int row = fi >> 2, c16 = (fi & 3) << 4;
            const char* g = (const char*)Bw + ((size_t)(n0 + row) * K + k0) * 2 + c16;
            CP_ASYNC16(sb + s * FSTG + row * FRS + c16, g);
        }
        CP_COMMIT();
    };

    auto compute = [&](int c, int s) {
        #pragma unroll
        for (int ks = 0; ks < 2; ks++) {
            int kbase = (c << 5) + (ks << 4);
            uint32_t ah[2][4];
            #pragma unroll
            for (int t = 0; t < 2; t++) {
                size_t o = (size_t)(t * 16) * K + kbase;
                ah[t][0] = *(const uint32_t*)(Abase + o);
                ah[t][1] = *(const uint32_t*)(Abase + o + (size_t)8 * K);
                ah[t][2] = *(const uint32_t*)(Abase + o + 8);
                ah[t][3] = *(const uint32_t*)(Abase + o + (size_t)8 * K + 8);
            }
            uint32_t bh[8][2];
            #pragma unroll
            for (int p = 0; p < 4; p++) {
                int row = warp_n * 64 + p * 16 + (lane & 7) + (((lane >> 4) & 1) << 3);
                uint32_t off = row * FRS + ks * 32 + (((lane >> 3) & 1) << 4);
                uint32_t r[4];
                ldmatrix_x4(r, sb + s * FSTG + off);
                bh[2 * p][0] = r[0]; bh[2 * p][1] = r[1];
                bh[2 * p + 1][0] = r[2]; bh[2 * p + 1][1] = r[3];
            }
            #pragma unroll
            for (int t = 0; t < 2; t++)
                #pragma unroll
                for (int n = 0; n < 8; n++)
                    mma_f16(acc[t][n], ah[t], bh[n][0], bh[n][1]);
        }
    };

    issueB(0, 0);
    issueB(1, 1);
    issueB(2, 2);

    for (int c = 0; c < NC; c++) {
        int s = c % 3;
        CP_WAIT2();
        __syncthreads();
        compute(c, s);
        __syncthreads();
        if (c + 3 < NC) issueB(c + 3, s);
    }

    #pragma unroll
    for (int t = 0; t < 2; t++) {
        int row0 = m0 + warp_m * 32 + t * 16 + (lane >> 2);
        #pragma unroll
        for (int n = 0; n < 8; n++) {
            int col = n0 + warp_n * 64 + n * 8 + (lane & 3) * 2;
            float b0 = 0.f, b1 = 0.f;
            if (BIAS) { b0 = bias[col]; b1 = bias[col + 1]; }
            float v0 = acc[t][n][0] + b0, v1 = acc[t][n][1] + b1;
            float v2 = acc[t][n][2] + b0, v3 = acc[t][n][3] + b1;
            size_t o0 = (size_t)row0 * N + col;
            size_t o1 = (size_t)(row0 + 8) * N + col;
            if (RESID) {
                float2 r0 = *(const float2*)(resid + o0);
                float2 r1 = *(const float2*)(resid + o1);
                v0 += r0.x; v1 += r0.y; v2 += r1.x; v3 += r1.y;
            }
            if (RELU) {
                v0 = fmaxf(v0, 0.f); v1 = fmaxf(v1, 0.f);
                v2 = fmaxf(v2, 0.f); v3 = fmaxf(v3, 0.f);
            }
            if (OUTF16) {
                *(uint32_t*)(C16 + o0) = pack_h16(v0, v1);
                *(uint32_t*)(C16 + o1) = pack_h16(v2, v3);
            } else {
                *(float2*)(C + o0) = make_float2(v0, v1);
                *(float2*)(C + o1) = make_float2(v2, v3);
            }
        }
    }
}

// ======================= embedding ====================================
__global__ __launch_bounds__(256) void embed_kernel(
    const int* __restrict__ idx, const float* __restrict__ tok,
    const float* __restrict__ pos, float* __restrict__ x)
{
    int bt = blockIdx.x;
    int t = bt & (T_ - 1);
    int token = idx[bt];
    int c = threadIdx.x * 4;
    float4 tv = *(const float4*)(tok + (size_t)token * C_ + c);
    float4 pv = *(const float4*)(pos + (size_t)t * C_ + c);
    *(float4*)(x + (size_t)bt * C_ + c) =
        make_float4(tv.x + pv.x, tv.y + pv.y, tv.z + pv.z, tv.w + pv.w);
}

// ======================= layernorm (OUT: 0=fp32, 1=fp16) ==============
template <int OUT>
__global__ __launch_bounds__(256) void ln_out_kernel(
    const float* __restrict__ x, const float* __restrict__ g,
    const float* __restrict__ b, float* __restrict__ yf, __half* __restrict__ yh)
{
    __shared__ float red[8];
    __shared__ float bc_mean, bc_inv;
    int row = blockIdx.x, tid = threadIdx.x;
    const float* xr = x + (size_t)row * C_;
    float4 xv = *(const float4*)(xr + tid * 4);
    float s = xv.x + xv.y + xv.z + xv.w;
    #pragma unroll
    for (int o = 16; o; o >>= 1) s += __shfl_xor_sync(0xffffffffu, s, o);
    if ((tid & 31) == 0) red[tid >> 5] = s;
    __syncthreads();
    if (tid == 0) {
        float t = 0.f;
        #pragma unroll
        for (int i = 0; i < 8; i++) t += red[i];
        bc_mean = t * (1.0f / C_);
    }
    __syncthreads();
    float mean = bc_mean;
    float d0 = xv.x - mean, d1 = xv.y - mean, d2 = xv.z - mean, d3 = xv.w - mean;
    float sq = d0 * d0 + d1 * d1 + d2 * d2 + d3 * d3;
    #pragma unroll
    for (int o = 16; o; o >>= 1) sq += __shfl_xor_sync(0xffffffffu, sq, o);
    if ((tid & 31) == 0) red[tid >> 5] = sq;
    __syncthreads();
    if (tid == 0) {
        float t = 0.f;
        #pragma unroll
        for (int i = 0; i < 8; i++) t += red[i];
        bc_inv = rsqrtf(t * (1.0f / C_) + 1e-5f);
    }
    __syncthreads();
    float inv = bc_inv;
    float4 gv = *(const float4*)(g + tid * 4);
    float4 bv = *(const float4*)(b + tid * 4);
    float y0 = d0 * inv * gv.x + bv.x;
    float y1 = d1 * inv * gv.y + bv.y;
    float y2 = d2 * inv * gv.z + bv.z;
    float y3 = d3 * inv * gv.w + bv.w;
    size_t off = (size_t)row * C_ + tid * 4;
    if (OUT == 0) {
        *(float4*)(yf + off) = make_float4(y0, y1, y2, y3);
    } else {
        *(uint2*)(yh + off) = make_uint2(pack_h16(y0, y1), pack_h16(y2, y3));
    }
}

// ======================= V pre-conversion (transpose) =================
__global__ __launch_bounds__(256) void vprep_kernel(
    const float* __restrict__ qkv, __half* __restrict__ vth, __half* __restrict__ vtl)
{
    __shared__ __half sh[64][65], sl[64][65];
    int kb = blockIdx.x, bhx = blockIdx.y;
    int b = bhx >> 4, hh = bhx & 15;
    int tid = threadIdx.x;
    int r = tid >> 2, d0 = (tid & 3) << 4;
    size_t grow = (size_t)(b * T_ + kb * 64 + r);
    const float* Vrow = qkv + grow * (3 * C_) + 2 * C_ + hh * 64;
    #pragma unroll
    for (int d = d0; d < d0 + 16; d += 2) {
        float2 vv = *(const float2*)(Vrow + d);
        __half hx = __float2half_rn(vv.x), hy = __float2half_rn(vv.y);
        sh[r][d] = hx; sh[r][d + 1] = hy;
        sl[r][d] = __float2half_rn(vv.x - __half2float(hx));
        sl[r][d + 1] = __float2half_rn(vv.y - __half2float(hy));
    }
    __syncthreads();
    int dd = tid >> 2, k0 = (tid & 3) << 4;
    __half* vht = vth + ((size_t)bhx * 16 + kb) * 4096 + dd * 64;
    __half* vlt = vtl + ((size_t)bhx * 16 + kb) * 4096 + dd * 64;
    #pragma unroll
    for (int k = k0; k < k0 + 16; k += 2) {
        uint32_t hv = ((uint32_t)__half_as_ushort(sh[k + 1][dd]) << 16) | __half_as_ushort(sh[k][dd]);
        uint32_t lv = ((uint32_t)__half_as_ushort(sl[k + 1][dd]) << 16) | __half_as_ushort(sl[k][dd]);
        *(uint32_t*)(vht + k) = hv;
        *(uint32_t*)(vlt + k) = lv;
    }
}

// ======================= tensor-core causal flash attention ===========
// 64 q-rows/block, keyhalf split; 2-stage cp.async KV ring (dynamic smem).
#define ARS 72
#define ASTG (4 * 64 * ARS * 2)             // one stage: Kh,Kl,Vh,Vl = 36864
#define ATTN_SMEM (2 * ASTG + 1024)         // 74752

__global__ __launch_bounds__(256) void attn_kernel(
    const float* __restrict__ QKV, const __half* __restrict__ khg,
    const __half* __restrict__ klg, const __half* __restrict__ vth,
    const __half* __restrict__ vtl, float* __restrict__ O)
{
    extern __shared__ __align__(16) char smb[];
    float* red0 = (float*)(smb + 2 * ASTG);
    float* red1 = red0 + 128;
    float* oex = (float*)smb;

    const int LDQ = 3 * C_;
    int qb = blockIdx.x, bhx = blockIdx.y;
    int b = bhx >> 4, hh = bhx & 15;
    const float* Qp = QKV + (size_t)b * T_ * LDQ + (size_t)hh * 64;
    size_t base_out = (size_t)b * T_ * C_ + (size_t)hh * 64;

    int tid = threadIdx.x, lane = tid & 31, wid = tid >> 5;
    int chunk = wid >> 1, keyhalf = wid & 1;
    int r0 = lane >> 2, c0 = (lane & 3) << 1;
    int rowl = chunk * 16 + r0;
    int growA = qb * 64 + rowl;

    uint32_t sbase = smem_u32(smb);

    // ---- Q fragments (hi/lo fp16), pre-scaled by 1/8 (exact pow2) ----
    uint32_t qh[4][4], ql[4][4];
    #pragma unroll
    for (int s = 0; s < 4; s++)
        #pragma unroll
        for (int j = 0; j < 4; j++) {
            int grow = growA + ((j & 1) << 3);
            int gcol = s * 16 + c0 + ((j >> 1) << 3);
            float2 v = *(const float2*)(Qp + (size_t)grow * LDQ + gcol);
            split_h16(v.x * 0.125f, v.y * 0.125f, qh[s][j], ql[s][j]);
        }

    float m0 = -1e30f, m1 = -1e30f, l0 = 0.f, l1 = 0.f;
    float o[8][4];
    #pragma unroll
    for (int n = 0; n < 8; n++)
        #pragma unroll
        for (int j = 0; j < 4; j++) o[n][j] = 0.f;

    auto issueKV = [&](int kb, int st) {
        const __half* kh_t = khg + ((size_t)(b * T_ + kb * 64)) * C_ + hh * 64;
        const __half* kl_t = klg + ((size_t)(b * T_ + kb * 64)) * C_ + hh * 64;
        const __half* vh_t = vth + ((size_t)bhx * 16 + kb) * 4096;
        const __half* vl_t = vtl + ((size_t)bhx * 16 + kb) * 4096;
        uint32_t sk = sbase + st * ASTG;
        #pragma unroll
        for (int j = 0; j < 2; j++) {
            int idx = tid + j * 256;
            int row = idx >> 3, cb = (idx & 7) << 4;
            CP_ASYNC16(sk + row * 144 + cb, (const char*)(kh_t + (size_t)row * C_) + cb);
            CP_ASYNC16(sk + 64 * 144 + row * 144 + cb, (const char*)(kl_t + (size_t)row * C_) + cb);
            CP_ASYNC16(sk + 2 * 64 * 144 + row * 144 + cb, (const char*)(vh_t + row * 64) + cb);
            CP_ASYNC16(sk + 3 * 64 * 144 + row * 144 + cb, (const char*)(vl_t + row * 64) + cb);
        }
        CP_COMMIT();
    };

    issueKV(0, 0);
    if (qb >= 1) issueKV(1, 1); else CP_COMMIT();

    for (int kb = 0; kb <= qb; kb++) {
        int st = kb & 1;
        uint32_t kbase = sbase + st * ASTG;
        uint32_t klbase = kbase + 64 * ARS * 2;
        uint32_t vbase = klbase + 64 * ARS * 2;
        uint32_t vlbase = vbase + 64 * ARS * 2;

        CP_WAIT1();
        __syncthreads();

        // ---- S = Q K^T (3-term) ----
        float c[4][4];
        #pragma unroll
        for (int n = 0; n < 4; n++)
            #pragma unroll
            for (int j = 0; j < 4; j++) c[n][j] = 0.f;

        #pragma unroll
        for (int s = 0; s < 4; s++) {
            uint32_t bhf[4][2], blf[4][2];
            #pragma unroll
            for (int p = 0; p < 2; p++) {
                int krow = keyhalf * 32 + p * 16 + (lane & 7) + (((lane >> 4) & 1) << 3);
                uint32_t off = krow * (ARS * 2) + s * 32 + (((lane >> 3) & 1) << 4);
                uint32_t r[4];
                ldmatrix_x4(r, kbase + off);
                bhf[2 * p][0] = r[0]; bhf[2 * p][1] = r[1];
                bhf[2 * p + 1][0] = r[2]; bhf[2 * p + 1][1] = r[3];
                ldmatrix_x4(r, klbase + off);
                blf[2 * p][0] = r[0]; blf[2 * p][1] = r[1];
                blf[2 * p + 1][0] = r[2]; blf[2 * p + 1][1] = r[3];
            }
            #pragma unroll
            for (int n = 0; n < 4; n++) {
                mma_f16(c[n], qh[s], bhf[n][0], bhf[n][1]);
                mma_f16(c[n], ql[s], bhf[n][0], bhf[n][1]);
                mma_f16(c[n], qh[s], blf[n][0], blf[n][1]);
            }
        }

        if (kb == qb) {
            #pragma unroll
            for (int n = 0; n < 4; n++) {
                int gk = kb * 64 + keyhalf * 32 + n * 8 + c0;
                if (gk > growA)         c[n][0] = -1e30f;
                if (gk + 1 > growA)     c[n][1] = -1e30f;
                if (gk > growA + 8)     c[n][2] = -1e30f;
                if (gk + 1 > growA + 8) c[n][3] = -1e30f;
            }
        }

        // ---- online softmax (cross-warp via red0/red1) ----
        float mx0 = fmaxf(fmaxf(c[0][0], c[0][1]), fmaxf(c[1][0], c[1][1]));
        mx0 = fmaxf(mx0, fmaxf(fmaxf(c[2][0], c[2][1]), fmaxf(c[3][0], c[3][1])));
        float mx1 = fmaxf(fmaxf(c[0][2], c[0][3]), fmaxf(c[1][2], c[1][3]));
        mx1 = fmaxf(mx1, fmaxf(fmaxf(c[2][2], c[2][3]), fmaxf(c[3][2], c[3][3])));
        mx0 = fmaxf(mx0, __shfl_xor_sync(0xffffffffu, mx0, 1));
        mx0 = fmaxf(mx0, __shfl_xor_sync(0xffffffffu, mx0, 2));
        mx1 = fmaxf(mx1, __shfl_xor_sync(0xffffffffu, mx1, 1));
        mx1 = fmaxf(mx1, __shfl_xor_sync(0xffffffffu, mx1, 2));
        if ((lane & 3) == 0) {
            red0[rowl * 2 + keyhalf] = mx0;
            red0[(rowl + 8) * 2 + keyhalf] = mx1;
        }
        __syncthreads();
        float mn0 = fmaxf(m0, fmaxf(red0[rowl * 2], red0[rowl * 2 + 1]));
        float mn1 = fmaxf(m1, fmaxf(red0[(rowl + 8) * 2], red0[(rowl + 8) * 2 + 1]));
        float corr0 = fexp(m0 - mn0), corr1 = fexp(m1 - mn1);
        m0 = mn0; m1 = mn1;

        float ls0 = 0.f, ls1 = 0.f;
        #pragma unroll
        for (int n = 0; n < 4; n++) {
            c[n][0] = fexp(c[n][0] - mn0); ls0 += c[n][0];
            c[n][1] = fexp(c[n][1] - mn0); ls0 += c[n][1];
            c[n][2] = fexp(c[n][2] - mn1); ls1 += c[n][2];
            c[n][3] = fexp(c[n][3] - mn1); ls1 += c[n][3];
        }
        ls0 += __shfl_xor_sync(0xffffffffu, ls0, 1);
        ls0 += __shfl_xor_sync(0xffffffffu, ls0, 2);
        ls1 += __shfl_xor_sync(0xffffffffu, ls1, 1);
        ls1 += __shfl_xor_sync(0xffffffffu, ls1, 2);
        if ((lane & 3) == 0) {
            red1[rowl * 2 + keyhalf] = ls0;
            red1[(rowl + 8) * 2 + keyhalf] = ls1;
        }
        l0 *= corr0; l1 *= corr1;
        #pragma unroll
        for (int n = 0; n < 8; n++) {
            o[n][0] *= corr0; o[n][1] *= corr0;
            o[n][2] *= corr1; o[n][3] *= corr1;
        }

        uint32_t ph[2][4], pl[2][4];
        #pragma unroll
        for (int k2 = 0; k2 < 2; k2++) {
            split_h16(c[2 * k2][0], c[2 * k2][1], ph[k2][0], pl[k2][0]);
            split_h16(c[2 * k2][2], c[2 * k2][3], ph[k2][1], pl[k2][1]);
            split_h16(c[2 * k2 + 1][0], c[2 * k2 + 1][1], ph[k2][2], pl[k2][2]);
            split_h16(c[2 * k2 + 1][2], c[2 * k2 + 1][3], ph[k2][3], pl[k2][3]);
        }

        // ---- O += P V (3-term) ----
        #pragma unroll
        for (int k2 = 0; k2 < 2; k2++) {
            #pragma unroll
            for (int p = 0; p < 4; p++) {
                int vrow = p * 16 + (lane & 7) + (((lane >> 4) & 1) << 3);
                uint32_t off = vrow * (ARS * 2) + (keyhalf * 32 + k2 * 16) * 2 +
                               (((lane >> 3) & 1) << 4);
                uint32_t rv[4], rl[4];
                ldmatrix_x4(rv, vbase + off);
                ldmatrix_x4(rl, vlbase + off);
                mma_f16(o[2 * p],     ph[k2], rv[0], rv[1]);
                mma_f16(o[2 * p],     pl[k2], rv[0], rv[1]);
                mma_f16(o[2 * p],     ph[k2], rl[0], rl[1]);
                mma_f16(o[2 * p + 1], ph[k2], rv[2], rv[3]);
                mma_f16(o[2 * p + 1], pl[k2], rv[2], rv[3]);
                mma_f16(o[2 * p + 1], ph[k2], rl[2], rl[3]);
            }
        }
        __syncthreads();
        l0 += red1[rowl * 2] + red1[rowl * 2 + 1];
        l1 += red1[(rowl + 8) * 2] + red1[(rowl + 8) * 2 + 1];

        // refill the stage we just finished (all warps past compute)
        int nk = kb + 2;
        if (nk <= qb) issueKV(nk, st); else CP_COMMIT();
    }

    // ---- merge key-halves, normalize, store ----
    __syncthreads();
    if (keyhalf == 1) {
        float* ox = oex + chunk * 1024;
        #pragma unroll
        for (int n = 0; n < 8; n++) {
            int d = n * 8 + c0;
            ox[r0 * 64 + d] = o[n][0];
            ox[r0 * 64 + d + 1] = o[n][1];
            ox[(r0 + 8) * 64 + d] = o[n][2];
            ox[(r0 + 8) * 64 + d + 1] = o[n][3];
        }
    }
    __syncthreads();
    if (keyhalf == 0) {
        const float* ox = oex + chunk * 1024;
        float inv0 = 1.0f / l0, inv1 = 1.0f / l1;
        #pragma unroll
        for (int n = 0; n < 8; n++) {
            int d = n * 8 + c0;
            float a0 = (o[n][0] + ox[r0 * 64 + d]) * inv0;
            float a1 = (o[n][1] + ox[r0 * 64 + d + 1]) * inv0;
            float a2 = (o[n][2] + ox[(r0 + 8) * 64 + d]) * inv1;
            float a3 = (o[n][3] + ox[(r0 + 8) * 64 + d + 1]) * inv1;
            *(float2*)(O + base_out + (size_t)growA * C_ + d) = make_float2(a0, a1);
            *(float2*)(O + base_out + (size_t)(growA + 8) * C_ + d) = make_float2(a2, a3);
        }
    }
}

// ======================= loss (single-pass online softmax) =============
__global__ void loss_init_kernel(float* loss) { *loss = 0.f; }

__global__ __launch_bounds__(256) void loss_kernel(
    const float* __restrict__ logits, const int* __restrict__ targets,
    float* __restrict__ loss)
{
    __shared__ float redm[8], reds[8];
    int row = blockIdx.x, tid = threadIdx.x;
    const float4* lr4 = (const float4*)(logits + (size_t)row * V_);

    float m = -1e30f, s = 0.f;
    for (int i = tid; i < V_ / 4; i += 256) {
        float4 u = lr4[i];
        float lm = fmaxf(fmaxf(u.x, u.y), fmaxf(u.z, u.w));
        if (lm > m) { s *= fexp(m - lm); m = lm; }
        s += fexp(u.x - m) + fexp(u.y - m) + fexp(u.z - m) + fexp(u.w - m);
    }
    #pragma unroll
    for (int o = 16; o; o >>= 1) {
        float mo = __shfl_xor_sync(0xffffffffu, m, o);
        float so = __shfl_xor_sync(0xffffffffu, s, o);
        float mn = fmaxf(m, mo);
        s = s * fexp(m - mn) + so * fexp(mo - mn);
        m = mn;
    }
    if ((tid & 31) == 0) { redm[tid >> 5] = m; reds[tid >> 5] = s; }
    __syncthreads();
    if (tid == 0) {
        float mm = redm[0], ss = reds[0];
        #pragma unroll
        for (int i = 1; i < 8; i++) {
            float mn = fmaxf(mm, redm[i]);
            ss = ss * fexp(mm - mn) + reds[i] * fexp(redm[i] - mn);
            mm = mn;
        }
        int tgt = targets[row];
        float lp = logits[(size_t)row * V_ + tgt] - mm - logf(ss);
        atomicAdd(loss, -lp * (1.0f / M_));
    }
}

// ======================= host =========================================
extern "C" void kernel_launch(void* const* d_in, const int* in_sizes, int n_in,
                              void* d_out, int out_size)
{
    const int*   idx     = (const int*)d_in[0];
    const int*   targets = (const int*)d_in[1];
    const float* tok     = (const float*)d_in[2];
    const float* pos     = (const float*)d_in[3];
    const float* ln1g    = (const float*)d_in[4];
    const float* ln1b    = (const float*)d_in[5];
    const float* Wq      = (const float*)d_in[6];
    const float* Wk      = (const float*)d_in[7];
    const float* Wv      = (const float*)d_in[8];
    const float* Wo      = (const float*)d_in[9];
    const float* bo      = (const float*)d_in[10];
    const float* ln2g    = (const float*)d_in[11];
    const float* ln2b    = (const float*)d_in[12];
    const float* W1      = (const float*)d_in[13];
    const float* b1      = (const float*)d_in[14];
    const float* W2      = (const float*)d_in[15];
    const float* b2      = (const float*)d_in[16];
    const float* lnfg    = (const float*)d_in[17];
    const float* lnfb    = (const float*)d_in[18];
    const float* Wlm     = (const float*)d_in[19];
    const float* blm     = (const float*)d_in[20];

    static float *x, *h, *qkv, *lgbuf;
    static __half *h16, *mlp16, *wqkv16, *wo16, *w1f, *w2f, *wlm16;
    static __half *khg, *klg, *vth, *vtl;
    static bool init = false;
    if (!init) {
        cudaGetSymbolAddress((void**)&x, g_x);
        cudaGetSymbolAddress((void**)&h, g_h);
        cudaGetSymbolAddress((void**)&qkv, g_qkv);
        cudaGetSymbolAddress((void**)&lgbuf, g_logits);
        cudaGetSymbolAddress((void**)&h16, g_h16);
        cudaGetSymbolAddress((void**)&mlp16, g_mlp16);
        cudaGetSymbolAddress((void**)&wqkv16, g_wqkv16);
        cudaGetSymbolAddress((void**)&wo16, g_wo16);
        cudaGetSymbolAddress((void**)&w1f, g_w1f);
        cudaGetSymbolAddress((void**)&w2f, g_w2f);
        cudaGetSymbolAddress((void**)&wlm16, g_wlm16);
        cudaGetSymbolAddress((void**)&khg, g_kh);
        cudaGetSymbolAddress((void**)&klg, g_kl);
        cudaGetSymbolAddress((void**)&vth, g_vth);
        cudaGetSymbolAddress((void**)&vtl, g_vtl);
        cudaFuncSetAttribute(attn_kernel, cudaFuncAttributeMaxDynamicSharedMemorySize, ATTN_SMEM);
        init = true;
    }

    const size_t NTV = (size_t)M_ * V_;
    float* logits_ptr = ((size_t)out_size >= NTV) ? (float*)d_out : lgbuf;
    float* loss_ptr = nullptr;
    if ((size_t)out_size == NTV + 1)     loss_ptr = (float*)d_out + NTV;
    else if ((size_t)out_size < NTV)     loss_ptr = (float*)d_out;

    const size_t CC = (size_t)C_ * C_;
    const size_t C3 = 3 * CC;
    const size_t C4 = 4 * CC;

    // ---- weight prep (all fp16 [N,K]) ----
    wsplit_f16_kernel<<<dim3(C_ / 32, C_ / 32, L_), 256>>>(Wq, wqkv16 + 0 * CC, C_, C_, C3);
    wsplit_f16_kernel<<<dim3(C_ / 32, C_ / 32, L_), 256>>>(Wk, wqkv16 + 1 * CC, C_, C_, C3);
    wsplit_f16_kernel<<<dim3(C_ / 32, C_ / 32, L_), 256>>>(Wv, wqkv16 + 2 * CC, C_, C_, C3);
    wsplit_f16_kernel<<<dim3(C_ / 32, C_ / 32, L_), 256>>>(Wo, wo16, C_, C_, CC);
    wsplit_f16_kernel<<<dim3(4 * C_ / 32, C_ / 32, L_), 256>>>(W1, w1f, C_, 4 * C_, C4);
    wsplit_f16_kernel<<<dim3(C_ / 32, 4 * C_ / 32, L_), 256>>>(W2, w2f, 4 * C_, C_, C4);
    wsplit_f16_kernel<<<dim3(V_ / 32, C_ / 32, 1), 256>>>(Wlm, wlm16, C_, V_, 0);

    dim3 gqkv(M_ / 128, 3 * C_ / 128);
    dim3 g1(M_ / 128, C_ / 128);
    dim3 g4(M_ / 128, 4 * C_ / 128);
    dim3 gl(M_ / 128, V_ / 128);
    dim3 gkv(T_ / 64, B_ * H_);

    embed_kernel<<<M_, 256>>>(idx, tok, pos, x);

    for (int l = 0; l < L_; l++) {
        ln_out_kernel<0><<<M_, 256>>>(x, ln1g + (size_t)l * C_, ln1b + (size_t)l * C_, h, nullptr);
        gemm_f16a2<0,0,1><<<gqkv, 256>>>(h, wqkv16 + (size_t)l * C3, nullptr, nullptr,
                                         qkv, khg, klg, 3 * C_, C_);
        vprep_kernel<<<gkv, 256>>>(qkv, vth, vtl);
        attn_kernel<<<gkv, 256, ATTN_SMEM>>>(qkv, khg, klg, vth, vtl, h);
        gemm_f16a2<1,1,0><<<g1, 256>>>(h, wo16 + (size_t)l * CC, bo + (size_t)l * C_, x,
                                       x, nullptr, nullptr, C_, C_);
        ln_out_kernel<1><<<M_, 256>>>(x, ln2g + (size_t)l * C_, ln2b + (size_t)l * C_, nullptr, h16);
        gemm_f16<1,1,0,1><<<g4, 256>>>(h16, w1f + (size_t)l * C4,
            b1 + (size_t)l * 4 * C_, nullptr, nullptr, mlp16, 4 * C_, C_);
        gemm_f16<1,0,1,0><<<g1, 256>>>(mlp16, w2f + (size_t)l * C4,
            b2 + (size_t)l * C_, x, x, nullptr, C_, 4 * C_);
    }

    ln_out_kernel<1><<<M_, 256>>>(x, lnfg, lnfb, nullptr, h16);
    gemm_f16<1,0,0,0><<<gl, 256>>>(h16, wlm16, blm, nullptr, logits_ptr, nullptr, V_, C_);

    if (loss_ptr) {
        loss_init_kernel<<<1, 1>>>(loss_ptr);
        loss_kernel<<<M_, 256>>>(logits_ptr, targets, loss_ptr);
    }
}

// round 15
// speedup vs baseline: 1.0749x; 1.0199x over previous
#include <cuda_runtime.h>
#include <cuda_fp16.h>
#include <math.h>
#include <stdint.h>

#define T_ 1024
#define C_ 1024
#define B_ 4
#define H_ 16
#define L_ 12
#define V_ 50304
#define M_ 4096   // B*T tokens

// ======================= scratch (device globals) =======================
__device__ float g_x[(size_t)M_ * C_];
__device__ float g_h[(size_t)M_ * C_];
__device__ float g_qkv[(size_t)M_ * 3 * C_];
__device__ float g_logits[(size_t)M_ * V_];
__device__ __half g_h16[(size_t)M_ * C_];
__device__ __half g_mlp16[(size_t)M_ * 4 * C_];
__device__ __half g_kh[(size_t)M_ * C_];
__device__ __half g_kl[(size_t)M_ * C_];
__device__ __half g_vth[(size_t)M_ * C_];
__device__ __half g_vtl[(size_t)M_ * C_];
__device__ __half g_wqkv16[(size_t)L_ * 3 * C_ * C_];
__device__ __half g_wo16[(size_t)L_ * C_ * C_];
__device__ __half g_w1f[(size_t)L_ * C_ * 4 * C_];
__device__ __half g_w2f[(size_t)L_ * 4 * C_ * C_];
__device__ __half g_wlm16[(size_t)V_ * C_];

// ======================= small asm helpers =======================
__device__ __forceinline__ uint32_t smem_u32(const void* p) {
    uint32_t a;
    asm("{ .reg .u64 t; cvta.to.shared.u64 t, %1; cvt.u32.u64 %0, t; }" : "=r"(a) : "l"(p));
    return a;
}
__device__ __forceinline__ void ldmatrix_x4(uint32_t* r, uint32_t addr) {
    asm volatile("ldmatrix.sync.aligned.m8n8.x4.shared.b16 {%0,%1,%2,%3}, [%4];"
        : "=r"(r[0]), "=r"(r[1]), "=r"(r[2]), "=r"(r[3]) : "r"(addr));
}
__device__ __forceinline__ void mma_f16(float* d, const uint32_t* a, uint32_t b0, uint32_t b1) {
    asm volatile(
        "mma.sync.aligned.m16n8k16.row.col.f32.f16.f16.f32 "
        "{%0,%1,%2,%3}, {%4,%5,%6,%7}, {%8,%9}, {%0,%1,%2,%3};"
        : "+f"(d[0]), "+f"(d[1]), "+f"(d[2]), "+f"(d[3])
        : "r"(a[0]), "r"(a[1]), "r"(a[2]), "r"(a[3]), "r"(b0), "r"(b1));
}
#define CP_ASYNC16(dst, src) \
    asm volatile("cp.async.cg.shared.global [%0], [%1], 16;" :: "r"(dst), "l"(src))
#define CP_COMMIT() asm volatile("cp.async.commit_group;")
#define CP_WAIT2()  asm volatile("cp.async.wait_group 2;")
#define CP_WAIT1()  asm volatile("cp.async.wait_group 1;")
#define CP_WAIT0()  asm volatile("cp.async.wait_group 0;")

__device__ __forceinline__ uint32_t pack_h16(float x, float y) {
    __half2 h = __floats2half2_rn(x, y);
    return *(uint32_t*)&h;
}
__device__ __forceinline__ void split_h16(float x, float y, uint32_t& hi, uint32_t& lo) {
    __half hx = __float2half_rn(x), hy = __float2half_rn(y);
    hi = ((uint32_t)__half_as_ushort(hy) << 16) | __half_as_ushort(hx);
    lo = pack_h16(x - __half2float(hx), y - __half2float(hy));
}

// fast exp on the FMA pipe
__device__ __forceinline__ float fexp(float x) {
    float t = fmaxf(x, -80.0f) * 1.442695041f;
    float n = floorf(t);
    float f = t - n;
    float p = 0.0013276471f;
    p = p * f + 0.0096755413f;
    p = p * f + 0.0555041086f;
    p = p * f + 0.2402264923f;
    p = p * f + 0.6931471825f;
    p = p * f + 1.0f;
    return __int_as_float(((int)n << 23) + __float_as_int(p));
}

// ======================= weight prep (fp32 [K,N] -> fp16 [N,K]) ========
__global__ __launch_bounds__(256) void wsplit_f16_kernel(
    const float* __restrict__ W, __half* __restrict__ out, int K, int N, size_t out_ls)
{
    __shared__ float t[32][33];
    const float* Wl = W + (size_t)blockIdx.z * K * N;
    __half* ol = out + (size_t)blockIdx.z * out_ls;
    int n0 = blockIdx.x * 32, k0 = blockIdx.y * 32;
    int tx = threadIdx.x & 31, ty = threadIdx.x >> 5;
    #pragma unroll
    for (int i = 0; i < 4; i++)
        t[ty + 8 * i][tx] = Wl[(size_t)(k0 + ty + 8 * i) * N + n0 + tx];
    __syncthreads();
    #pragma unroll
    for (int i = 0; i < 4; i++) {
        float v = t[tx][ty + 8 * i];
        ol[(size_t)(n0 + ty + 8 * i) * K + k0 + tx] = __float2half(v);
    }
}

// ======================= fp16 2-term GEMM (fp32 A, fp16 W) =============
#define FRS 80
#define FSTG (128 * FRS)
#define F16_SMEM (3 * FSTG)

template <int BIAS, int RESID, int KSPLIT>
__global__ __launch_bounds__(256, 2) void gemm_f16a2(
    const float* __restrict__ A, const __half* __restrict__ Bw,
    const float* __restrict__ bias, const float* __restrict__ resid,
    float* __restrict__ C, __half* __restrict__ Kh, __half* __restrict__ Kl,
    int N, int K)
{
    __shared__ char sm[F16_SMEM];
    uint32_t sb = smem_u32(sm);
    int tid = threadIdx.x;
    int lane = tid & 31, wid = tid >> 5;
    int warp_m = wid >> 1, warp_n = wid & 1;
    int m0 = blockIdx.x * 128, n0 = blockIdx.y * 128;
    const int NC = K >> 5;

    float acc[2][8][4];
    #pragma unroll
    for (int t = 0; t < 2; t++)
        #pragma unroll
        for (int n = 0; n < 8; n++)
            #pragma unroll
            for (int j = 0; j < 4; j++) acc[t][n][j] = 0.f;

    const float* Abase = A + (size_t)(m0 + warp_m * 32 + (lane >> 2)) * K + (lane & 3) * 2;

    auto issueB = [&](int c, int s) {
        int k0 = c << 5;
        #pragma unroll
        for (int j = 0; j < 2; j++) {
            int fi = tid + j * 256;
            int row = fi >> 2, c16 = (fi & 3) << 4;
            const char* g = (const char*)Bw + ((size_t)(n0 + row) * K + k0) * 2 + c16;
            CP_ASYNC16(sb + s * FSTG + row * FRS + c16, g);
        }
        CP_COMMIT();
    };

    auto compute = [&](int c, int s) {
        #pragma unroll
        for (int ks = 0; ks < 2; ks++) {
            int kbase = (c << 5) + (ks << 4);
            float2 f[2][4];
            #pragma unroll
            for (int t = 0; t < 2; t++) {
                const float* ap = Abase + (size_t)t * 16 * K + kbase;
                f[t][0] = *(const float2*)(ap);
                f[t][1] = *(const float2*)(ap + (size_t)8 * K);
                f[t][2] = *(const float2*)(ap + 8);
                f[t][3] = *(const float2*)(ap + (size_t)8 * K + 8);
            }
            uint32_t bh[8][2];
            #pragma unroll
            for (int p = 0; p < 4; p++) {
                int row = warp_n * 64 + p * 16 + (lane & 7) + (((lane >> 4) & 1) << 3);
                uint32_t off = row * FRS + ks * 32 + (((lane >> 3) & 1) << 4);
                uint32_t r[4];
                ldmatrix_x4(r, sb + s * FSTG + off);
                bh[2 * p][0] = r[0]; bh[2 * p][1] = r[1];
                bh[2 * p + 1][0] = r[2]; bh[2 * p + 1][1] = r[3];
            }
            uint32_t ah[2][4], al[2][4];
            #pragma unroll
            for (int t = 0; t < 2; t++)
                #pragma unroll
                for (int j = 0; j < 4; j++)
                    split_h16(f[t][j].x, f[t][j].y, ah[t][j], al[t][j]);
            #pragma unroll
            for (int t = 0; t < 2; t++)
                #pragma unroll
                for (int n = 0; n < 8; n++) {
                    mma_f16(acc[t][n], ah[t], bh[n][0], bh[n][1]);
                    mma_f16(acc[t][n], al[t], bh[n][0], bh[n][1]);
                }
        }
    };

    issueB(0, 0);
    issueB(1, 1);
    issueB(2, 2);

    for (int c = 0; c < NC; c++) {
        int s = c % 3;
        CP_WAIT2();
        __syncthreads();
        compute(c, s);
        __syncthreads();
        if (c + 3 < NC) issueB(c + 3, s);
    }

    bool kreg = KSPLIT && (n0 >= 1024) && (n0 < 2048);
    #pragma unroll
    for (int t = 0; t < 2; t++) {
        int row0 = m0 + warp_m * 32 + t * 16 + (lane >> 2);
        #pragma unroll
        for (int n = 0; n < 8; n++) {
            int col = n0 + warp_n * 64 + n * 8 + (lane & 3) * 2;
            float b0 = 0.f, b1 = 0.f;
            if (BIAS) { b0 = bias[col]; b1 = bias[col + 1]; }
            float v0 = acc[t][n][0] + b0, v1 = acc[t][n][1] + b1;
            float v2 = acc[t][n][2] + b0, v3 = acc[t][n][3] + b1;
            if (kreg) {
                size_t k0o = (size_t)row0 * C_ + (col - 1024);
                size_t k1o = (size_t)(row0 + 8) * C_ + (col - 1024);
                uint32_t hi, lo;
                split_h16(v0, v1, hi, lo);
                *(uint32_t*)(Kh + k0o) = hi;
                *(uint32_t*)(Kl + k0o) = lo;
                split_h16(v2, v3, hi, lo);
                *(uint32_t*)(Kh + k1o) = hi;
                *(uint32_t*)(Kl + k1o) = lo;
            } else {
                size_t o0 = (size_t)row0 * N + col;
                size_t o1 = (size_t)(row0 + 8) * N + col;
                if (RESID) {
                    float2 r0 = *(const float2*)(resid + o0);
                    float2 r1 = *(const float2*)(resid + o1);
                    v0 += r0.x; v1 += r0.y; v2 += r1.x; v3 += r1.y;
                }
                *(float2*)(C + o0) = make_float2(v0, v1);
                *(float2*)(C + o1) = make_float2(v2, v3);
            }
        }
    }
}

// ======================= fp16 single-digit GEMM ========================
template <int BIAS, int RELU, int RESID, int OUTF16>
__global__ __launch_bounds__(256, 2) void gemm_f16(
    const __half* __restrict__ A, const __half* __restrict__ Bw,
    const float* __restrict__ bias, const float* __restrict__ resid,
    float* __restrict__ C, __half* __restrict__ C16, int N, int K)
{
    __shared__ char sm[F16_SMEM];
    uint32_t sb = smem_u32(sm);
    int tid = threadIdx.x;
    int lane = tid & 31, wid = tid >> 5;
    int warp_m = wid >> 1, warp_n = wid & 1;
    int m0 = blockIdx.x * 128, n0 = blockIdx.y * 128;
    const int NC = K >> 5;

    float acc[2][8][4];
    #pragma unroll
    for (int t = 0; t < 2; t++)
        #pragma unroll
        for (int n = 0; n < 8; n++)
            #pragma unroll
            for (int j = 0; j < 4; j++) acc[t][n][j] = 0.f;

    const __half* Abase = A + (size_t)(m0 + warp_m * 32 + (lane >> 2)) * K + ((lane & 3) << 1);

    auto issueB = [&](int c, int s) {
        int k0 = c << 5;
        #pragma unroll
        for (int j = 0; j < 2; j++) {
            int fi = tid + j * 256;
            int row = fi >> 2, c16 = (fi & 3) << 4;
            const char* g = (const char*)Bw + ((size_t)(n0 + row) * K + k0) * 2 + c16;
            CP_ASYNC16(sb + s * FSTG + row * FRS + c16, g);
        }
        CP_COMMIT();
    };

    auto compute = [&](int c, int s) {
        #pragma unroll
        for (int ks = 0; ks < 2; ks++) {
            int kbase = (c << 5) + (ks << 4);
            uint32_t ah[2][4];
            #pragma unroll
            for (int t = 0; t < 2; t++) {
                size_t o = (size_t)(t * 16) * K + kbase;
                ah[t][0] = *(const uint32_t*)(Abase + o);
                ah[t][1] = *(const uint32_t*)(Abase + o + (size_t)8 * K);
                ah[t][2] = *(const uint32_t*)(Abase + o + 8);
                ah[t][3] = *(const uint32_t*)(Abase + o + (size_t)8 * K + 8);
            }
            uint32_t bh[8][2];
            #pragma unroll
            for (int p = 0; p < 4; p++) {
                int row = warp_n * 64 + p * 16 + (lane & 7) + (((lane >> 4) & 1) << 3);
                uint32_t off = row * FRS + ks * 32 + (((lane >> 3) & 1) << 4);
                uint32_t r[4];
                ldmatrix_x4(r, sb + s * FSTG + off);
                bh[2 * p][0] = r[0]; bh[2 * p][1] = r[1];
                bh[2 * p + 1][0] = r[2]; bh[2 * p + 1][1] = r[3];
            }
            #pragma unroll
            for (int t = 0; t < 2; t++)
                #pragma unroll
                for (int n = 0; n < 8; n++)
                    mma_f16(acc[t][n], ah[t], bh[n][0], bh[n][1]);
        }
    };

    issueB(0, 0);
    issueB(1, 1);
    issueB(2, 2);

    for (int c = 0; c < NC; c++) {
        int s = c % 3;
        CP_WAIT2();
        __syncthreads();
        compute(c, s);
        __syncthreads();
        if (c + 3 < NC) issueB(c + 3, s);
    }

    #pragma unroll
    for (int t = 0; t < 2; t++) {
        int row0 = m0 + warp_m * 32 + t * 16 + (lane >> 2);
        #pragma unroll
        for (int n = 0; n < 8; n++) {
            int col = n0 + warp_n * 64 + n * 8 + (lane & 3) * 2;
            float b0 = 0.f, b1 = 0.f;
            if (BIAS) { b0 = bias[col]; b1 = bias[col + 1]; }
            float v0 = acc[t][n][0] + b0, v1 = acc[t][n][1] + b1;
            float v2 = acc[t][n][2] + b0, v3 = acc[t][n][3] + b1;
            size_t o0 = (size_t)row0 * N + col;
            size_t o1 = (size_t)(row0 + 8) * N + col;
            if (RESID) {
                float2 r0 = *(const float2*)(resid + o0);
                float2 r1 = *(const float2*)(resid + o1);
                v0 += r0.x; v1 += r0.y; v2 += r1.x; v3 += r1.y;
            }
            if (RELU) {
                v0 = fmaxf(v0, 0.f); v1 = fmaxf(v1, 0.f);
                v2 = fmaxf(v2, 0.f); v3 = fmaxf(v3, 0.f);
            }
            if (OUTF16) {
                *(uint32_t*)(C16 + o0) = pack_h16(v0, v1);
                *(uint32_t*)(C16 + o1) = pack_h16(v2, v3);
            } else {
                *(float2*)(C + o0) = make_float2(v0, v1);
                *(float2*)(C + o1) = make_float2(v2, v3);
            }
        }
    }
}

// ======================= embedding ====================================
__global__ __launch_bounds__(256) void embed_kernel(
    const int* __restrict__ idx, const float* __restrict__ tok,
    const float* __restrict__ pos, float* __restrict__ x)
{
    int bt = blockIdx.x;
    int t = bt & (T_ - 1);
    int token = idx[bt];
    int c = threadIdx.x * 4;
    float4 tv = *(const float4*)(tok + (size_t)token * C_ + c);
    float4 pv = *(const float4*)(pos + (size_t)t * C_ + c);
    *(float4*)(x + (size_t)bt * C_ + c) =
        make_float4(tv.x + pv.x, tv.y + pv.y, tv.z + pv.z, tv.w + pv.w);
}

// ======================= layernorm (OUT: 0=fp32, 1=fp16) ==============
template <int OUT>
__global__ __launch_bounds__(256) void ln_out_kernel(
    const float* __restrict__ x, const float* __restrict__ g,
    const float* __restrict__ b, float* __restrict__ yf, __half* __restrict__ yh)
{
    __shared__ float red[8];
    __shared__ float bc_mean, bc_inv;
    int row = blockIdx.x, tid = threadIdx.x;
    const float* xr = x + (size_t)row * C_;
    float4 xv = *(const float4*)(xr + tid * 4);
    float s = xv.x + xv.y + xv.z + xv.w;
    #pragma unroll
    for (int o = 16; o; o >>= 1) s += __shfl_xor_sync(0xffffffffu, s, o);
    if ((tid & 31) == 0) red[tid >> 5] = s;
    __syncthreads();
    if (tid == 0) {
        float t = 0.f;
        #pragma unroll
        for (int i = 0; i < 8; i++) t += red[i];
        bc_mean = t * (1.0f / C_);
    }
    __syncthreads();
    float mean = bc_mean;
    float d0 = xv.x - mean, d1 = xv.y - mean, d2 = xv.z - mean, d3 = xv.w - mean;
    float sq = d0 * d0 + d1 * d1 + d2 * d2 + d3 * d3;
    #pragma unroll
    for (int o = 16; o; o >>= 1) sq += __shfl_xor_sync(0xffffffffu, sq, o);
    if ((tid & 31) == 0) red[tid >> 5] = sq;
    __syncthreads();
    if (tid == 0) {
        float t = 0.f;
        #pragma unroll
        for (int i = 0; i < 8; i++) t += red[i];
        bc_inv = rsqrtf(t * (1.0f / C_) + 1e-5f);
    }
    __syncthreads();
    float inv = bc_inv;
    float4 gv = *(const float4*)(g + tid * 4);
    float4 bv = *(const float4*)(b + tid * 4);
    float y0 = d0 * inv * gv.x + bv.x;
    float y1 = d1 * inv * gv.y + bv.y;
    float y2 = d2 * inv * gv.z + bv.z;
    float y3 = d3 * inv * gv.w + bv.w;
    size_t off = (size_t)row * C_ + tid * 4;
    if (OUT == 0) {
        *(float4*)(yf + off) = make_float4(y0, y1, y2, y3);
    } else {
        *(uint2*)(yh + off) = make_uint2(pack_h16(y0, y1), pack_h16(y2, y3));
    }
}

// ======================= V pre-conversion (transpose) =================
__global__ __launch_bounds__(256) void vprep_kernel(
    const float* __restrict__ qkv, __half* __restrict__ vth, __half* __restrict__ vtl)
{
    __shared__ __half sh[64][65], sl[64][65];
    int kb = blockIdx.x, bhx = blockIdx.y;
    int b = bhx >> 4, hh = bhx & 15;
    int tid = threadIdx.x;
    int r = tid >> 2, d0 = (tid & 3) << 4;
    size_t grow = (size_t)(b * T_ + kb * 64 + r);
    const float* Vrow = qkv + grow * (3 * C_) + 2 * C_ + hh * 64;
    #pragma unroll
    for (int d = d0; d < d0 + 16; d += 2) {
        float2 vv = *(const float2*)(Vrow + d);
        __half hx = __float2half_rn(vv.x), hy = __float2half_rn(vv.y);
        sh[r][d] = hx; sh[r][d + 1] = hy;
        sl[r][d] = __float2half_rn(vv.x - __half2float(hx));
        sl[r][d + 1] = __float2half_rn(vv.y - __half2float(hy));
    }
    __syncthreads();
    int dd = tid >> 2, k0 = (tid & 3) << 4;
    __half* vht = vth + ((size_t)bhx * 16 + kb) * 4096 + dd * 64;
    __half* vlt = vtl + ((size_t)bhx * 16 + kb) * 4096 + dd * 64;
    #pragma unroll
    for (int k = k0; k < k0 + 16; k += 2) {
        uint32_t hv = ((uint32_t)__half_as_ushort(sh[k + 1][dd]) << 16) | __half_as_ushort(sh[k][dd]);
        uint32_t lv = ((uint32_t)__half_as_ushort(sl[k + 1][dd]) << 16) | __half_as_ushort(sl[k][dd]);
        *(uint32_t*)(vht + k) = hv;
        *(uint32_t*)(vtl + ((size_t)bhx * 16 + kb) * 4096 + dd * 64 + k - (size_t)(vlt - (vtl + ((size_t)bhx * 16 + kb) * 4096 + dd * 64)) * 0) = lv;
    }
}

// ======================= tensor-core causal flash attention ===========
// 64 q-rows/block, keyhalf split; 2-stage cp.async KV ring (dynamic smem).
// Grid: (B*H, T/64) with qb DESCENDING (longest blocks launch first).
#define ARS 72
#define ASTG (4 * 64 * ARS * 2)             // one stage: Kh,Kl,Vh,Vl = 36864
#define ATTN_SMEM (2 * ASTG + 1024)         // 74752

__global__ __launch_bounds__(256) void attn_kernel(
    const float* __restrict__ QKV, const __half* __restrict__ khg,
    const __half* __restrict__ klg, const __half* __restrict__ vth,
    const __half* __restrict__ vtl, float* __restrict__ O)
{
    extern __shared__ __align__(16) char smb[];
    float* red0 = (float*)(smb + 2 * ASTG);
    float* red1 = red0 + 128;
    float* oex = (float*)smb;

    const int LDQ = 3 * C_;
    int bhx = blockIdx.x;
    int qb = (T_ / 64 - 1) - blockIdx.y;   // longest-first (LPT) scheduling
    int b = bhx >> 4, hh = bhx & 15;
    const float* Qp = QKV + (size_t)b * T_ * LDQ + (size_t)hh * 64;
    size_t base_out = (size_t)b * T_ * C_ + (size_t)hh * 64;

    int tid = threadIdx.x, lane = tid & 31, wid = tid >> 5;
    int chunk = wid >> 1, keyhalf = wid & 1;
    int r0 = lane >> 2, c0 = (lane & 3) << 1;
    int rowl = chunk * 16 + r0;
    int growA = qb * 64 + rowl;

    uint32_t sbase = smem_u32(smb);

    // ---- Q fragments (hi/lo fp16), pre-scaled by 1/8 (exact pow2) ----
    uint32_t qh[4][4], ql[4][4];
    #pragma unroll
    for (int s = 0; s < 4; s++)
        #pragma unroll
        for (int j = 0; j < 4; j++) {
            int grow = growA + ((j & 1) << 3);
            int gcol = s * 16 + c0 + ((j >> 1) << 3);
            float2 v = *(const float2*)(Qp + (size_t)grow * LDQ + gcol);
            split_h16(v.x * 0.125f, v.y * 0.125f, qh[s][j], ql[s][j]);
        }

    float m0 = -1e30f, m1 = -1e30f, l0 = 0.f, l1 = 0.f;
    float o[8][4];
    #pragma unroll
    for (int n = 0; n < 8; n++)
        #pragma unroll
        for (int j = 0; j < 4; j++) o[n][j] = 0.f;

    auto issueKV = [&](int kb, int st) {
        const __half* kh_t = khg + ((size_t)(b * T_ + kb * 64)) * C_ + hh * 64;
        const __half* kl_t = klg + ((size_t)(b * T_ + kb * 64)) * C_ + hh * 64;
        const __half* vh_t = vth + ((size_t)bhx * 16 + kb) * 4096;
        const __half* vl_t = vtl + ((size_t)bhx * 16 + kb) * 4096;
        uint32_t sk = sbase + st * ASTG;
        #pragma unroll
        for (int j = 0; j < 2; j++) {
            int idx = tid + j * 256;
            int row = idx >> 3, cb = (idx & 7) << 4;
            CP_ASYNC16(sk + row * 144 + cb, (const char*)(kh_t + (size_t)row * C_) + cb);
            CP_ASYNC16(sk + 64 * 144 + row * 144 + cb, (const char*)(kl_t + (size_t)row * C_) + cb);
            CP_ASYNC16(sk + 2 * 64 * 144 + row * 144 + cb, (const char*)(vh_t + row * 64) + cb);
            CP_ASYNC16(sk + 3 * 64 * 144 + row * 144 + cb, (const char*)(vl_t + row * 64) + cb);
        }
        CP_COMMIT();
    };

    issueKV(0, 0);
    if (qb >= 1) issueKV(1, 1); else CP_COMMIT();

    for (int kb = 0; kb <= qb; kb++) {
        int st = kb & 1;
        uint32_t kbase = sbase + st * ASTG;
        uint32_t klbase = kbase + 64 * ARS * 2;
        uint32_t vbase = klbase + 64 * ARS * 2;
        uint32_t vlbase = vbase + 64 * ARS * 2;

        CP_WAIT1();
        __syncthreads();

        // ---- S = Q K^T (3-term) ----
        float c[4][4];
        #pragma unroll
        for (int n = 0; n < 4; n++)
            #pragma unroll
            for (int j = 0; j < 4; j++) c[n][j] = 0.f;

        #pragma unroll
        for (int s = 0; s < 4; s++) {
            uint32_t bhf[4][2], blf[4][2];
            #pragma unroll
            for (int p = 0; p < 2; p++) {
                int krow = keyhalf * 32 + p * 16 + (lane & 7) + (((lane >> 4) & 1) << 3);
                uint32_t off = krow * (ARS * 2) + s * 32 + (((lane >> 3) & 1) << 4);
                uint32_t r[4];
                ldmatrix_x4(r, kbase + off);
                bhf[2 * p][0] = r[0]; bhf[2 * p][1] = r[1];
                bhf[2 * p + 1][0] = r[2]; bhf[2 * p + 1][1] = r[3];
                ldmatrix_x4(r, klbase + off);
                blf[2 * p][0] = r[0]; blf[2 * p][1] = r[1];
                blf[2 * p + 1][0] = r[2]; blf[2 * p + 1][1] = r[3];
            }
            #pragma unroll
            for (int n = 0; n < 4; n++) {
                mma_f16(c[n], qh[s], bhf[n][0], bhf[n][1]);
                mma_f16(c[n], ql[s], bhf[n][0], bhf[n][1]);
                mma_f16(c[n], qh[s], blf[n][0], blf[n][1]);
            }
        }

        if (kb == qb) {
            #pragma unroll
            for (int n = 0; n < 4; n++) {
                int gk = kb * 64 + keyhalf * 32 + n * 8 + c0;
                if (gk > growA)         c[n][0] = -1e30f;
                if (gk + 1 > growA)     c[n][1] = -1e30f;
                if (gk > growA + 8)     c[n][2] = -1e30f;
                if (gk + 1 > growA + 8) c[n][3] = -1e30f;
            }
        }

        // ---- online softmax (cross-warp via red0/red1) ----
        float mx0 = fmaxf(fmaxf(c[0][0], c[0][1]), fmaxf(c[1][0], c[1][1]));
        mx0 = fmaxf(mx0, fmaxf(fmaxf(c[2][0], c[2][1]), fmaxf(c[3][0], c[3][1])));
        float mx1 = fmaxf(fmaxf(c[0][2], c[0][3]), fmaxf(c[1][2], c[1][3]));
        mx1 = fmaxf(mx1, fmaxf(fmaxf(c[2][2], c[2][3]), fmaxf(c[3][2], c[3][3])));
        mx0 = fmaxf(mx0, __shfl_xor_sync(0xffffffffu, mx0, 1));
        mx0 = fmaxf(mx0, __shfl_xor_sync(0xffffffffu, mx0, 2));
        mx1 = fmaxf(mx1, __shfl_xor_sync(0xffffffffu, mx1, 1));
        mx1 = fmaxf(mx1, __shfl_xor_sync(0xffffffffu, mx1, 2));
        if ((lane & 3) == 0) {
            red0[rowl * 2 + keyhalf] = mx0;
            red0[(rowl + 8) * 2 + keyhalf] = mx1;
        }
        __syncthreads();
        float mn0 = fmaxf(m0, fmaxf(red0[rowl * 2], red0[rowl * 2 + 1]));
        float mn1 = fmaxf(m1, fmaxf(red0[(rowl + 8) * 2], red0[(rowl + 8) * 2 + 1]));
        float corr0 = fexp(m0 - mn0), corr1 = fexp(m1 - mn1);
        m0 = mn0; m1 = mn1;

        float ls0 = 0.f, ls1 = 0.f;
        #pragma unroll
        for (int n = 0; n < 4; n++) {
            c[n][0] = fexp(c[n][0] - mn0); ls0 += c[n][0];
            c[n][1] = fexp(c[n][1] - mn0); ls0 += c[n][1];
            c[n][2] = fexp(c[n][2] - mn1); ls1 += c[n][2];
            c[n][3] = fexp(c[n][3] - mn1); ls1 += c[n][3];
        }
        ls0 += __shfl_xor_sync(0xffffffffu, ls0, 1);
        ls0 += __shfl_xor_sync(0xffffffffu, ls0, 2);
        ls1 += __shfl_xor_sync(0xffffffffu, ls1, 1);
        ls1 += __shfl_xor_sync(0xffffffffu, ls1, 2);
        if ((lane & 3) == 0) {
            red1[rowl * 2 + keyhalf] = ls0;
            red1[(rowl + 8) * 2 + keyhalf] = ls1;
        }
        l0 *= corr0; l1 *= corr1;
        #pragma unroll
        for (int n = 0; n < 8; n++) {
            o[n][0] *= corr0; o[n][1] *= corr0;
            o[n][2] *= corr1; o[n][3] *= corr1;
        }

        uint32_t ph[2][4], pl[2][4];
        #pragma unroll
        for (int k2 = 0; k2 < 2; k2++) {
            split_h16(c[2 * k2][0], c[2 * k2][1], ph[k2][0], pl[k2][0]);
            split_h16(c[2 * k2][2], c[2 * k2][3], ph[k2][1], pl[k2][1]);
            split_h16(c[2 * k2 + 1][0], c[2 * k2 + 1][1], ph[k2][2], pl[k2][2]);
            split_h16(c[2 * k2 + 1][2], c[2 * k2 + 1][3], ph[k2][3], pl[k2][3]);
        }

        // ---- O += P V (3-term) ----
        #pragma unroll
        for (int k2 = 0; k2 < 2; k2++) {
            #pragma unroll
            for (int p = 0; p < 4; p++) {
                int vrow = p * 16 + (lane & 7) + (((lane >> 4) & 1) << 3);
                uint32_t off = vrow * (ARS * 2) + (keyhalf * 32 + k2 * 16) * 2 +
                               (((lane >> 3) & 1) << 4);
                uint32_t rv[4], rl[4];
                ldmatrix_x4(rv, vbase + off);
                ldmatrix_x4(rl, vlbase + off);
                mma_f16(o[2 * p],     ph[k2], rv[0], rv[1]);
                mma_f16(o[2 * p],     pl[k2], rv[0], rv[1]);
                mma_f16(o[2 * p],     ph[k2], rl[0], rl[1]);
                mma_f16(o[2 * p + 1], ph[k2], rv[2], rv[3]);
                mma_f16(o[2 * p + 1], pl[k2], rv[2], rv[3]);
                mma_f16(o[2 * p + 1], ph[k2], rl[2], rl[3]);
            }
        }
        __syncthreads();
        l0 += red1[rowl * 2] + red1[rowl * 2 + 1];
        l1 += red1[(rowl + 8) * 2] + red1[(rowl + 8) * 2 + 1];

        int nk = kb + 2;
        if (nk <= qb) issueKV(nk, st); else CP_COMMIT();
    }

    // ---- merge key-halves, normalize, store ----
    __syncthreads();
    if (keyhalf == 1) {
        float* ox = oex + chunk * 1024;
        #pragma unroll
        for (int n = 0; n < 8; n++) {
            int d = n * 8 + c0;
            ox[r0 * 64 + d] = o[n][0];
            ox[r0 * 64 + d + 1] = o[n][1];
            ox[(r0 + 8) * 64 + d] = o[n][2];
            ox[(r0 + 8) * 64 + d + 1] = o[n][3];
        }
    }
    __syncthreads();
    if (keyhalf == 0) {
        const float* ox = oex + chunk * 1024;
        float inv0 = 1.0f / l0, inv1 = 1.0f / l1;
        #pragma unroll
        for (int n = 0; n < 8; n++) {
            int d = n * 8 + c0;
            float a0 = (o[n][0] + ox[r0 * 64 + d]) * inv0;
            float a1 = (o[n][1] + ox[r0 * 64 + d + 1]) * inv0;
            float a2 = (o[n][2] + ox[(r0 + 8) * 64 + d]) * inv1;
            float a3 = (o[n][3] + ox[(r0 + 8) * 64 + d + 1]) * inv1;
            *(float2*)(O + base_out + (size_t)growA * C_ + d) = make_float2(a0, a1);
            *(float2*)(O + base_out + (size_t)(growA + 8) * C_ + d) = make_float2(a2, a3);
        }
    }
}

// ======================= loss (single-pass online softmax) =============
__global__ void loss_init_kernel(float* loss) { *loss = 0.f; }

__global__ __launch_bounds__(256) void loss_kernel(
    const float* __restrict__ logits, const int* __restrict__ targets,
    float* __restrict__ loss)
{
    __shared__ float redm[8], reds[8];
    int row = blockIdx.x, tid = threadIdx.x;
    const float4* lr4 = (const float4*)(logits + (size_t)row * V_);

    float m = -1e30f, s = 0.f;
    for (int i = tid; i < V_ / 4; i += 256) {
        float4 u = lr4[i];
        float lm = fmaxf(fmaxf(u.x, u.y), fmaxf(u.z, u.w));
        if (lm > m) { s *= fexp(m - lm); m = lm; }
        s += fexp(u.x - m) + fexp(u.y - m) + fexp(u.z - m) + fexp(u.w - m);
    }
    #pragma unroll
    for (int o = 16; o; o >>= 1) {
        float mo = __shfl_xor_sync(0xffffffffu, m, o);
        float so = __shfl_xor_sync(0xffffffffu, s, o);
        float mn = fmaxf(m, mo);
        s = s * fexp(m - mn) + so * fexp(mo - mn);
        m = mn;
    }
    if ((tid & 31) == 0) { redm[tid >> 5] = m; reds[tid >> 5] = s; }
    __syncthreads();
    if (tid == 0) {
        float mm = redm[0], ss = reds[0];
        #pragma unroll
        for (int i = 1; i < 8; i++) {
            float mn = fmaxf(mm, redm[i]);
            ss = ss * fexp(mm - mn) + reds[i] * fexp(redm[i] - mn);
            mm = mn;
        }
        int tgt = targets[row];
        float lp = logits[(size_t)row * V_ + tgt] - mm - logf(ss);
        atomicAdd(loss, -lp * (1.0f / M_));
    }
}

// ======================= host =========================================
extern "C" void kernel_launch(void* const* d_in, const int* in_sizes, int n_in,
                              void* d_out, int out_size)
{
    const int*   idx     = (const int*)d_in[0];
    const int*   targets = (const int*)d_in[1];
    const float* tok     = (const float*)d_in[2];
    const float* pos     = (const float*)d_in[3];
    const float* ln1g    = (const float*)d_in[4];
    const float* ln1b    = (const float*)d_in[5];
    const float* Wq      = (const float*)d_in[6];
    const float* Wk      = (const float*)d_in[7];
    const float* Wv      = (const float*)d_in[8];
    const float* Wo      = (const float*)d_in[9];
    const float* bo      = (const float*)d_in[10];
    const float* ln2g    = (const float*)d_in[11];
    const float* ln2b    = (const float*)d_in[12];
    const float* W1      = (const float*)d_in[13];
    const float* b1      = (const float*)d_in[14];
    const float* W2      = (const float*)d_in[15];
    const float* b2      = (const float*)d_in[16];
    const float* lnfg    = (const float*)d_in[17];
    const float* lnfb    = (const float*)d_in[18];
    const float* Wlm     = (const float*)d_in[19];
    const float* blm     = (const float*)d_in[20];

    static float *x, *h, *qkv, *lgbuf;
    static __half *h16, *mlp16, *wqkv16, *wo16, *w1f, *w2f, *wlm16;
    static __half *khg, *klg, *vth, *vtl;
    static bool init = false;
    if (!init) {
        cudaGetSymbolAddress((void**)&x, g_x);
        cudaGetSymbolAddress((void**)&h, g_h);
        cudaGetSymbolAddress((void**)&qkv, g_qkv);
        cudaGetSymbolAddress((void**)&lgbuf, g_logits);
        cudaGetSymbolAddress((void**)&h16, g_h16);
        cudaGetSymbolAddress((void**)&mlp16, g_mlp16);
        cudaGetSymbolAddress((void**)&wqkv16, g_wqkv16);
        cudaGetSymbolAddress((void**)&wo16, g_wo16);
        cudaGetSymbolAddress((void**)&w1f, g_w1f);
        cudaGetSymbolAddress((void**)&w2f, g_w2f);
        cudaGetSymbolAddress((void**)&wlm16, g_wlm16);
        cudaGetSymbolAddress((void**)&khg, g_kh);
        cudaGetSymbolAddress((void**)&klg, g_kl);
        cudaGetSymbolAddress((void**)&vth, g_vth);
        cudaGetSymbolAddress((void**)&vtl, g_vtl);
        cudaFuncSetAttribute(attn_kernel, cudaFuncAttributeMaxDynamicSharedMemorySize, ATTN_SMEM);
        init = true;
    }

    const size_t NTV = (size_t)M_ * V_;
    float* logits_ptr = ((size_t)out_size >= NTV) ? (float*)d_out : lgbuf;
    float* loss_ptr = nullptr;
    if ((size_t)out_size == NTV + 1)     loss_ptr = (float*)d_out + NTV;
    else if ((size_t)out_size < NTV)     loss_ptr = (float*)d_out;

    const size_t CC = (size_t)C_ * C_;
    const size_t C3 = 3 * CC;
    const size_t C4 = 4 * CC;

    // ---- weight prep (all fp16 [N,K]) ----
    wsplit_f16_kernel<<<dim3(C_ / 32, C_ / 32, L_), 256>>>(Wq, wqkv16 + 0 * CC, C_, C_, C3);
    wsplit_f16_kernel<<<dim3(C_ / 32, C_ / 32, L_), 256>>>(Wk, wqkv16 + 1 * CC, C_, C_, C3);
    wsplit_f16_kernel<<<dim3(C_ / 32, C_ / 32, L_), 256>>>(Wv, wqkv16 + 2 * CC, C_, C_, C3);
    wsplit_f16_kernel<<<dim3(C_ / 32, C_ / 32, L_), 256>>>(Wo, wo16, C_, C_, CC);
    wsplit_f16_kernel<<<dim3(4 * C_ / 32, C_ / 32, L_), 256>>>(W1, w1f, C_, 4 * C_, C4);
    wsplit_f16_kernel<<<dim3(C_ / 32, 4 * C_ / 32, L_), 256>>>(W2, w2f, 4 * C_, C_, C4);
    wsplit_f16_kernel<<<dim3(V_ / 32, C_ / 32, 1), 256>>>(Wlm, wlm16, C_, V_, 0);

    dim3 gqkv(M_ / 128, 3 * C_ / 128);
    dim3 g1(M_ / 128, C_ / 128);
    dim3 g4(M_ / 128, 4 * C_ / 128);
    dim3 gl(M_ / 128, V_ / 128);
    dim3 gkv(T_ / 64, B_ * H_);
    dim3 gatt(B_ * H_, T_ / 64);   // attention: bh fast, qb slow (descending in-kernel)

    embed_kernel<<<M_, 256>>>(idx, tok, pos, x);

    for (int l = 0; l < L_; l++) {
        ln_out_kernel<0><<<M_, 256>>>(x, ln1g + (size_t)l * C_, ln1b + (size_t)l * C_, h, nullptr);
        gemm_f16a2<0,0,1><<<gqkv, 256>>>(h, wqkv16 + (size_t)l * C3, nullptr, nullptr,
                                         qkv, khg, klg, 3 * C_, C_);
        vprep_kernel<<<gkv, 256>>>(qkv, vth, vtl);
        attn_kernel<<<gatt, 256, ATTN_SMEM>>>(qkv, khg, klg, vth, vtl, h);
        gemm_f16a2<1,1,0><<<g1, 256>>>(h, wo16 + (size_t)l * CC, bo + (size_t)l * C_, x,
                                       x, nullptr, nullptr, C_, C_);
        ln_out_kernel<1><<<M_, 256>>>(x, ln2g + (size_t)l * C_, ln2b + (size_t)l * C_, nullptr, h16);
        gemm_f16<1,1,0,1><<<g4, 256>>>(h16, w1f + (size_t)l * C4,
            b1 + (size_t)l * 4 * C_, nullptr, nullptr, mlp16, 4 * C_, C_);
        gemm_f16<1,0,1,0><<<g1, 256>>>(mlp16, w2f + (size_t)l * C4,
            b2 + (size_t)l * C_, x, x, nullptr, C_, 4 * C_);
    }

    ln_out_kernel<1><<<M_, 256>>>(x, lnfg, lnfb, nullptr, h16);
    gemm_f16<1,0,0,0><<<gl, 256>>>(h16, wlm16, blm, nullptr, logits_ptr, nullptr, V_, C_);

    if (loss_ptr) {
        loss_init_kernel<<<1, 1>>>(loss_ptr);
        loss_kernel<<<M_, 256>>>(logits_ptr, targets, loss_ptr);
    }
}

// round 16
// speedup vs baseline: 1.0977x; 1.0212x over previous
#include <cuda_runtime.h>
#include <cuda_fp16.h>
#include <math.h>
#include <stdint.h>

#define T_ 1024
#define C_ 1024
#define B_ 4
#define H_ 16
#define L_ 12
#define V_ 50304
#define M_ 4096   // B*T tokens

// ======================= scratch (device globals) =======================
__device__ float g_x[(size_t)M_ * C_];
__device__ float g_h[(size_t)M_ * C_];
__device__ float g_qkv[(size_t)M_ * 3 * C_];
__device__ float g_logits[(size_t)M_ * V_];
__device__ __half g_h16[(size_t)M_ * C_];
__device__ __half g_mlp16[(size_t)M_ * 4 * C_];
__device__ __half g_kh[(size_t)M_ * C_];
__device__ __half g_kl[(size_t)M_ * C_];
__device__ __half g_vth[(size_t)M_ * C_];
__device__ __half g_vtl[(size_t)M_ * C_];
__device__ __half g_wqkv16[(size_t)L_ * 3 * C_ * C_];
__device__ __half g_wo16[(size_t)L_ * C_ * C_];
__device__ __half g_w1f[(size_t)L_ * C_ * 4 * C_];
__device__ __half g_w2f[(size_t)L_ * 4 * C_ * C_];
__device__ __half g_wlm16[(size_t)V_ * C_];

// ======================= small asm helpers =======================
__device__ __forceinline__ uint32_t smem_u32(const void* p) {
    uint32_t a;
    asm("{ .reg .u64 t; cvta.to.shared.u64 t, %1; cvt.u32.u64 %0, t; }" : "=r"(a) : "l"(p));
    return a;
}
__device__ __forceinline__ void ldmatrix_x4(uint32_t* r, uint32_t addr) {
    asm volatile("ldmatrix.sync.aligned.m8n8.x4.shared.b16 {%0,%1,%2,%3}, [%4];"
        : "=r"(r[0]), "=r"(r[1]), "=r"(r[2]), "=r"(r[3]) : "r"(addr));
}
__device__ __forceinline__ void mma_f16(float* d, const uint32_t* a, uint32_t b0, uint32_t b1) {
    asm volatile(
        "mma.sync.aligned.m16n8k16.row.col.f32.f16.f16.f32 "
        "{%0,%1,%2,%3}, {%4,%5,%6,%7}, {%8,%9}, {%0,%1,%2,%3};"
        : "+f"(d[0]), "+f"(d[1]), "+f"(d[2]), "+f"(d[3])
        : "r"(a[0]), "r"(a[1]), "r"(a[2]), "r"(a[3]), "r"(b0), "r"(b1));
}
#define CP_ASYNC16(dst, src) \
    asm volatile("cp.async.cg.shared.global [%0], [%1], 16;" :: "r"(dst), "l"(src))
#define CP_COMMIT() asm volatile("cp.async.commit_group;")
#define CP_WAIT3()  asm volatile("cp.async.wait_group 3;")
#define CP_WAIT1()  asm volatile("cp.async.wait_group 1;")

__device__ __forceinline__ uint32_t pack_h16(float x, float y) {
    __half2 h = __floats2half2_rn(x, y);
    return *(uint32_t*)&h;
}
__device__ __forceinline__ void split_h16(float x, float y, uint32_t& hi, uint32_t& lo) {
    __half hx = __float2half_rn(x), hy = __float2half_rn(y);
    hi = ((uint32_t)__half_as_ushort(hy) << 16) | __half_as_ushort(hx);
    lo = pack_h16(x - __half2float(hx), y - __half2float(hy));
}

// fast exp on the FMA pipe
__device__ __forceinline__ float fexp(float x) {
    float t = fmaxf(x, -80.0f) * 1.442695041f;
    float n = floorf(t);
    float f = t - n;
    float p = 0.0013276471f;
    p = p * f + 0.0096755413f;
    p = p * f + 0.0555041086f;
    p = p * f + 0.2402264923f;
    p = p * f + 0.6931471825f;
    p = p * f + 1.0f;
    return __int_as_float(((int)n << 23) + __float_as_int(p));
}

// ======================= weight prep (fp32 [K,N] -> fp16 [N,K]) ========
// vectorized: half2 stores, fewer instructions; rounding identical to rn.
__global__ __launch_bounds__(256) void wsplit_f16_kernel(
    const float* __restrict__ W, __half* __restrict__ out, int K, int N, size_t out_ls)
{
    __shared__ float t[32][33];
    const float* Wl = W + (size_t)blockIdx.z * K * N;
    __half* ol = out + (size_t)blockIdx.z * out_ls;
    int n0 = blockIdx.x * 32, k0 = blockIdx.y * 32;
    int tx = threadIdx.x & 31, ty = threadIdx.x >> 5;
    #pragma unroll
    for (int i = 0; i < 4; i++)
        t[ty + 8 * i][tx] = Wl[(size_t)(k0 + ty + 8 * i) * N + n0 + tx];
    __syncthreads();
    int kp = threadIdx.x & 15, nn = threadIdx.x >> 4;   // 16 kpairs x 16 n, x2
    #pragma unroll
    for (int j = 0; j < 2; j++) {
        int n = nn + 16 * j;
        uint32_t v = pack_h16(t[2 * kp][n], t[2 * kp + 1][n]);
        *(uint32_t*)(ol + (size_t)(n0 + n) * K + k0 + 2 * kp) = v;
    }
}

// ======================= fp16 2-term GEMM (fp32 A, fp16 W) =============
// 4-stage cp.async ring with exact group accounting (empty commits in tail).
#define FRS 80
#define FSTG (128 * FRS)
#define F16_SMEM (4 * FSTG)

template <int BIAS, int RESID, int KSPLIT>
__global__ __launch_bounds__(256, 2) void gemm_f16a2(
    const float* __restrict__ A, const __half* __restrict__ Bw,
    const float* __restrict__ bias, const float* __restrict__ resid,
    float* __restrict__ C, __half* __restrict__ Kh, __half* __restrict__ Kl,
    int N, int K)
{
    __shared__ char sm[F16_SMEM];
    uint32_t sb = smem_u32(sm);
    int tid = threadIdx.x;
    int lane = tid & 31, wid = tid >> 5;
    int warp_m = wid >> 1, warp_n = wid & 1;
    int m0 = blockIdx.x * 128, n0 = blockIdx.y * 128;
    const int NC = K >> 5;

    float acc[2][8][4];
    #pragma unroll
    for (int t = 0; t < 2; t++)
        #pragma unroll
        for (int n = 0; n < 8; n++)
            #pragma unroll
            for (int j = 0; j < 4; j++) acc[t][n][j] = 0.f;

    const float* Abase = A + (size_t)(m0 + warp_m * 32 + (lane >> 2)) * K + (lane & 3) * 2;

    auto issueB = [&](int c, int s) {
        int k0 = c << 5;
        #pragma unroll
        for (int j = 0; j < 2; j++) {
            int fi = tid + j * 256;
            int row = fi >> 2, c16 = (fi & 3) << 4;
            const char* g = (const char*)Bw + ((size_t)(n0 + row) * K + k0) * 2 + c16;
            CP_ASYNC16(sb + s * FSTG + row * FRS + c16, g);
        }
        CP_COMMIT();
    };

    auto compute = [&](int c, int s) {
        #pragma unroll
        for (int ks = 0; ks < 2; ks++) {
            int kbase = (c << 5) + (ks << 4);
            float2 f[2][4];
            #pragma unroll
            for (int t = 0; t < 2; t++) {
                const float* ap = Abase + (size_t)t * 16 * K + kbase;
                f[t][0] = *(const float2*)(ap);
                f[t][1] = *(const float2*)(ap + (size_t)8 * K);
                f[t][2] = *(const float2*)(ap + 8);
                f[t][3] = *(const float2*)(ap + (size_t)8 * K + 8);
            }
            uint32_t bh[8][2];
            #pragma unroll
            for (int p = 0; p < 4; p++) {
                int row = warp_n * 64 + p * 16 + (lane & 7) + (((lane >> 4) & 1) << 3);
                uint32_t off = row * FRS + ks * 32 + (((lane >> 3) & 1) << 4);
                uint32_t r[4];
                ldmatrix_x4(r, sb + s * FSTG + off);
                bh[2 * p][0] = r[0]; bh[2 * p][1] = r[1];
                bh[2 * p + 1][0] = r[2]; bh[2 * p + 1][1] = r[3];
            }
            uint32_t ah[2][4], al[2][4];
            #pragma unroll
            for (int t = 0; t < 2; t++)
                #pragma unroll
                for (int j = 0; j < 4; j++)
                    split_h16(f[t][j].x, f[t][j].y, ah[t][j], al[t][j]);
            #pragma unroll
            for (int t = 0; t < 2; t++)
                #pragma unroll
                for (int n = 0; n < 8; n++) {
                    mma_f16(acc[t][n], ah[t], bh[n][0], bh[n][1]);
                    mma_f16(acc[t][n], al[t], bh[n][0], bh[n][1]);
                }
        }
    };

    issueB(0, 0);
    issueB(1, 1);
    issueB(2, 2);
    issueB(3, 3);

    for (int c = 0; c < NC; c++) {
        int s = c & 3;
        CP_WAIT3();
        __syncthreads();
        compute(c, s);
        __syncthreads();
        if (c + 4 < NC) issueB(c + 4, s); else CP_COMMIT();
    }

    bool kreg = KSPLIT && (n0 >= 1024) && (n0 < 2048);
    #pragma unroll
    for (int t = 0; t < 2; t++) {
        int row0 = m0 + warp_m * 32 + t * 16 + (lane >> 2);
        #pragma unroll
        for (int n = 0; n < 8; n++) {
            int col = n0 + warp_n * 64 + n * 8 + (lane & 3) * 2;
            float b0 = 0.f, b1 = 0.f;
            if (BIAS) { b0 = bias[col]; b1 = bias[col + 1]; }
            float v0 = acc[t][n][0] + b0, v1 = acc[t][n][1] + b1;
            float v2 = acc[t][n][2] + b0, v3 = acc[t][n][3] + b1;
            if (kreg) {
                size_t k0o = (size_t)row0 * C_ + (col - 1024);
                size_t k1o = (size_t)(row0 + 8) * C_ + (col - 1024);
                uint32_t hi, lo;
                split_h16(v0, v1, hi, lo);
                *(uint32_t*)(Kh + k0o) = hi;
                *(uint32_t*)(Kl + k0o) = lo;
                split_h16(v2, v3, hi, lo);
                *(uint32_t*)(Kh + k1o) = hi;
                *(uint32_t*)(Kl + k1o) = lo;
            } else {
                size_t o0 = (size_t)row0 * N + col;
                size_t o1 = (size_t)(row0 + 8) * N + col;
                if (RESID) {
                    float2 r0 = *(const float2*)(resid + o0);
                    float2 r1 = *(const float2*)(resid + o1);
                    v0 += r0.x; v1 += r0.y; v2 += r1.x; v3 += r1.y;
                }
                *(float2*)(C + o0) = make_float2(v0, v1);
                *(float2*)(C + o1) = make_float2(v2, v3);
            }
        }
    }
}

// ======================= fp16 single-digit GEMM ========================
template <int BIAS, int RELU, int RESID, int OUTF16>
__global__ __launch_bounds__(256, 2) void gemm_f16(
    const __half* __restrict__ A, const __half* __restrict__ Bw,
    const float* __restrict__ bias, const float* __restrict__ resid,
    float* __restrict__ C, __half* __restrict__ C16, int N, int K)
{
    __shared__ char sm[F16_SMEM];
    uint32_t sb = smem_u32(sm);
    int tid = threadIdx.x;
    int lane = tid & 31, wid = tid >> 5;
    int warp_m = wid >> 1, warp_n = wid & 1;
    int m0 = blockIdx.x * 128, n0 = blockIdx.y * 128;
    const int NC = K >> 5;

    float acc[2][8][4];
    #pragma unroll
    for (int t = 0; t < 2; t++)
        #pragma unroll
        for (int n = 0; n < 8; n++)
            #pragma unroll
            for (int j = 0; j < 4; j++) acc[t][n][j] = 0.f;

    const __half* Abase = A + (size_t)(m0 + warp_m * 32 + (lane >> 2)) * K + ((lane & 3) << 1);

    auto issueB = [&](int c, int s) {
        int k0 = c << 5;
        #pragma unroll
        for (int j = 0; j < 2; j++) {
            int fi = tid + j * 256;
            int row = fi >> 2, c16 = (fi & 3) << 4;
            const char* g = (const char*)Bw + ((size_t)(n0 + row) * K + k0) * 2 + c16;
            CP_ASYNC16(sb + s * FSTG + row * FRS + c16, g);
        }
        CP_COMMIT();
    };

    auto compute = [&](int c, int s) {
        #pragma unroll
        for (int ks = 0; ks < 2; ks++) {
            int kbase = (c << 5) + (ks << 4);
            uint32_t ah[2][4];
            #pragma unroll
            for (int t = 0; t < 2; t++) {
                size_t o = (size_t)(t * 16) * K + kbase;
                ah[t][0] = *(const uint32_t*)(Abase + o);
                ah[t][1] = *(const uint32_t*)(Abase + o + (size_t)8 * K);
                ah[t][2] = *(const uint32_t*)(Abase + o + 8);
                ah[t][3] = *(const uint32_t*)(Abase + o + (size_t)8 * K + 8);
            }
            uint32_t bh[8][2];
            #pragma unroll
            for (int p = 0; p < 4; p++) {
                int row = warp_n * 64 + p * 16 + (lane & 7) + (((lane >> 4) & 1) << 3);
                uint32_t off = row * FRS + ks * 32 + (((lane >> 3) & 1) << 4);
                uint32_t r[4];
                ldmatrix_x4(r, sb + s * FSTG + off);
                bh[2 * p][0] = r[0]; bh[2 * p][1] = r[1];
                bh[2 * p + 1][0] = r[2]; bh[2 * p + 1][1] = r[3];
            }
            #pragma unroll
            for (int t = 0; t < 2; t++)
                #pragma unroll
                for (int n = 0; n < 8; n++)
                    mma_f16(acc[t][n], ah[t], bh[n][0], bh[n][1]);
        }
    };

    issueB(0, 0);
    issueB(1, 1);
    issueB(2, 2);
    issueB(3, 3);

    for (int c = 0; c < NC; c++) {
        int s = c & 3;
        CP_WAIT3();
        __syncthreads();
        compute(c, s);
        __syncthreads();
        if (c + 4 < NC) issueB(c + 4, s); else CP_COMMIT();
    }

    #pragma unroll
    for (int t = 0; t < 2; t++) {
        int row0 = m0 + warp_m * 32 + t * 16 + (lane >> 2);
        #pragma unroll
        for (int n = 0; n < 8; n++) {
            int col = n0 + warp_n * 64 + n * 8 + (lane & 3) * 2;
            float b0 = 0.f, b1 = 0.f;
            if (BIAS) { b0 = bias[col]; b1 = bias[col + 1]; }
            float v0 = acc[t][n][0] + b0, v1 = acc[t][n][1] + b1;
            float v2 = acc[t][n][2] + b0, v3 = acc[t][n][3] + b1;
            size_t o0 = (size_t)row0 * N + col;
            size_t o1 = (size_t)(row0 + 8) * N + col;
            if (RESID) {
                float2 r0 = *(const float2*)(resid + o0);
                float2 r1 = *(const float2*)(resid + o1);
                v0 += r0.x; v1 += r0.y; v2 += r1.x; v3 += r1.y;
            }
            if (RELU) {
                v0 = fmaxf(v0, 0.f); v1 = fmaxf(v1, 0.f);
                v2 = fmaxf(v2, 0.f); v3 = fmaxf(v3, 0.f);
            }
            if (OUTF16) {
                *(uint32_t*)(C16 + o0) = pack_h16(v0, v1);
                *(uint32_t*)(C16 + o1) = pack_h16(v2, v3);
            } else {
                *(float2*)(C + o0) = make_float2(v0, v1);
                *(float2*)(C + o1) = make_float2(v2, v3);
            }
        }
    }
}

// ======================= embedding ====================================
__global__ __launch_bounds__(256) void embed_kernel(
    const int* __restrict__ idx, const float* __restrict__ tok,
    const float* __restrict__ pos, float* __restrict__ x)
{
    int bt = blockIdx.x;
    int t = bt & (T_ - 1);
    int token = idx[bt];
    int c = threadIdx.x * 4;
    float4 tv = *(const float4*)(tok + (size_t)token * C_ + c);
    float4 pv = *(const float4*)(pos + (size_t)t * C_ + c);
    *(float4*)(x + (size_t)bt * C_ + c) =
        make_float4(tv.x + pv.x, tv.y + pv.y, tv.z + pv.z, tv.w + pv.w);
}

// ======================= layernorm (OUT: 0=fp32, 1=fp16) ==============
template <int OUT>
__global__ __launch_bounds__(256) void ln_out_kernel(
    const float* __restrict__ x, const float* __restrict__ g,
    const float* __restrict__ b, float* __restrict__ yf, __half* __restrict__ yh)
{
    __shared__ float red[8];
    __shared__ float bc_mean, bc_inv;
    int row = blockIdx.x, tid = threadIdx.x;
    const float* xr = x + (size_t)row * C_;
    float4 xv = *(const float4*)(xr + tid * 4);
    float s = xv.x + xv.y + xv.z + xv.w;
    #pragma unroll
    for (int o = 16; o; o >>= 1) s += __shfl_xor_sync(0xffffffffu, s, o);
    if ((tid & 31) == 0) red[tid >> 5] = s;
    __syncthreads();
    if (tid == 0) {
        float t = 0.f;
        #pragma unroll
        for (int i = 0; i < 8; i++) t += red[i];
        bc_mean = t * (1.0f / C_);
    }
    __syncthreads();
    float mean = bc_mean;
    float d0 = xv.x - mean, d1 = xv.y - mean, d2 = xv.z - mean, d3 = xv.w - mean;
    float sq = d0 * d0 + d1 * d1 + d2 * d2 + d3 * d3;
    #pragma unroll
    for (int o = 16; o; o >>= 1) sq += __shfl_xor_sync(0xffffffffu, sq, o);
    if ((tid & 31) == 0) red[tid >> 5] = sq;
    __syncthreads();
    if (tid == 0) {
        float t = 0.f;
        #pragma unroll
        for (int i = 0; i < 8; i++) t += red[i];
        bc_inv = rsqrtf(t * (1.0f / C_) + 1e-5f);
    }
    __syncthreads();
    float inv = bc_inv;
    float4 gv = *(const float4*)(g + tid * 4);
    float4 bv = *(const float4*)(b + tid * 4);
    float y0 = d0 * inv * gv.x + bv.x;
    float y1 = d1 * inv * gv.y + bv.y;
    float y2 = d2 * inv * gv.z + bv.z;
    float y3 = d3 * inv * gv.w + bv.w;
    size_t off = (size_t)row * C_ + tid * 4;
    if (OUT == 0) {
        *(float4*)(yf + off) = make_float4(y0, y1, y2, y3);
    } else {
        *(uint2*)(yh + off) = make_uint2(pack_h16(y0, y1), pack_h16(y2, y3));
    }
}

// ======================= V pre-conversion (transpose) =================
__global__ __launch_bounds__(256) void vprep_kernel(
    const float* __restrict__ qkv, __half* __restrict__ vth, __half* __restrict__ vtl)
{
    __shared__ __half sh[64][65], sl[64][65];
    int kb = blockIdx.x, bhx = blockIdx.y;
    int b = bhx >> 4, hh = bhx & 15;
    int tid = threadIdx.x;
    int r = tid >> 2, d0 = (tid & 3) << 4;
    size_t grow = (size_t)(b * T_ + kb * 64 + r);
    const float* Vrow = qkv + grow * (3 * C_) + 2 * C_ + hh * 64;
    #pragma unroll
    for (int d = d0; d < d0 + 16; d += 2) {
        float2 vv = *(const float2*)(Vrow + d);
        __half hx = __float2half_rn(vv.x), hy = __float2half_rn(vv.y);
        sh[r][d] = hx; sh[r][d + 1] = hy;
        sl[r][d] = __float2half_rn(vv.x - __half2float(hx));
        sl[r][d + 1] = __float2half_rn(vv.y - __half2float(hy));
    }
    __syncthreads();
    int dd = tid >> 2, k0 = (tid & 3) << 4;
    __half* vht = vth + ((size_t)bhx * 16 + kb) * 4096 + dd * 64;
    __half* vlt = vtl + ((size_t)bhx * 16 + kb) * 4096 + dd * 64;
    #pragma unroll
    for (int k = k0; k < k0 + 16; k += 2) {
        uint32_t hv = ((uint32_t)__half_as_ushort(sh[k + 1][dd]) << 16) | __half_as_ushort(sh[k][dd]);
        uint32_t lv = ((uint32_t)__half_as_ushort(sl[k + 1][dd]) << 16) | __half_as_ushort(sl[k][dd]);
        *(uint32_t*)(vht + k) = hv;
        *(uint32_t*)(vlt + k) = lv;
    }
}

// ======================= tensor-core causal flash attention ===========
// 64 q-rows/block, keyhalf split; 2-stage cp.async KV ring (dynamic smem).
// Grid: (B*H, T/64) with qb DESCENDING (LPT); 2 blocks/SM enforced.
#define ARS 72
#define ASTG (4 * 64 * ARS * 2)             // one stage: Kh,Kl,Vh,Vl = 36864
#define ATTN_SMEM (2 * ASTG + 1024)         // 74752

__global__ __launch_bounds__(256, 2) void attn_kernel(
    const float* __restrict__ QKV, const __half* __restrict__ khg,
    const __half* __restrict__ klg, const __half* __restrict__ vth,
    const __half* __restrict__ vtl, float* __restrict__ O)
{
    extern __shared__ __align__(16) char smb[];
    float* red0 = (float*)(smb + 2 * ASTG);
    float* red1 = red0 + 128;
    float* oex = (float*)smb;

    const int LDQ = 3 * C_;
    int bhx = blockIdx.x;
    int qb = (T_ / 64 - 1) - blockIdx.y;   // longest-first (LPT) scheduling
    int b = bhx >> 4, hh = bhx & 15;
    const float* Qp = QKV + (size_t)b * T_ * LDQ + (size_t)hh * 64;
    size_t base_out = (size_t)b * T_ * C_ + (size_t)hh * 64;

    int tid = threadIdx.x, lane = tid & 31, wid = tid >> 5;
    int chunk = wid >> 1, keyhalf = wid & 1;
    int r0 = lane >> 2, c0 = (lane & 3) << 1;
    int rowl = chunk * 16 + r0;
    int growA = qb * 64 + rowl;

    uint32_t sbase = smem_u32(smb);

    uint32_t qh[4][4], ql[4][4];
    #pragma unroll
    for (int s = 0; s < 4; s++)
        #pragma unroll
        for (int j = 0; j < 4; j++) {
            int grow = growA + ((j & 1) << 3);
            int gcol = s * 16 + c0 + ((j >> 1) << 3);
            float2 v = *(const float2*)(Qp + (size_t)grow * LDQ + gcol);
            split_h16(v.x * 0.125f, v.y * 0.125f, qh[s][j], ql[s][j]);
        }

    float m0 = -1e30f, m1 = -1e30f, l0 = 0.f, l1 = 0.f;
    float o[8][4];
    #pragma unroll
    for (int n = 0; n < 8; n++)
        #pragma unroll
        for (int j = 0; j < 4; j++) o[n][j] = 0.f;

    auto issueKV = [&](int kb, int st) {
        const __half* kh_t = khg + ((size_t)(b * T_ + kb * 64)) * C_ + hh * 64;
        const __half* kl_t = klg + ((size_t)(b * T_ + kb * 64)) * C_ + hh * 64;
        const __half* vh_t = vth + ((size_t)bhx * 16 + kb) * 4096;
        const __half* vl_t = vtl + ((size_t)bhx * 16 + kb) * 4096;
        uint32_t sk = sbase + st * ASTG;
        #pragma unroll
        for (int j = 0; j < 2; j++) {
            int idx = tid + j * 256;
            int row = idx >> 3, cb = (idx & 7) << 4;
            CP_ASYNC16(sk + row * 144 + cb, (const char*)(kh_t + (size_t)row * C_) + cb);
            CP_ASYNC16(sk + 64 * 144 + row * 144 + cb, (const char*)(kl_t + (size_t)row * C_) + cb);
            CP_ASYNC16(sk + 2 * 64 * 144 + row * 144 + cb, (const char*)(vh_t + row * 64) + cb);
            CP_ASYNC16(sk + 3 * 64 * 144 + row * 144 + cb, (const char*)(vl_t + row * 64) + cb);
        }
        CP_COMMIT();
    };

    issueKV(0, 0);
    if (qb >= 1) issueKV(1, 1); else CP_COMMIT();

    for (int kb = 0; kb <= qb; kb++) {
        int st = kb & 1;
        uint32_t kbase = sbase + st * ASTG;
        uint32_t klbase = kbase + 64 * ARS * 2;
        uint32_t vbase = klbase + 64 * ARS * 2;
        uint32_t vlbase = vbase + 64 * ARS * 2;

        CP_WAIT1();
        __syncthreads();

        float c[4][4];
        #pragma unroll
        for (int n = 0; n < 4; n++)
            #pragma unroll
            for (int j = 0; j < 4; j++) c[n][j] = 0.f;

        #pragma unroll
        for (int s = 0; s < 4; s++) {
            uint32_t bhf[4][2], blf[4][2];
            #pragma unroll
            for (int p = 0; p < 2; p++) {
                int krow = keyhalf * 32 + p * 16 + (lane & 7) + (((lane >> 4) & 1) << 3);
                uint32_t off = krow * (ARS * 2) + s * 32 + (((lane >> 3) & 1) << 4);
                uint32_t r[4];
                ldmatrix_x4(r, kbase + off);
                bhf[2 * p][0] = r[0]; bhf[2 * p][1] = r[1];
                bhf[2 * p + 1][0] = r[2]; bhf[2 * p + 1][1] = r[3];
                ldmatrix_x4(r, klbase + off);
                blf[2 * p][0] = r[0]; blf[2 * p][1] = r[1];
                blf[2 * p + 1][0] = r[2]; blf[2 * p + 1][1] = r[3];
            }
            #pragma unroll
            for (int n = 0; n < 4; n++) {
                mma_f16(c[n], qh[s], bhf[n][0], bhf[n][1]);
                mma_f16(c[n], ql[s], bhf[n][0], bhf[n][1]);
                mma_f16(c[n], qh[s], blf[n][0], blf[n][1]);
            }
        }

        if (kb == qb) {
            #pragma unroll
            for (int n = 0; n < 4; n++) {
                int gk = kb * 64 + keyhalf * 32 + n * 8 + c0;
                if (gk > growA)         c[n][0] = -1e30f;
                if (gk + 1 > growA)     c[n][1] = -1e30f;
                if (gk > growA + 8)     c[n][2] = -1e30f;
                if (gk + 1 > growA + 8) c[n][3] = -1e30f;
            }
        }

        float mx0 = fmaxf(fmaxf(c[0][0], c[0][1]), fmaxf(c[1][0], c[1][1]));
        mx0 = fmaxf(mx0, fmaxf(fmaxf(c[2][0], c[2][1]), fmaxf(c[3][0], c[3][1])));
        float mx1 = fmaxf(fmaxf(c[0][2], c[0][3]), fmaxf(c[1][2], c[1][3]));
        mx1 = fmaxf(mx1, fmaxf(fmaxf(c[2][2], c[2][3]), fmaxf(c[3][2], c[3][3])));
        mx0 = fmaxf(mx0, __shfl_xor_sync(0xffffffffu, mx0, 1));
        mx0 = fmaxf(mx0, __shfl_xor_sync(0xffffffffu, mx0, 2));
        mx1 = fmaxf(mx1, __shfl_xor_sync(0xffffffffu, mx1, 1));
        mx1 = fmaxf(mx1, __shfl_xor_sync(0xffffffffu, mx1, 2));
        if ((lane & 3) == 0) {
            red0[rowl * 2 + keyhalf] = mx0;
            red0[(rowl + 8) * 2 + keyhalf] = mx1;
        }
        __syncthreads();
        float mn0 = fmaxf(m0, fmaxf(red0[rowl * 2], red0[rowl * 2 + 1]));
        float mn1 = fmaxf(m1, fmaxf(red0[(rowl + 8) * 2], red0[(rowl + 8) * 2 + 1]));
        float corr0 = fexp(m0 - mn0), corr1 = fexp(m1 - mn1);
        m0 = mn0; m1 = mn1;

        float ls0 = 0.f, ls1 = 0.f;
        #pragma unroll
        for (int n = 0; n < 4; n++) {
            c[n][0] = fexp(c[n][0] - mn0); ls0 += c[n][0];
            c[n][1] = fexp(c[n][1] - mn0); ls0 += c[n][1];
            c[n][2] = fexp(c[n][2] - mn1); ls1 += c[n][2];
            c[n][3] = fexp(c[n][3] - mn1); ls1 += c[n][3];
        }
        ls0 += __shfl_xor_sync(0xffffffffu, ls0, 1);
        ls0 += __shfl_xor_sync(0xffffffffu, ls0, 2);
        ls1 += __shfl_xor_sync(0xffffffffu, ls1, 1);
        ls1 += __shfl_xor_sync(0xffffffffu, ls1, 2);
        if ((lane & 3) == 0) {
            red1[rowl * 2 + keyhalf] = ls0;
            red1[(rowl + 8) * 2 + keyhalf] = ls1;
        }
        l0 *= corr0; l1 *= corr1;
        #pragma unroll
        for (int n = 0; n < 8; n++) {
            o[n][0] *= corr0; o[n][1] *= corr0;
            o[n][2] *= corr1; o[n][3] *= corr1;
        }

        uint32_t ph[2][4], pl[2][4];
        #pragma unroll
        for (int k2 = 0; k2 < 2; k2++) {
            split_h16(c[2 * k2][0], c[2 * k2][1], ph[k2][0], pl[k2][0]);
            split_h16(c[2 * k2][2], c[2 * k2][3], ph[k2][1], pl[k2][1]);
            split_h16(c[2 * k2 + 1][0], c[2 * k2 + 1][1], ph[k2][2], pl[k2][2]);
            split_h16(c[2 * k2 + 1][2], c[2 * k2 + 1][3], ph[k2][3], pl[k2][3]);
        }

        #pragma unroll
        for (int k2 = 0; k2 < 2; k2++) {
            #pragma unroll
            for (int p = 0; p < 4; p++) {
                int vrow = p * 16 + (lane & 7) + (((lane >> 4) & 1) << 3);
                uint32_t off = vrow * (ARS * 2) + (keyhalf * 32 + k2 * 16) * 2 +
                               (((lane >> 3) & 1) << 4);
                uint32_t rv[4], rl[4];
                ldmatrix_x4(rv, vbase + off);
                ldmatrix_x4(rl, vlbase + off);
                mma_f16(o[2 * p],     ph[k2], rv[0], rv[1]);
                mma_f16(o[2 * p],     pl[k2], rv[0], rv[1]);
                mma_f16(o[2 * p],     ph[k2], rl[0], rl[1]);
                mma_f16(o[2 * p + 1], ph[k2], rv[2], rv[3]);
                mma_f16(o[2 * p + 1], pl[k2], rv[2], rv[3]);
                mma_f16(o[2 * p + 1], ph[k2], rl[2], rl[3]);
            }
        }
        __syncthreads();
        l0 += red1[rowl * 2] + red1[rowl * 2 + 1];
        l1 += red1[(rowl + 8) * 2] + red1[(rowl + 8) * 2 + 1];

        int nk = kb + 2;
        if (nk <= qb) issueKV(nk, st); else CP_COMMIT();
    }

    __syncthreads();
    if (keyhalf == 1) {
        float* ox = oex + chunk * 1024;
        #pragma unroll
        for (int n = 0; n < 8; n++) {
            int d = n * 8 + c0;
            ox[r0 * 64 + d] = o[n][0];
            ox[r0 * 64 + d + 1] = o[n][1];
            ox[(r0 + 8) * 64 + d] = o[n][2];
            ox[(r0 + 8) * 64 + d + 1] = o[n][3];
        }
    }
    __syncthreads();
    if (keyhalf == 0) {
        const float* ox = oex + chunk * 1024;
        float inv0 = 1.0f / l0, inv1 = 1.0f / l1;
        #pragma unroll
        for (int n = 0; n < 8; n++) {
            int d = n * 8 + c0;
            float a0 = (o[n][0] + ox[r0 * 64 + d]) * inv0;
            float a1 = (o[n][1] + ox[r0 * 64 + d + 1]) * inv0;
            float a2 = (o[n][2] + ox[(r0 + 8) * 64 + d]) * inv1;
            float a3 = (o[n][3] + ox[(r0 + 8) * 64 + d + 1]) * inv1;
            *(float2*)(O + base_out + (size_t)growA * C_ + d) = make_float2(a0, a1);
            *(float2*)(O + base_out + (size_t)(growA + 8) * C_ + d) = make_float2(a2, a3);
        }
    }
}

// ======================= loss (single-pass online softmax) =============
__global__ void loss_init_kernel(float* loss) { *loss = 0.f; }

__global__ __launch_bounds__(256) void loss_kernel(
    const float* __restrict__ logits, const int* __restrict__ targets,
    float* __restrict__ loss)
{
    __shared__ float redm[8], reds[8];
    int row = blockIdx.x, tid = threadIdx.x;
    const float4* lr4 = (const float4*)(logits + (size_t)row * V_);

    float m = -1e30f, s = 0.f;
    for (int i = tid; i < V_ / 4; i += 256) {
        float4 u = lr4[i];
        float lm = fmaxf(fmaxf(u.x, u.y), fmaxf(u.z, u.w));
        if (lm > m) { s *= fexp(m - lm); m = lm; }
        s += fexp(u.x - m) + fexp(u.y - m) + fexp(u.z - m) + fexp(u.w - m);
    }
    #pragma unroll
    for (int o = 16; o; o >>= 1) {
        float mo = __shfl_xor_sync(0xffffffffu, m, o);
        float so = __shfl_xor_sync(0xffffffffu, s, o);
        float mn = fmaxf(m, mo);
        s = s * fexp(m - mn) + so * fexp(mo - mn);
        m = mn;
    }
    if ((tid & 31) == 0) { redm[tid >> 5] = m; reds[tid >> 5] = s; }
    __syncthreads();
    if (tid == 0) {
        float mm = redm[0], ss = reds[0];
        #pragma unroll
        for (int i = 1; i < 8; i++) {
            float mn = fmaxf(mm, redm[i]);
            ss = ss * fexp(mm - mn) + reds[i] * fexp(redm[i] - mn);
            mm = mn;
        }
        int tgt = targets[row];
        float lp = logits[(size_t)row * V_ + tgt] - mm - logf(ss);
        atomicAdd(loss, -lp * (1.0f / M_));
    }
}

// ======================= host =========================================
extern "C" void kernel_launch(void* const* d_in, const int* in_sizes, int n_in,
                              void* d_out, int out_size)
{
    const int*   idx     = (const int*)d_in[0];
    const int*   targets = (const int*)d_in[1];
    const float* tok     = (const float*)d_in[2];
    const float* pos     = (const float*)d_in[3];
    const float* ln1g    = (const float*)d_in[4];
    const float* ln1b    = (const float*)d_in[5];
    const float* Wq      = (const float*)d_in[6];
    const float* Wk      = (const float*)d_in[7];
    const float* Wv      = (const float*)d_in[8];
    const float* Wo      = (const float*)d_in[9];
    const float* bo      = (const float*)d_in[10];
    const float* ln2g    = (const float*)d_in[11];
    const float* ln2b    = (const float*)d_in[12];
    const float* W1      = (const float*)d_in[13];
    const float* b1      = (const float*)d_in[14];
    const float* W2      = (const float*)d_in[15];
    const float* b2      = (const float*)d_in[16];
    const float* lnfg    = (const float*)d_in[17];
    const float* lnfb    = (const float*)d_in[18];
    const float* Wlm     = (const float*)d_in[19];
    const float* blm     = (const float*)d_in[20];

    static float *x, *h, *qkv, *lgbuf;
    static __half *h16, *mlp16, *wqkv16, *wo16, *w1f, *w2f, *wlm16;
    static __half *khg, *klg, *vth, *vtl;
    static bool init = false;
    if (!init) {
        cudaGetSymbolAddress((void**)&x, g_x);
        cudaGetSymbolAddress((void**)&h, g_h);
        cudaGetSymbolAddress((void**)&qkv, g_qkv);
        cudaGetSymbolAddress((void**)&lgbuf, g_logits);
        cudaGetSymbolAddress((void**)&h16, g_h16);
        cudaGetSymbolAddress((void**)&mlp16, g_mlp16);
        cudaGetSymbolAddress((void**)&wqkv16, g_wqkv16);
        cudaGetSymbolAddress((void**)&wo16, g_wo16);
        cudaGetSymbolAddress((void**)&w1f, g_w1f);
        cudaGetSymbolAddress((void**)&w2f, g_w2f);
        cudaGetSymbolAddress((void**)&wlm16, g_wlm16);
        cudaGetSymbolAddress((void**)&khg, g_kh);
        cudaGetSymbolAddress((void**)&klg, g_kl);
        cudaGetSymbolAddress((void**)&vth, g_vth);
        cudaGetSymbolAddress((void**)&vtl, g_vtl);
        cudaFuncSetAttribute(attn_kernel, cudaFuncAttributeMaxDynamicSharedMemorySize, ATTN_SMEM);
        init = true;
    }

    const size_t NTV = (size_t)M_ * V_;
    float* logits_ptr = ((size_t)out_size >= NTV) ? (float*)d_out : lgbuf;
    float* loss_ptr = nullptr;
    if ((size_t)out_size == NTV + 1)     loss_ptr = (float*)d_out + NTV;
    else if ((size_t)out_size < NTV)     loss_ptr = (float*)d_out;

    const size_t CC = (size_t)C_ * C_;
    const size_t C3 = 3 * CC;
    const size_t C4 = 4 * CC;

    // ---- weight prep (all fp16 [N,K]) ----
    wsplit_f16_kernel<<<dim3(C_ / 32, C_ / 32, L_), 256>>>(Wq, wqkv16 + 0 * CC, C_, C_, C3);
    wsplit_f16_kernel<<<dim3(C_ / 32, C_ / 32, L_), 256>>>(Wk, wqkv16 + 1 * CC, C_, C_, C3);
    wsplit_f16_kernel<<<dim3(C_ / 32, C_ / 32, L_), 256>>>(Wv, wqkv16 + 2 * CC, C_, C_, C3);
    wsplit_f16_kernel<<<dim3(C_ / 32, C_ / 32, L_), 256>>>(Wo, wo16, C_, C_, CC);
    wsplit_f16_kernel<<<dim3(4 * C_ / 32, C_ / 32, L_), 256>>>(W1, w1f, C_, 4 * C_, C4);
    wsplit_f16_kernel<<<dim3(C_ / 32, 4 * C_ / 32, L_), 256>>>(W2, w2f, 4 * C_, C_, C4);
    wsplit_f16_kernel<<<dim3(V_ / 32, C_ / 32, 1), 256>>>(Wlm, wlm16, C_, V_, 0);

    dim3 gqkv(M_ / 128, 3 * C_ / 128);
    dim3 g1(M_ / 128, C_ / 128);
    dim3 g4(M_ / 128, 4 * C_ / 128);
    dim3 gl(M_ / 128, V_ / 128);
    dim3 gkv(T_ / 64, B_ * H_);
    dim3 gatt(B_ * H_, T_ / 64);   // bh fast, qb slow (descending in-kernel)

    embed_kernel<<<M_, 256>>>(idx, tok, pos, x);

    for (int l = 0; l < L_; l++) {
        ln_out_kernel<0><<<M_, 256>>>(x, ln1g + (size_t)l * C_, ln1b + (size_t)l * C_, h, nullptr);
        gemm_f16a2<0,0,1><<<gqkv, 256>>>(h, wqkv16 + (size_t)l * C3, nullptr, nullptr,
                                         qkv, khg, klg, 3 * C_, C_);
        vprep_kernel<<<gkv, 256>>>(qkv, vth, vtl);
        attn_kernel<<<gatt, 256, ATTN_SMEM>>>(qkv, khg, klg, vth, vtl, h);
        gemm_f16a2<1,1,0><<<g1, 256>>>(h, wo16 + (size_t)l * CC, bo + (size_t)l * C_, x,
                                       x, nullptr, nullptr, C_, C_);
        ln_out_kernel<1><<<M_, 256>>>(x, ln2g + (size_t)l * C_, ln2b + (size_t)l * C_, nullptr, h16);
        gemm_f16<1,1,0,1><<<g4, 256>>>(h16, w1f + (size_t)l * C4,
            b1 + (size_t)l * 4 * C_, nullptr, nullptr, mlp16, 4 * C_, C_);
        gemm_f16<1,0,1,0><<<g1, 256>>>(mlp16, w2f + (size_t)l * C4,
            b2 + (size_t)l * C_, x, x, nullptr, C_, 4 * C_);
    }

    ln_out_kernel<1><<<M_, 256>>>(x, lnfg, lnfb, nullptr, h16);
    gemm_f16<1,0,0,0><<<gl, 256>>>(h16, wlm16, blm, nullptr, logits_ptr, nullptr, V_, C_);

    if (loss_ptr) {
        loss_init_kernel<<<1, 1>>>(loss_ptr);
        loss_kernel<<<M_, 256>>>(logits_ptr, targets, loss_ptr);
    }
}

// round 17
// speedup vs baseline: 1.1034x; 1.0053x over previous
#include <cuda_runtime.h>
#include <cuda_fp16.h>
#include <math.h>
#include <stdint.h>

#define T_ 1024
#define C_ 1024
#define B_ 4
#define H_ 16
#define L_ 12
#define V_ 50304
#define M_ 4096   // B*T tokens
#define NPART 786 // loss partials per row: 2 warps x 393 col tiles

// ======================= scratch (device globals) =======================
__device__ float g_x[(size_t)M_ * C_];
__device__ float g_h[(size_t)M_ * C_];
__device__ float g_qkv[(size_t)M_ * 3 * C_];
__device__ float g_logits[(size_t)M_ * V_];
__device__ float g_lm[(size_t)M_ * NPART];
__device__ float g_ls[(size_t)M_ * NPART];
__device__ __half g_h16[(size_t)M_ * C_];
__device__ __half g_mlp16[(size_t)M_ * 4 * C_];
__device__ __half g_kh[(size_t)M_ * C_];
__device__ __half g_kl[(size_t)M_ * C_];
__device__ __half g_vth[(size_t)M_ * C_];
__device__ __half g_vtl[(size_t)M_ * C_];
__device__ __half g_wqkv16[(size_t)L_ * 3 * C_ * C_];
__device__ __half g_wo16[(size_t)L_ * C_ * C_];
__device__ __half g_w1f[(size_t)L_ * C_ * 4 * C_];
__device__ __half g_w2f[(size_t)L_ * 4 * C_ * C_];
__device__ __half g_wlm16[(size_t)V_ * C_];

// ======================= small asm helpers =======================
__device__ __forceinline__ uint32_t smem_u32(const void* p) {
    uint32_t a;
    asm("{ .reg .u64 t; cvta.to.shared.u64 t, %1; cvt.u32.u64 %0, t; }" : "=r"(a) : "l"(p));
    return a;
}
__device__ __forceinline__ void ldmatrix_x4(uint32_t* r, uint32_t addr) {
    asm volatile("ldmatrix.sync.aligned.m8n8.x4.shared.b16 {%0,%1,%2,%3}, [%4];"
        : "=r"(r[0]), "=r"(r[1]), "=r"(r[2]), "=r"(r[3]) : "r"(addr));
}
__device__ __forceinline__ void mma_f16(float* d, const uint32_t* a, uint32_t b0, uint32_t b1) {
    asm volatile(
        "mma.sync.aligned.m16n8k16.row.col.f32.f16.f16.f32 "
        "{%0,%1,%2,%3}, {%4,%5,%6,%7}, {%8,%9}, {%0,%1,%2,%3};"
        : "+f"(d[0]), "+f"(d[1]), "+f"(d[2]), "+f"(d[3])
        : "r"(a[0]), "r"(a[1]), "r"(a[2]), "r"(a[3]), "r"(b0), "r"(b1));
}
#define CP_ASYNC16(dst, src) \
    asm volatile("cp.async.cg.shared.global [%0], [%1], 16;" :: "r"(dst), "l"(src))
#define CP_COMMIT() asm volatile("cp.async.commit_group;")
#define CP_WAIT3()  asm volatile("cp.async.wait_group 3;")
#define CP_WAIT1()  asm volatile("cp.async.wait_group 1;")

__device__ __forceinline__ uint32_t pack_h16(float x, float y) {
    __half2 h = __floats2half2_rn(x, y);
    return *(uint32_t*)&h;
}
__device__ __forceinline__ void split_h16(float x, float y, uint32_t& hi, uint32_t& lo) {
    __half hx = __float2half_rn(x), hy = __float2half_rn(y);
    hi = ((uint32_t)__half_as_ushort(hy) << 16) | __half_as_ushort(hx);
    lo = pack_h16(x - __half2float(hx), y - __half2float(hy));
}

// fast exp on the FMA pipe
__device__ __forceinline__ float fexp(float x) {
    float t = fmaxf(x, -80.0f) * 1.442695041f;
    float n = floorf(t);
    float f = t - n;
    float p = 0.0013276471f;
    p = p * f + 0.0096755413f;
    p = p * f + 0.0555041086f;
    p = p * f + 0.2402264923f;
    p = p * f + 0.6931471825f;
    p = p * f + 1.0f;
    return __int_as_float(((int)n << 23) + __float_as_int(p));
}

// ======================= weight prep (fp32 [K,N] -> fp16 [N,K]) ========
__global__ __launch_bounds__(256) void wsplit_f16_kernel(
    const float* __restrict__ W, __half* __restrict__ out, int K, int N, size_t out_ls)
{
    __shared__ float t[32][33];
    const float* Wl = W + (size_t)blockIdx.z * K * N;
    __half* ol = out + (size_t)blockIdx.z * out_ls;
    int n0 = blockIdx.x * 32, k0 = blockIdx.y * 32;
    int tx = threadIdx.x & 31, ty = threadIdx.x >> 5;
    #pragma unroll
    for (int i = 0; i < 4; i++)
        t[ty + 8 * i][tx] = Wl[(size_t)(k0 + ty + 8 * i) * N + n0 + tx];
    __syncthreads();
    int kp = threadIdx.x & 15, nn = threadIdx.x >> 4;
    #pragma unroll
    for (int j = 0; j < 2; j++) {
        int n = nn + 16 * j;
        uint32_t v = pack_h16(t[2 * kp][n], t[2 * kp + 1][n]);
        *(uint32_t*)(ol + (size_t)(n0 + n) * K + k0 + 2 * kp) = v;
    }
}

// ======================= fp16 2-term GEMM (fp32 A, fp16 W) =============
#define FRS 80
#define FSTG (128 * FRS)
#define F16_SMEM (4 * FSTG)

template <int BIAS, int RESID, int KSPLIT>
__global__ __launch_bounds__(256, 2) void gemm_f16a2(
    const float* __restrict__ A, const __half* __restrict__ Bw,
    const float* __restrict__ bias, const float* __restrict__ resid,
    float* __restrict__ C, __half* __restrict__ Kh, __half* __restrict__ Kl,
    int N, int K)
{
    __shared__ char sm[F16_SMEM];
    uint32_t sb = smem_u32(sm);
    int tid = threadIdx.x;
    int lane = tid & 31, wid = tid >> 5;
    int warp_m = wid >> 1, warp_n = wid & 1;
    int m0 = blockIdx.x * 128, n0 = blockIdx.y * 128;
    const int NC = K >> 5;

    float acc[2][8][4];
    #pragma unroll
    for (int t = 0; t < 2; t++)
        #pragma unroll
        for (int n = 0; n < 8; n++)
            #pragma unroll
            for (int j = 0; j < 4; j++) acc[t][n][j] = 0.f;

    const float* Abase = A + (size_t)(m0 + warp_m * 32 + (lane >> 2)) * K + (lane & 3) * 2;

    auto issueB = [&](int c, int s) {
        int k0 = c << 5;
        #pragma unroll
        for (int j = 0; j < 2; j++) {
            int fi = tid + j * 256;
            int row = fi >> 2, c16 = (fi & 3) << 4;
            const char* g = (const char*)Bw + ((size_t)(n0 + row) * K + k0) * 2 + c16;
            CP_ASYNC16(sb + s * FSTG + row * FRS + c16, g);
        }
        CP_COMMIT();
    };

    auto compute = [&](int c, int s) {
        #pragma unroll
        for (int ks = 0; ks < 2; ks++) {
            int kbase = (c << 5) + (ks << 4);
            float2 f[2][4];
            #pragma unroll
            for (int t = 0; t < 2; t++) {
                const float* ap = Abase + (size_t)t * 16 * K + kbase;
                f[t][0] = *(const float2*)(ap);
                f[t][1] = *(const float2*)(ap + (size_t)8 * K);
                f[t][2] = *(const float2*)(ap + 8);
                f[t][3] = *(const float2*)(ap + (size_t)8 * K + 8);
            }
            uint32_t bh[8][2];
            #pragma unroll
            for (int p = 0; p < 4; p++) {
                int row = warp_n * 64 + p * 16 + (lane & 7) + (((lane >> 4) & 1) << 3);
                uint32_t off = row * FRS + ks * 32 + (((lane >> 3) & 1) << 4);
                uint32_t r[4];
                ldmatrix_x4(r, sb + s * FSTG + off);
                bh[2 * p][0] = r[0]; bh[2 * p][1] = r[1];
                bh[2 * p + 1][0] = r[2]; bh[2 * p + 1][1] = r[3];
            }
            uint32_t ah[2][4], al[2][4];
            #pragma unroll
            for (int t = 0; t < 2; t++)
                #pragma unroll
                for (int j = 0; j < 4; j++)
                    split_h16(f[t][j].x, f[t][j].y, ah[t][j], al[t][j]);
            #pragma unroll
            for (int t = 0; t < 2; t++)
                #pragma unroll
                for (int n = 0; n < 8; n++) {
                    mma_f16(acc[t][n], ah[t], bh[n][0], bh[n][1]);
                    mma_f16(acc[t][n], al[t], bh[n][0], bh[n][1]);
                }
        }
    };

    issueB(0, 0);
    issueB(1, 1);
    issueB(2, 2);
    issueB(3, 3);

    for (int c = 0; c < NC; c++) {
        int s = c & 3;
        CP_WAIT3();
        __syncthreads();
        compute(c, s);
        __syncthreads();
        if (c + 4 < NC) issueB(c + 4, s); else CP_COMMIT();
    }

    bool kreg = KSPLIT && (n0 >= 1024) && (n0 < 2048);
    #pragma unroll
    for (int t = 0; t < 2; t++) {
        int row0 = m0 + warp_m * 32 + t * 16 + (lane >> 2);
        #pragma unroll
        for (int n = 0; n < 8; n++) {
            int col = n0 + warp_n * 64 + n * 8 + (lane & 3) * 2;
            float b0 = 0.f, b1 = 0.f;
            if (BIAS) { b0 = bias[col]; b1 = bias[col + 1]; }
            float v0 = acc[t][n][0] + b0, v1 = acc[t][n][1] + b1;
            float v2 = acc[t][n][2] + b0, v3 = acc[t][n][3] + b1;
            if (kreg) {
                size_t k0o = (size_t)row0 * C_ + (col - 1024);
                size_t k1o = (size_t)(row0 + 8) * C_ + (col - 1024);
                uint32_t hi, lo;
                split_h16(v0, v1, hi, lo);
                *(uint32_t*)(Kh + k0o) = hi;
                *(uint32_t*)(Kl + k0o) = lo;
                split_h16(v2, v3, hi, lo);
                *(uint32_t*)(Kh + k1o) = hi;
                *(uint32_t*)(Kl + k1o) = lo;
            } else {
                size_t o0 = (size_t)row0 * N + col;
                size_t o1 = (size_t)(row0 + 8) * N + col;
                if (RESID) {
                    float2 r0 = *(const float2*)(resid + o0);
                    float2 r1 = *(const float2*)(resid + o1);
                    v0 += r0.x; v1 += r0.y; v2 += r1.x; v3 += r1.y;
                }
                *(float2*)(C + o0) = make_float2(v0, v1);
                *(float2*)(C + o1) = make_float2(v2, v3);
            }
        }
    }
}

// ======================= fp16 single-digit GEMM (opt. loss partials) ===
template <int BIAS, int RELU, int RESID, int OUTF16, int LOSS>
__global__ __launch_bounds__(256, 2) void gemm_f16(
    const __half* __restrict__ A, const __half* __restrict__ Bw,
    const float* __restrict__ bias, const float* __restrict__ resid,
    float* __restrict__ C, __half* __restrict__ C16,
    float* __restrict__ lmp, float* __restrict__ lsp, int N, int K)
{
    __shared__ char sm[F16_SMEM];
    uint32_t sb = smem_u32(sm);
    int tid = threadIdx.x;
    int lane = tid & 31, wid = tid >> 5;
    int warp_m = wid >> 1, warp_n = wid & 1;
    int m0 = blockIdx.x * 128, n0 = blockIdx.y * 128;
    const int NC = K >> 5;

    float acc[2][8][4];
    #pragma unroll
    for (int t = 0; t < 2; t++)
        #pragma unroll
        for (int n = 0; n < 8; n++)
            #pragma unroll
            for (int j = 0; j < 4; j++) acc[t][n][j] = 0.f;

    const __half* Abase = A + (size_t)(m0 + warp_m * 32 + (lane >> 2)) * K + ((lane & 3) << 1);

    auto issueB = [&](int c, int s) {
        int k0 = c << 5;
        #pragma unroll
        for (int j = 0; j < 2; j++) {
            int fi = tid + j * 256;
            int row = fi >> 2, c16 = (fi & 3) << 4;
            const char* g = (const char*)Bw + ((size_t)(n0 + row) * K + k0) * 2 + c16;
            CP_ASYNC16(sb + s * FSTG + row * FRS + c16, g);
        }
        CP_COMMIT();
    };

    auto compute = [&](int c, int s) {
        #pragma unroll
        for (int ks = 0; ks < 2; ks++) {
            int kbase = (c << 5) + (ks << 4);
            uint32_t ah[2][4];
            #pragma unroll
            for (int t = 0; t < 2; t++) {
                size_t o = (size_t)(t * 16) * K + kbase;
                ah[t][0] = *(const uint32_t*)(Abase + o);
                ah[t][1] = *(const uint32_t*)(Abase + o + (size_t)8 * K);
                ah[t][2] = *(const uint32_t*)(Abase + o + 8);
                ah[t][3] = *(const uint32_t*)(Abase + o + (size_t)8 * K + 8);
            }
            uint32_t bh[8][2];
            #pragma unroll
            for (int p = 0; p < 4; p++) {
                int row = warp_n * 64 + p * 16 + (lane & 7) + (((lane >> 4) & 1) << 3);
                uint32_t off = row * FRS + ks * 32 + (((lane >> 3) & 1) << 4);
                uint32_t r[4];
                ldmatrix_x4(r, sb + s * FSTG + off);
                bh[2 * p][0] = r[0]; bh[2 * p][1] = r[1];
                bh[2 * p + 1][0] = r[2]; bh[2 * p + 1][1] = r[3];
            }
            #pragma unroll
            for (int t = 0; t < 2; t++)
                #pragma unroll
                for (int n = 0; n < 8; n++)
                    mma_f16(acc[t][n], ah[t], bh[n][0], bh[n][1]);
        }
    };

    issueB(0, 0);
    issueB(1, 1);
    issueB(2, 2);
    issueB(3, 3);

    for (int c = 0; c < NC; c++) {
        int s = c & 3;
        CP_WAIT3();
        __syncthreads();
        compute(c, s);
        __syncthreads();
        if (c + 4 < NC) issueB(c + 4, s); else CP_COMMIT();
    }

    #pragma unroll
    for (int t = 0; t < 2; t++) {
        int row0 = m0 + warp_m * 32 + t * 16 + (lane >> 2);
        #pragma unroll
        for (int n = 0; n < 8; n++) {
            int col = n0 + warp_n * 64 + n * 8 + (lane & 3) * 2;
            float b0 = 0.f, b1 = 0.f;
            if (BIAS) { b0 = bias[col]; b1 = bias[col + 1]; }
            float v0 = acc[t][n][0] + b0, v1 = acc[t][n][1] + b1;
            float v2 = acc[t][n][2] + b0, v3 = acc[t][n][3] + b1;
            size_t o0 = (size_t)row0 * N + col;
            size_t o1 = (size_t)(row0 + 8) * N + col;
            if (RESID) {
                float2 r0 = *(const float2*)(resid + o0);
                float2 r1 = *(const float2*)(resid + o1);
                v0 += r0.x; v1 += r0.y; v2 += r1.x; v3 += r1.y;
            }
            if (RELU) {
                v0 = fmaxf(v0, 0.f); v1 = fmaxf(v1, 0.f);
                v2 = fmaxf(v2, 0.f); v3 = fmaxf(v3, 0.f);
            }
            if (OUTF16) {
                *(uint32_t*)(C16 + o0) = pack_h16(v0, v1);
                *(uint32_t*)(C16 + o1) = pack_h16(v2, v3);
            } else {
                *(float2*)(C + o0) = make_float2(v0, v1);
                *(float2*)(C + o1) = make_float2(v2, v3);
            }
            if (LOSS) {
                acc[t][n][0] = v0; acc[t][n][1] = v1;
                acc[t][n][2] = v2; acc[t][n][3] = v3;
            }
        }
        if (LOSS) {
            // per-row (max, sumexp) over this warp's 64-col slice
            float mA = -1e30f, mB = -1e30f;
            #pragma unroll
            for (int n = 0; n < 8; n++) {
                mA = fmaxf(mA, fmaxf(acc[t][n][0], acc[t][n][1]));
                mB = fmaxf(mB, fmaxf(acc[t][n][2], acc[t][n][3]));
            }
            mA = fmaxf(mA, __shfl_xor_sync(0xffffffffu, mA, 1));
            mA = fmaxf(mA, __shfl_xor_sync(0xffffffffu, mA, 2));
            mB = fmaxf(mB, __shfl_xor_sync(0xffffffffu, mB, 1));
            mB = fmaxf(mB, __shfl_xor_sync(0xffffffffu, mB, 2));
            float sA = 0.f, sB = 0.f;
            #pragma unroll
            for (int n = 0; n < 8; n++) {
                sA += fexp(acc[t][n][0] - mA) + fexp(acc[t][n][1] - mA);
                sB += fexp(acc[t][n][2] - mB) + fexp(acc[t][n][3] - mB);
            }
            sA += __shfl_xor_sync(0xffffffffu, sA, 1);
            sA += __shfl_xor_sync(0xffffffffu, sA, 2);
            sB += __shfl_xor_sync(0xffffffffu, sB, 1);
            sB += __shfl_xor_sync(0xffffffffu, sB, 2);
            if ((lane & 3) == 0) {
                int np = (N >> 7) * 2;
                size_t pa = (size_t)row0 * np + blockIdx.y * 2 + warp_n;
                size_t pb = (size_t)(row0 + 8) * np + blockIdx.y * 2 + warp_n;
                lmp[pa] = mA; lsp[pa] = sA;
                lmp[pb] = mB; lsp[pb] = sB;
            }
        }
    }
}

// ======================= embedding ====================================
__global__ __launch_bounds__(256) void embed_kernel(
    const int* __restrict__ idx, const float* __restrict__ tok,
    const float* __restrict__ pos, float* __restrict__ x)
{
    int bt = blockIdx.x;
    int t = bt & (T_ - 1);
    int token = idx[bt];
    int c = threadIdx.x * 4;
    float4 tv = *(const float4*)(tok + (size_t)token * C_ + c);
    float4 pv = *(const float4*)(pos + (size_t)t * C_ + c);
    *(float4*)(x + (size_t)bt * C_ + c) =
        make_float4(tv.x + pv.x, tv.y + pv.y, tv.z + pv.z, tv.w + pv.w);
}

// ======================= layernorm (OUT: 0=fp32, 1=fp16) ==============
template <int OUT>
__global__ __launch_bounds__(256) void ln_out_kernel(
    const float* __restrict__ x, const float* __restrict__ g,
    const float* __restrict__ b, float* __restrict__ yf, __half* __restrict__ yh)
{
    __shared__ float red[8];
    __shared__ float bc_mean, bc_inv;
    int row = blockIdx.x, tid = threadIdx.x;
    const float* xr = x + (size_t)row * C_;
    float4 xv = *(const float4*)(xr + tid * 4);
    float s = xv.x + xv.y + xv.z + xv.w;
    #pragma unroll
    for (int o = 16; o; o >>= 1) s += __shfl_xor_sync(0xffffffffu, s, o);
    if ((tid & 31) == 0) red[tid >> 5] = s;
    __syncthreads();
    if (tid == 0) {
        float t = 0.f;
        #pragma unroll
        for (int i = 0; i < 8; i++) t += red[i];
        bc_mean = t * (1.0f / C_);
    }
    __syncthreads();
    float mean = bc_mean;
    float d0 = xv.x - mean, d1 = xv.y - mean, d2 = xv.z - mean, d3 = xv.w - mean;
    float sq = d0 * d0 + d1 * d1 + d2 * d2 + d3 * d3;
    #pragma unroll
    for (int o = 16; o; o >>= 1) sq += __shfl_xor_sync(0xffffffffu, sq, o);
    if ((tid & 31) == 0) red[tid >> 5] = sq;
    __syncthreads();
    if (tid == 0) {
        float t = 0.f;
        #pragma unroll
        for (int i = 0; i < 8; i++) t += red[i];
        bc_inv = rsqrtf(t * (1.0f / C_) + 1e-5f);
    }
    __syncthreads();
    float inv = bc_inv;
    float4 gv = *(const float4*)(g + tid * 4);
    float4 bv = *(const float4*)(b + tid * 4);
    float y0 = d0 * inv * gv.x + bv.x;
    float y1 = d1 * inv * gv.y + bv.y;
    float y2 = d2 * inv * gv.z + bv.z;
    float y3 = d3 * inv * gv.w + bv.w;
    size_t off = (size_t)row * C_ + tid * 4;
    if (OUT == 0) {
        *(float4*)(yf + off) = make_float4(y0, y1, y2, y3);
    } else {
        *(uint2*)(yh + off) = make_uint2(pack_h16(y0, y1), pack_h16(y2, y3));
    }
}

// ======================= V pre-conversion (transpose) =================
__global__ __launch_bounds__(256) void vprep_kernel(
    const float* __restrict__ qkv, __half* __restrict__ vth, __half* __restrict__ vtl)
{
    __shared__ __half sh[64][65], sl[64][65];
    int kb = blockIdx.x, bhx = blockIdx.y;
    int b = bhx >> 4, hh = bhx & 15;
    int tid = threadIdx.x;
    int r = tid >> 2, d0 = (tid & 3) << 4;
    size_t grow = (size_t)(b * T_ + kb * 64 + r);
    const float* Vrow = qkv + grow * (3 * C_) + 2 * C_ + hh * 64;
    #pragma unroll
    for (int d = d0; d < d0 + 16; d += 2) {
        float2 vv = *(const float2*)(Vrow + d);
        __half hx = __float2half_rn(vv.x), hy = __float2half_rn(vv.y);
        sh[r][d] = hx; sh[r][d + 1] = hy;
        sl[r][d] = __float2half_rn(vv.x - __half2float(hx));
        sl[r][d + 1] = __float2half_rn(vv.y - __half2float(hy));
    }
    __syncthreads();
    int dd = tid >> 2, k0 = (tid & 3) << 4;
    __half* vht = vth + ((size_t)bhx * 16 + kb) * 4096 + dd * 64;
    __half* vlt = vtl + ((size_t)bhx * 16 + kb) * 4096 + dd * 64;
    #pragma unroll
    for (int k = k0; k < k0 + 16; k += 2) {
        uint32_t hv = ((uint32_t)__half_as_ushort(sh[k + 1][dd]) << 16) | __half_as_ushort(sh[k][dd]);
        uint32_t lv = ((uint32_t)__half_as_ushort(sl[k + 1][dd]) << 16) | __half_as_ushort(sl[k][dd]);
        *(uint32_t*)(vht + k) = hv;
        *(uint32_t*)(vlt + k) = lv;
    }
}

// ======================= tensor-core causal flash attention ===========
#define ARS 72
#define ASTG (4 * 64 * ARS * 2)
#define ATTN_SMEM (2 * ASTG + 1024)

__global__ __launch_bounds__(256, 2) void attn_kernel(
    const float* __restrict__ QKV, const __half* __restrict__ khg,
    const __half* __restrict__ klg, const __half* __restrict__ vth,
    const __half* __restrict__ vtl, float* __restrict__ O)
{
    extern __shared__ __align__(16) char smb[];
    float* red0 = (float*)(smb + 2 * ASTG);
    float* red1 = red0 + 128;
    float* oex = (float*)smb;

    const int LDQ = 3 * C_;
    int bhx = blockIdx.x;
    int qb = (T_ / 64 - 1) - blockIdx.y;
    int b = bhx >> 4, hh = bhx & 15;
    const float* Qp = QKV + (size_t)b * T_ * LDQ + (size_t)hh * 64;
    size_t base_out = (size_t)b * T_ * C_ + (size_t)hh * 64;

    int tid = threadIdx.x, lane = tid & 31, wid = tid >> 5;
    int chunk = wid >> 1, keyhalf = wid & 1;
    int r0 = lane >> 2, c0 = (lane & 3) << 1;
    int rowl = chunk * 16 + r0;
    int growA = qb * 64 + rowl;

    uint32_t sbase = smem_u32(smb);

    uint32_t qh[4][4], ql[4][4];
    #pragma unroll
    for (int s = 0; s < 4; s++)
        #pragma unroll
        for (int j = 0; j < 4; j++) {
            int grow = growA + ((j & 1) << 3);
            int gcol = s * 16 + c0 + ((j >> 1) << 3);
            float2 v = *(const float2*)(Qp + (size_t)grow * LDQ + gcol);
            split_h16(v.x * 0.125f, v.y * 0.125f, qh[s][j], ql[s][j]);
        }

    float m0 = -1e30f, m1 = -1e30f, l0 = 0.f, l1 = 0.f;
    float o[8][4];
    #pragma unroll
    for (int n = 0; n < 8; n++)
        #pragma unroll
        for (int j = 0; j < 4; j++) o[n][j] = 0.f;

    auto issueKV = [&](int kb, int st) {
        const __half* kh_t = khg + ((size_t)(b * T_ + kb * 64)) * C_ + hh * 64;
        const __half* kl_t = klg + ((size_t)(b * T_ + kb * 64)) * C_ + hh * 64;
        const __half* vh_t = vth + ((size_t)bhx * 16 + kb) * 4096;
        const __half* vl_t = vtl + ((size_t)bhx * 16 + kb) * 4096;
        uint32_t sk = sbase + st * ASTG;
        #pragma unroll
        for (int j = 0; j < 2; j++) {
            int idx = tid + j * 256;
            int row = idx >> 3, cb = (idx & 7) << 4;
            CP_ASYNC16(sk + row * 144 + cb, (const char*)(kh_t + (size_t)row * C_) + cb);
            CP_ASYNC16(sk + 64 * 144 + row * 144 + cb, (const char*)(kl_t + (size_t)row * C_) + cb);
            CP_ASYNC16(sk + 2 * 64 * 144 + row * 144 + cb, (const char*)(vh_t + row * 64) + cb);
            CP_ASYNC16(sk + 3 * 64 * 144 + row * 144 + cb, (const char*)(vl_t + row * 64) + cb);
        }
        CP_COMMIT();
    };

    issueKV(0, 0);
    if (qb >= 1) issueKV(1, 1); else CP_COMMIT();

    for (int kb = 0; kb <= qb; kb++) {
        int st = kb & 1;
        uint32_t kbase = sbase + st * ASTG;
        uint32_t klbase = kbase + 64 * ARS * 2;
        uint32_t vbase = klbase + 64 * ARS * 2;
        uint32_t vlbase = vbase + 64 * ARS * 2;

        CP_WAIT1();
        __syncthreads();

        float c[4][4];
        #pragma unroll
        for (int n = 0; n < 4; n++)
            #pragma unroll
            for (int j = 0; j < 4; j++) c[n][j] = 0.f;

        #pragma unroll
        for (int s = 0; s < 4; s++) {
            uint32_t bhf[4][2], blf[4][2];
            #pragma unroll
            for (int p = 0; p < 2; p++) {
                int krow = keyhalf * 32 + p * 16 + (lane & 7) + (((lane >> 4) & 1) << 3);
                uint32_t off = krow * (ARS * 2) + s * 32 + (((lane >> 3) & 1) << 4);
                uint32_t r[4];
                ldmatrix_x4(r, kbase + off);
                bhf[2 * p][0] = r[0]; bhf[2 * p][1] = r[1];
                bhf[2 * p + 1][0] = r[2]; bhf[2 * p + 1][1] = r[3];
                ldmatrix_x4(r, klbase + off);
                blf[2 * p][0] = r[0]; blf[2 * p][1] = r[1];
                blf[2 * p + 1][0] = r[2]; blf[2 * p + 1][1] = r[3];
            }
            #pragma unroll
            for (int n = 0; n < 4; n++) {
                mma_f16(c[n], qh[s], bhf[n][0], bhf[n][1]);
                mma_f16(c[n], ql[s], bhf[n][0], bhf[n][1]);
                mma_f16(c[n], qh[s], blf[n][0], blf[n][1]);
            }
        }

        if (kb == qb) {
            #pragma unroll
            for (int n = 0; n < 4; n++) {
                int gk = kb * 64 + keyhalf * 32 + n * 8 + c0;
                if (gk > growA)         c[n][0] = -1e30f;
                if (gk + 1 > growA)     c[n][1] = -1e30f;
                if (gk > growA + 8)     c[n][2] = -1e30f;
                if (gk + 1 > growA + 8) c[n][3] = -1e30f;
            }
        }

        float mx0 = fmaxf(fmaxf(c[0][0], c[0][1]), fmaxf(c[1][0], c[1][1]));
        mx0 = fmaxf(mx0, fmaxf(fmaxf(c[2][0], c[2][1]), fmaxf(c[3][0], c[3][1])));
        float mx1 = fmaxf(fmaxf(c[0][2], c[0][3]), fmaxf(c[1][2], c[1][3]));
        mx1 = fmaxf(mx1, fmaxf(fmaxf(c[2][2], c[2][3]), fmaxf(c[3][2], c[3][3])));
        mx0 = fmaxf(mx0, __shfl_xor_sync(0xffffffffu, mx0, 1));
        mx0 = fmaxf(mx0, __shfl_xor_sync(0xffffffffu, mx0, 2));
        mx1 = fmaxf(mx1, __shfl_xor_sync(0xffffffffu, mx1, 1));
        mx1 = fmaxf(mx1, __shfl_xor_sync(0xffffffffu, mx1, 2));
        if ((lane & 3) == 0) {
            red0[rowl * 2 + keyhalf] = mx0;
            red0[(rowl + 8) * 2 + keyhalf] = mx1;
        }
        __syncthreads();
        float mn0 = fmaxf(m0, fmaxf(red0[rowl * 2], red0[rowl * 2 + 1]));
        float mn1 = fmaxf(m1, fmaxf(red0[(rowl + 8) * 2], red0[(rowl + 8) * 2 + 1]));
        float corr0 = fexp(m0 - mn0), corr1 = fexp(m1 - mn1);
        m0 = mn0; m1 = mn1;

        float ls0 = 0.f, ls1 = 0.f;
        #pragma unroll
        for (int n = 0; n < 4; n++) {
            c[n][0] = fexp(c[n][0] - mn0); ls0 += c[n][0];
            c[n][1] = fexp(c[n][1] - mn0); ls0 += c[n][1];
            c[n][2] = fexp(c[n][2] - mn1); ls1 += c[n][2];
            c[n][3] = fexp(c[n][3] - mn1); ls1 += c[n][3];
        }
        ls0 += __shfl_xor_sync(0xffffffffu, ls0, 1);
        ls0 += __shfl_xor_sync(0xffffffffu, ls0, 2);
        ls1 += __shfl_xor_sync(0xffffffffu, ls1, 1);
        ls1 += __shfl_xor_sync(0xffffffffu, ls1, 2);
        if ((lane & 3) == 0) {
            red1[rowl * 2 + keyhalf] = ls0;
            red1[(rowl + 8) * 2 + keyhalf] = ls1;
        }
        l0 *= corr0; l1 *= corr1;
        #pragma unroll
        for (int n = 0; n < 8; n++) {
            o[n][0] *= corr0; o[n][1] *= corr0;
            o[n][2] *= corr1; o[n][3] *= corr1;
        }

        uint32_t ph[2][4], pl[2][4];
        #pragma unroll
        for (int k2 = 0; k2 < 2; k2++) {
            split_h16(c[2 * k2][0], c[2 * k2][1], ph[k2][0], pl[k2][0]);
            split_h16(c[2 * k2][2], c[2 * k2][3], ph[k2][1], pl[k2][1]);
            split_h16(c[2 * k2 + 1][0], c[2 * k2 + 1][1], ph[k2][2], pl[k2][2]);
            split_h16(c[2 * k2 + 1][2], c[2 * k2 + 1][3], ph[k2][3], pl[k2][3]);
        }

        #pragma unroll
        for (int k2 = 0; k2 < 2; k2++) {
            #pragma unroll
            for (int p = 0; p < 4; p++) {
                int vrow = p * 16 + (lane & 7) + (((lane >> 4) & 1) << 3);
                uint32_t off = vrow * (ARS * 2) + (keyhalf * 32 + k2 * 16) * 2 +
                               (((lane >> 3) & 1) << 4);
                uint32_t rv[4], rl[4];
                ldmatrix_x4(rv, vbase + off);
                ldmatrix_x4(rl, vlbase + off);
                mma_f16(o[2 * p],     ph[k2], rv[0], rv[1]);
                mma_f16(o[2 * p],     pl[k2], rv[0], rv[1]);
                mma_f16(o[2 * p],     ph[k2], rl[0], rl[1]);
                mma_f16(o[2 * p + 1], ph[k2], rv[2], rv[3]);
                mma_f16(o[2 * p + 1], pl[k2], rv[2], rv[3]);
                mma_f16(o[2 * p + 1], ph[k2], rl[2], rl[3]);
            }
        }
        __syncthreads();
        l0 += red1[rowl * 2] + red1[rowl * 2 + 1];
        l1 += red1[(rowl + 8) * 2] + red1[(rowl + 8) * 2 + 1];

        int nk = kb + 2;
        if (nk <= qb) issueKV(nk, st); else CP_COMMIT();
    }

    __syncthreads();
    if (keyhalf == 1) {
        float* ox = oex + chunk * 1024;
        #pragma unroll
        for (int n = 0; n < 8; n++) {
            int d = n * 8 + c0;
            ox[r0 * 64 + d] = o[n][0];
            ox[r0 * 64 + d + 1] = o[n][1];
            ox[(r0 + 8) * 64 + d] = o[n][2];
            ox[(r0 + 8) * 64 + d + 1] = o[n][3];
        }
    }
    __syncthreads();
    if (keyhalf == 0) {
        const float* ox = oex + chunk * 1024;
        float inv0 = 1.0f / l0, inv1 = 1.0f / l1;
        #pragma unroll
        for (int n = 0; n < 8; n++) {
            int d = n * 8 + c0;
            float a0 = (o[n][0] + ox[r0 * 64 + d]) * inv0;
            float a1 = (o[n][1] + ox[r0 * 64 + d + 1]) * inv0;
            float a2 = (o[n][2] + ox[(r0 + 8) * 64 + d]) * inv1;
            float a3 = (o[n][3] + ox[(r0 + 8) * 64 + d + 1]) * inv1;
            *(float2*)(O + base_out + (size_t)growA * C_ + d) = make_float2(a0, a1);
            *(float2*)(O + base_out + (size_t)(growA + 8) * C_ + d) = make_float2(a2, a3);
        }
    }
}

// ======================= loss final (combine partials) =================
__global__ void loss_init_kernel(float* loss) { *loss = 0.f; }

__global__ __launch_bounds__(256) void loss_final_kernel(
    const float* __restrict__ logits, const float* __restrict__ lmp,
    const float* __restrict__ lsp, const int* __restrict__ targets,
    float* __restrict__ loss)
{
    __shared__ float redm[8], reds[8];
    int row = blockIdx.x, tid = threadIdx.x;
    const float* lm = lmp + (size_t)row * NPART;
    const float* ls = lsp + (size_t)row * NPART;

    float m = -1e30f, s = 0.f;
    for (int i = tid; i < NPART; i += 256) {
        float mi = lm[i], si = ls[i];
        float mn = fmaxf(m, mi);
        s = s * fexp(m - mn) + si * fexp(mi - mn);
        m = mn;
    }
    #pragma unroll
    for (int o = 16; o; o >>= 1) {
        float mo = __shfl_xor_sync(0xffffffffu, m, o);
        float so = __shfl_xor_sync(0xffffffffu, s, o);
        float mn = fmaxf(m, mo);
        s = s * fexp(m - mn) + so * fexp(mo - mn);
        m = mn;
    }
    if ((tid & 31) == 0) { redm[tid >> 5] = m; reds[tid >> 5] = s; }
    __syncthreads();
    if (tid == 0) {
        float mm = redm[0], ss = reds[0];
        #pragma unroll
        for (int i = 1; i < 8; i++) {
            float mn = fmaxf(mm, redm[i]);
            ss = ss * fexp(mm - mn) + reds[i] * fexp(redm[i] - mn);
            mm = mn;
        }
        int tgt = targets[row];
        float lp = logits[(size_t)row * V_ + tgt] - mm - logf(ss);
        atomicAdd(loss, -lp * (1.0f / M_));
    }
}

// ======================= host =========================================
extern "C" void kernel_launch(void* const* d_in, const int* in_sizes, int n_in,
                              void* d_out, int out_size)
{
    const int*   idx     = (const int*)d_in[0];
    const int*   targets = (const int*)d_in[1];
    const float* tok     = (const float*)d_in[2];
    const float* pos     = (const float*)d_in[3];
    const float* ln1g    = (const float*)d_in[4];
    const float* ln1b    = (const float*)d_in[5];
    const float* Wq      = (const float*)d_in[6];
    const float* Wk      = (const float*)d_in[7];
    const float* Wv      = (const float*)d_in[8];
    const float* Wo      = (const float*)d_in[9];
    const float* bo      = (const float*)d_in[10];
    const float* ln2g    = (const float*)d_in[11];
    const float* ln2b    = (const float*)d_in[12];
    const float* W1      = (const float*)d_in[13];
    const float* b1      = (const float*)d_in[14];
    const float* W2      = (const float*)d_in[15];
    const float* b2      = (const float*)d_in[16];
    const float* lnfg    = (const float*)d_in[17];
    const float* lnfb    = (const float*)d_in[18];
    const float* Wlm     = (const float*)d_in[19];
    const float* blm     = (const float*)d_in[20];

    static float *x, *h, *qkv, *lgbuf, *lmp, *lsp;
    static __half *h16, *mlp16, *wqkv16, *wo16, *w1f, *w2f, *wlm16;
    static __half *khg, *klg, *vth, *vtl;
    static bool init = false;
    if (!init) {
        cudaGetSymbolAddress((void**)&x, g_x);
        cudaGetSymbolAddress((void**)&h, g_h);
        cudaGetSymbolAddress((void**)&qkv, g_qkv);
        cudaGetSymbolAddress((void**)&lgbuf, g_logits);
        cudaGetSymbolAddress((void**)&lmp, g_lm);
        cudaGetSymbolAddress((void**)&lsp, g_ls);
        cudaGetSymbolAddress((void**)&h16, g_h16);
        cudaGetSymbolAddress((void**)&mlp16, g_mlp16);
        cudaGetSymbolAddress((void**)&wqkv16, g_wqkv16);
        cudaGetSymbolAddress((void**)&wo16, g_wo16);
        cudaGetSymbolAddress((void**)&w1f, g_w1f);
        cudaGetSymbolAddress((void**)&w2f, g_w2f);
        cudaGetSymbolAddress((void**)&wlm16, g_wlm16);
        cudaGetSymbolAddress((void**)&khg, g_kh);
        cudaGetSymbolAddress((void**)&klg, g_kl);
        cudaGetSymbolAddress((void**)&vth, g_vth);
        cudaGetSymbolAddress((void**)&vtl, g_vtl);
        cudaFuncSetAttribute(attn_kernel, cudaFuncAttributeMaxDynamicSharedMemorySize, ATTN_SMEM);
        init = true;
    }

    const size_t NTV = (size_t)M_ * V_;
    float* logits_ptr = ((size_t)out_size >= NTV) ? (float*)d_out : lgbuf;
    float* loss_ptr = nullptr;
    if ((size_t)out_size == NTV + 1)     loss_ptr = (float*)d_out + NTV;
    else if ((size_t)out_size < NTV)     loss_ptr = (float*)d_out;

    const size_t CC = (size_t)C_ * C_;
    const size_t C3 = 3 * CC;
    const size_t C4 = 4 * CC;

    // ---- weight prep (all fp16 [N,K]) ----
    wsplit_f16_kernel<<<dim3(C_ / 32, C_ / 32, L_), 256>>>(Wq, wqkv16 + 0 * CC, C_, C_, C3);
    wsplit_f16_kernel<<<dim3(C_ / 32, C_ / 32, L_), 256>>>(Wk, wqkv16 + 1 * CC, C_, C_, C3);
    wsplit_f16_kernel<<<dim3(C_ / 32, C_ / 32, L_), 256>>>(Wv, wqkv16 + 2 * CC, C_, C_, C3);
    wsplit_f16_kernel<<<dim3(C_ / 32, C_ / 32, L_), 256>>>(Wo, wo16, C_, C_, CC);
    wsplit_f16_kernel<<<dim3(4 * C_ / 32, C_ / 32, L_), 256>>>(W1, w1f, C_, 4 * C_, C4);
    wsplit_f16_kernel<<<dim3(C_ / 32, 4 * C_ / 32, L_), 256>>>(W2, w2f, 4 * C_, C_, C4);
    wsplit_f16_kernel<<<dim3(V_ / 32, C_ / 32, 1), 256>>>(Wlm, wlm16, C_, V_, 0);

    dim3 gqkv(M_ / 128, 3 * C_ / 128);
    dim3 g1(M_ / 128, C_ / 128);
    dim3 g4(M_ / 128, 4 * C_ / 128);
    dim3 gl(M_ / 128, V_ / 128);
    dim3 gkv(T_ / 64, B_ * H_);
    dim3 gatt(B_ * H_, T_ / 64);

    embed_kernel<<<M_, 256>>>(idx, tok, pos, x);

    for (int l = 0; l < L_; l++) {
        ln_out_kernel<0><<<M_, 256>>>(x, ln1g + (size_t)l * C_, ln1b + (size_t)l * C_, h, nullptr);
        gemm_f16a2<0,0,1><<<gqkv, 256>>>(h, wqkv16 + (size_t)l * C3, nullptr, nullptr,
                                         qkv, khg, klg, 3 * C_, C_);
        vprep_kernel<<<gkv, 256>>>(qkv, vth, vtl);
        attn_kernel<<<gatt, 256, ATTN_SMEM>>>(qkv, khg, klg, vth, vtl, h);
        gemm_f16a2<1,1,0><<<g1, 256>>>(h, wo16 + (size_t)l * CC, bo + (size_t)l * C_, x,
                                       x, nullptr, nullptr, C_, C_);
        ln_out_kernel<1><<<M_, 256>>>(x, ln2g + (size_t)l * C_, ln2b + (size_t)l * C_, nullptr, h16);
        gemm_f16<1,1,0,1,0><<<g4, 256>>>(h16, w1f + (size_t)l * C4,
            b1 + (size_t)l * 4 * C_, nullptr, nullptr, mlp16, nullptr, nullptr, 4 * C_, C_);
        gemm_f16<1,0,1,0,0><<<g1, 256>>>(mlp16, w2f + (size_t)l * C4,
            b2 + (size_t)l * C_, x, x, nullptr, nullptr, nullptr, C_, 4 * C_);
    }

    ln_out_kernel<1><<<M_, 256>>>(x, lnfg, lnfb, nullptr, h16);
    gemm_f16<1,0,0,0,1><<<gl, 256>>>(h16, wlm16, blm, nullptr, logits_ptr, nullptr,
                                     lmp, lsp, V_, C_);

    if (loss_ptr) {
        loss_init_kernel<<<1, 1>>>(loss_ptr);
        loss_final_kernel<<<M_, 256>>>(logits_ptr, lmp, lsp, targets, loss_ptr);
    }
}